// round 12
// baseline (speedup 1.0000x reference)
#include <cuda_runtime.h>
#include <cuda_bf16.h>
#include <cuda_fp16.h>
#include <stdint.h>
#include <math.h>

// ============================================================================
// Scratch (device globals — no allocations allowed).
// ============================================================================
__device__ __align__(16) __nv_bfloat16 g_xhi [8192ull * 1024];
__device__ __align__(16) __nv_bfloat16 g_xlo [8192ull * 1024];
__device__ __align__(16) __half        g_x16 [8192ull * 1024];
__device__ __align__(16) __nv_bfloat16 g_wthi[32ull * 64 * 1024];   // Q/K W^T [e][h][d]
__device__ __align__(16) __nv_bfloat16 g_wtlo[32ull * 64 * 1024];
__device__ __align__(16) __half        g_wt16[16ull * 64 * 1024];   // V W^T fp16
__device__ __align__(16) __half        g_wp16[1024ull * 1024];      // Wp fp16
__device__ __align__(16) __half        g_avhi[8192ull * 1024];      // av split fp16
__device__ __align__(16) __half        g_avlo[8192ull * 1024];
__device__ __align__(16) __nv_bfloat16 g_qhi [16ull * 8192 * 64];   // [hd][row][d], scaled
__device__ __align__(16) __nv_bfloat16 g_qlo [16ull * 8192 * 64];
__device__ __align__(16) __nv_bfloat16 g_khi [16ull * 8192 * 64];
__device__ __align__(16) __nv_bfloat16 g_klo [16ull * 8192 * 64];
__device__ __align__(16) __half        g_v16 [16ull * 8192 * 64];   // [hd][row][d]
__device__ __align__(16) __half        g_vt16[64ull * 64 * 2048];   // [hb][d][l]

// ============================================================================
// PTX helpers (sm_80-era ISA — compiles for plain compute_103)
// ============================================================================
__device__ __forceinline__ uint32_t smem_u32(const void* p) {
    uint32_t a;
    asm("{ .reg .u64 t; cvta.to.shared.u64 t, %1; cvt.u32.u64 %0, t; }"
        : "=r"(a) : "l"(p));
    return a;
}

__device__ __forceinline__ void ldmatrix_x4(uint32_t& r0, uint32_t& r1,
                                            uint32_t& r2, uint32_t& r3,
                                            uint32_t addr) {
    asm volatile("ldmatrix.sync.aligned.m8n8.x4.shared.b16 {%0,%1,%2,%3}, [%4];"
                 : "=r"(r0), "=r"(r1), "=r"(r2), "=r"(r3) : "r"(addr));
}

__device__ __forceinline__ void mma_bf16(float* c,
                                         uint32_t a0, uint32_t a1, uint32_t a2, uint32_t a3,
                                         uint32_t b0, uint32_t b1) {
    asm volatile("mma.sync.aligned.m16n8k16.row.col.f32.bf16.bf16.f32 "
                 "{%0,%1,%2,%3}, {%4,%5,%6,%7}, {%8,%9}, {%0,%1,%2,%3};"
                 : "+f"(c[0]), "+f"(c[1]), "+f"(c[2]), "+f"(c[3])
                 : "r"(a0), "r"(a1), "r"(a2), "r"(a3), "r"(b0), "r"(b1));
}

__device__ __forceinline__ void mma_f16(float* c,
                                        uint32_t a0, uint32_t a1, uint32_t a2, uint32_t a3,
                                        uint32_t b0, uint32_t b1) {
    asm volatile("mma.sync.aligned.m16n8k16.row.col.f32.f16.f16.f32 "
                 "{%0,%1,%2,%3}, {%4,%5,%6,%7}, {%8,%9}, {%0,%1,%2,%3};"
                 : "+f"(c[0]), "+f"(c[1]), "+f"(c[2]), "+f"(c[3])
                 : "r"(a0), "r"(a1), "r"(a2), "r"(a3), "r"(b0), "r"(b1));
}

__device__ __forceinline__ void cp_async16(uint32_t dst, const void* src) {
    asm volatile("cp.async.cg.shared.global [%0], [%1], 16;"
                 :: "r"(dst), "l"(src) : "memory");
}
__device__ __forceinline__ void cp_commit() {
    asm volatile("cp.async.commit_group;" ::: "memory");
}
template <int N>
__device__ __forceinline__ void cp_wait() {
    asm volatile("cp.async.wait_group %0;" :: "n"(N) : "memory");
}

__device__ __forceinline__ uint32_t pack_bf16x2(float x, float y) {
    uint32_t r;
    asm("cvt.rn.bf16x2.f32 %0, %1, %2;" : "=r"(r) : "f"(y), "f"(x));
    return r;
}
__device__ __forceinline__ uint32_t pack_f16x2(float x, float y) {
    uint32_t r;
    asm("cvt.rn.f16x2.f32 %0, %1, %2;" : "=r"(r) : "f"(y), "f"(x));
    return r;
}

// fast 2^t for t <= 0, FFMA/ALU only (no MUFU). rel err ~2.5e-6.
__device__ __forceinline__ float exp2_fast(float t) {
    float r = fmaxf(t, -30.f);
    float z = r + 12582912.f;
    int   i = __float_as_int(z);
    float f = r - (z - 12582912.f);
    float p = 1.33335581e-3f;
    p = fmaf(p, f, 9.61812911e-3f);
    p = fmaf(p, f, 5.55041087e-2f);
    p = fmaf(p, f, 2.40226507e-1f);
    p = fmaf(p, f, 6.93147181e-1f);
    p = fmaf(p, f, 1.0f);
    return p * __int_as_float((i + 127) << 23);
}

__device__ __forceinline__ void split4(float4 v, uint32_t& h01, uint32_t& h23,
                                       uint32_t& l01, uint32_t& l23) {
    h01 = pack_bf16x2(v.x, v.y);
    h23 = pack_bf16x2(v.z, v.w);
    float r0 = v.x - __int_as_float(h01 << 16);
    float r1 = v.y - __int_as_float(h01 & 0xFFFF0000u);
    float r2 = v.z - __int_as_float(h23 << 16);
    float r3 = v.w - __int_as_float(h23 & 0xFFFF0000u);
    l01 = pack_bf16x2(r0, r1);
    l23 = pack_bf16x2(r2, r3);
}

__device__ __forceinline__ void split2_bf(float a, float b, uint32_t& h, uint32_t& l) {
    h = pack_bf16x2(a, b);
    float ra = a - __int_as_float(h << 16);
    float rb = b - __int_as_float(h & 0xFFFF0000u);
    l = pack_bf16x2(ra, rb);
}

__device__ __forceinline__ void split2_f16(float a, float b, uint32_t& h, uint32_t& l) {
    h = pack_f16x2(a, b);
    float ha = __half2float(__ushort_as_half((unsigned short)(h & 0xFFFFu)));
    float hb = __half2float(__ushort_as_half((unsigned short)(h >> 16)));
    l = pack_f16x2(a - ha, b - hb);
}

// ============================================================================
// Prep kernels
// ============================================================================
__global__ __launch_bounds__(256) void prep_x(const float* __restrict__ x) {
    #pragma unroll
    for (int i = 0; i < 4; ++i) {
        size_t idx = (size_t)blockIdx.x * 256 + threadIdx.x + (size_t)i * 524288;
        float4 v = *(const float4*)(x + idx * 4);
        uint32_t h01, h23, l01, l23;
        split4(v, h01, h23, l01, l23);
        *(uint2*)&g_xhi[idx * 4] = make_uint2(h01, h23);
        *(uint2*)&g_xlo[idx * 4] = make_uint2(l01, l23);
        *(uint2*)&g_x16[idx * 4] = make_uint2(pack_f16x2(v.x, v.y),
                                              pack_f16x2(v.z, v.w));
    }
}

__global__ __launch_bounds__(256) void prep_wp16(const float* __restrict__ Wp) {
    #pragma unroll
    for (int i = 0; i < 4; ++i) {
        size_t idx = (size_t)blockIdx.x * 256 + threadIdx.x + (size_t)i * 65536;
        float4 v = *(const float4*)(Wp + idx * 4);
        *(uint2*)&g_wp16[idx * 4] = make_uint2(pack_f16x2(v.x, v.y),
                                               pack_f16x2(v.z, v.w));
    }
}

// transpose Wqkv [48][1024][64] -> Q/K: split bf16 [e][64][1024]; V: fp16.
__global__ void transpose_w(const float* __restrict__ W) {
    __shared__ float t[32][33];
    const int e  = blockIdx.z;
    const int k0 = blockIdx.x * 32;
    const int h0 = blockIdx.y * 32;
    const int tx = threadIdx.x, ty = threadIdx.y;
    #pragma unroll
    for (int i = 0; i < 32; i += 8)
        t[ty + i][tx] = W[(size_t)e * 65536 + (size_t)(k0 + ty + i) * 64 + h0 + tx];
    __syncthreads();
    #pragma unroll
    for (int i = 0; i < 32; i += 8) {
        float val = t[tx][ty + i];
        if (e < 32) {
            __nv_bfloat16 hi = __float2bfloat16(val);
            __nv_bfloat16 lo = __float2bfloat16(val - __bfloat162float(hi));
            size_t off = (size_t)e * 65536 + (size_t)(h0 + ty + i) * 1024 + k0 + tx;
            g_wthi[off] = hi;
            g_wtlo[off] = lo;
        } else {
            size_t o16 = (size_t)(e - 32) * 65536 + (size_t)(h0 + ty + i) * 1024 + k0 + tx;
            g_wt16[o16] = __float2half(val);
        }
    }
}

// transpose V fp16 [hb][l][d] -> [hb][d][l]
__global__ __launch_bounds__(256)
void prep_vt()
{
    __shared__ __half t[64 * 72];
    const int tid = threadIdx.x;
    const int hb  = blockIdx.y;
    const int l0  = blockIdx.x * 64;

    const __half* src = g_v16 + ((size_t)hb * 2048 + l0) * 64;
    #pragma unroll
    for (int i = 0; i < 4; ++i) {
        int idx = tid + i * 256;
        int l   = idx >> 4;
        int c4  = idx & 15;
        uint2 v = *(const uint2*)(src + (size_t)l * 64 + c4 * 4);
        int d = c4 * 4;
        t[(d + 0) * 72 + l] = __ushort_as_half((unsigned short)(v.x & 0xFFFF));
        t[(d + 1) * 72 + l] = __ushort_as_half((unsigned short)(v.x >> 16));
        t[(d + 2) * 72 + l] = __ushort_as_half((unsigned short)(v.y & 0xFFFF));
        t[(d + 3) * 72 + l] = __ushort_as_half((unsigned short)(v.y >> 16));
    }
    __syncthreads();
    #pragma unroll
    for (int i = 0; i < 2; ++i) {
        int idx = tid + i * 256;
        int d   = idx >> 3;
        int c   = idx & 7;
        uint4 v = *(uint4*)&t[d * 72 + c * 8];
        *(uint4*)&g_vt16[((size_t)hb * 64 + d) * 2048 + l0 + c * 8] = v;
    }
}

// ============================================================================
// gemm_qk: 128x128 CTA, 3-term split bf16, 3-stage. Q/K ensembles (e 0..31);
//   epilogue writes Q (scaled by 8/ln2) and K pre-split bf16 hi/lo.
// ============================================================================
#define LDA 80u
#define G2_AHI 0u
#define G2_ALO 10240u
#define G2_BHI 20480u
#define G2_BLO 30720u
#define G2_STG 40960u
#define GEMM_SMEM (3 * 40960)

__global__ __launch_bounds__(256)
void gemm_qk(const float* __restrict__ bias)
{
    extern __shared__ __align__(128) char smem[];
    const uint32_t sb  = smem_u32(smem);
    const int tid  = threadIdx.x;
    const int lane = tid & 31;
    const int wid  = tid >> 5;
    const int wm   = wid & 1;
    const int wn   = wid >> 1;
    const int m0   = blockIdx.x * 128;
    const int grp0 = blockIdx.y * 2;

    const __nv_bfloat16* Ahi = g_xhi;
    const __nv_bfloat16* Alo = g_xlo;
    const __nv_bfloat16* Bh0 = g_wthi + (size_t)grp0 * 65536;
    const __nv_bfloat16* Bl0 = g_wtlo + (size_t)grp0 * 65536;

    float acc[4][4][4];
    #pragma unroll
    for (int mt = 0; mt < 4; ++mt)
        #pragma unroll
        for (int nt = 0; nt < 4; ++nt)
            #pragma unroll
            for (int i = 0; i < 4; ++i) acc[mt][nt][i] = 0.f;

    const int cp_r = tid >> 2;
    const int cp_c = tid & 3;
    const int ce   = cp_c * 8;
    auto issue = [&](int ks, uint32_t stg) {
        const int k0 = ks * 32;
        uint32_t d0 = stg + (uint32_t)cp_r * LDA + (uint32_t)cp_c * 16u;
        uint32_t d1 = d0 + 64u * LDA;
        size_t a0 = (size_t)(m0 + cp_r) * 1024 + k0 + ce;
        size_t a1 = a0 + 64 * 1024;
        size_t b0 = (size_t)cp_r * 1024 + k0 + ce;
        cp_async16(d0 + G2_AHI, Ahi + a0);
        cp_async16(d1 + G2_AHI, Ahi + a1);
        cp_async16(d0 + G2_ALO, Alo + a0);
        cp_async16(d1 + G2_ALO, Alo + a1);
        cp_async16(d0 + G2_BHI, Bh0 + b0);
        cp_async16(d1 + G2_BHI, Bh0 + 65536 + b0);
        cp_async16(d0 + G2_BLO, Bl0 + b0);
        cp_async16(d1 + G2_BLO, Bl0 + 65536 + b0);
        cp_commit();
    };

    const uint32_t a_row = (uint32_t)(wm * 64 + (lane & 7) + ((lane >> 3) & 1) * 8);
    const uint32_t a_kb  = (uint32_t)(lane >> 4) * 16u;
    const uint32_t b_row = (uint32_t)(wn * 32 + (lane & 7) + (lane >> 4) * 8);
    const uint32_t b_kb  = (uint32_t)((lane >> 3) & 1) * 16u;

    issue(0, sb);
    issue(1, sb + G2_STG);

    for (int ks = 0; ks < 32; ++ks) {
        if (ks < 31) cp_wait<1>(); else cp_wait<0>();
        __syncthreads();
        if (ks + 2 < 32) issue(ks + 2, sb + (uint32_t)((ks + 2) % 3) * G2_STG);

        const uint32_t stg = sb + (uint32_t)(ks % 3) * G2_STG;
        const uint32_t aHi = stg + G2_AHI + a_row * LDA + a_kb;
        const uint32_t aLo = stg + G2_ALO + a_row * LDA + a_kb;
        const uint32_t bHi = stg + G2_BHI + b_row * LDA + b_kb;
        const uint32_t bLo = stg + G2_BLO + b_row * LDA + b_kb;

        #pragma unroll
        for (int kk = 0; kk < 2; ++kk) {
            const uint32_t koff = (uint32_t)kk * 32u;

            uint32_t ahi[4][4], alo[4][4];
            #pragma unroll
            for (int mt = 0; mt < 4; ++mt) {
                ldmatrix_x4(ahi[mt][0], ahi[mt][1], ahi[mt][2], ahi[mt][3],
                            aHi + (uint32_t)mt * 16u * LDA + koff);
                ldmatrix_x4(alo[mt][0], alo[mt][1], alo[mt][2], alo[mt][3],
                            aLo + (uint32_t)mt * 16u * LDA + koff);
            }
            uint32_t bhi[4][2], blo[4][2];
            #pragma unroll
            for (int ntp = 0; ntp < 2; ++ntp) {
                uint32_t r0, r1, r2, r3;
                ldmatrix_x4(r0, r1, r2, r3, bHi + (uint32_t)ntp * 16u * LDA + koff);
                bhi[ntp * 2][0] = r0; bhi[ntp * 2][1] = r1;
                bhi[ntp * 2 + 1][0] = r2; bhi[ntp * 2 + 1][1] = r3;
                ldmatrix_x4(r0, r1, r2, r3, bLo + (uint32_t)ntp * 16u * LDA + koff);
                blo[ntp * 2][0] = r0; blo[ntp * 2][1] = r1;
                blo[ntp * 2 + 1][0] = r2; blo[ntp * 2 + 1][1] = r3;
            }

            #pragma unroll
            for (int mt = 0; mt < 4; ++mt)
                #pragma unroll
                for (int nt = 0; nt < 4; ++nt) {
                    mma_bf16(acc[mt][nt], ahi[mt][0], ahi[mt][1], ahi[mt][2], ahi[mt][3],
                             bhi[nt][0], bhi[nt][1]);
                    mma_bf16(acc[mt][nt], ahi[mt][0], ahi[mt][1], ahi[mt][2], ahi[mt][3],
                             blo[nt][0], blo[nt][1]);
                    mma_bf16(acc[mt][nt], alo[mt][0], alo[mt][1], alo[mt][2], alo[mt][3],
                             bhi[nt][0], bhi[nt][1]);
                }
        }
    }

    const float QSCALE = 11.5415603272f;
    const int g  = lane >> 2;
    const int tg = lane & 3;
    #pragma unroll
    for (int mt = 0; mt < 4; ++mt)
        #pragma unroll
        for (int nt = 0; nt < 4; ++nt) {
            int n    = wn * 32 + nt * 8 + tg * 2;
            int gsel = n >> 6;
            int c64  = n & 63;
            int e    = grp0 + gsel;
            const float* bp = bias + (size_t)e * 64;
            float b0 = bp[c64], b1 = bp[c64 + 1];
            int r0 = m0 + wm * 64 + mt * 16 + g;
            float v00 = acc[mt][nt][0] + b0, v01 = acc[mt][nt][1] + b1;
            float v10 = acc[mt][nt][2] + b0, v11 = acc[mt][nt][3] + b1;
            bool isQ = (e < 16);
            float s = isQ ? QSCALE : 1.f;
            v00 *= s; v01 *= s; v10 *= s; v11 *= s;
            __nv_bfloat16* dh = isQ ? g_qhi : g_khi;
            __nv_bfloat16* dl = isQ ? g_qlo : g_klo;
            int eo = isQ ? e : (e - 16);
            size_t base0 = ((size_t)eo * 8192 + r0) * 64 + c64;
            size_t base1 = base0 + 8 * 64;
            uint32_t h, l;
            split2_bf(v00, v01, h, l);
            *(uint32_t*)&dh[base0] = h;
            *(uint32_t*)&dl[base0] = l;
            split2_bf(v10, v11, h, l);
            *(uint32_t*)&dh[base1] = h;
            *(uint32_t*)&dl[base1] = l;
        }
}

// ============================================================================
// gemm_v16: 1-term fp16 GEMM for V ensembles; writes fp16 g_v16 [hd][row][d].
// ============================================================================
#define GF_A 0u
#define GF_B 10240u
#define GF_STG 20480u
#define GF_SMEM (3 * 20480)

__global__ __launch_bounds__(256)
void gemm_v16(const float* __restrict__ bias)
{
    extern __shared__ __align__(128) char smem[];
    const uint32_t sb  = smem_u32(smem);
    const int tid  = threadIdx.x;
    const int lane = tid & 31;
    const int wid  = tid >> 5;
    const int wm   = wid & 1;
    const int wn   = wid >> 1;
    const int m0   = blockIdx.x * 128;
    const int grp0 = blockIdx.y * 2;

    const __half* A  = g_x16;
    const __half* B0 = g_wt16 + (size_t)grp0 * 65536;

    float acc[4][4][4];
    #pragma unroll
    for (int mt = 0; mt < 4; ++mt)
        #pragma unroll
        for (int nt = 0; nt < 4; ++nt)
            #pragma unroll
            for (int i = 0; i < 4; ++i) acc[mt][nt][i] = 0.f;

    const int cp_r = tid >> 2;
    const int cp_c = tid & 3;
    const int ce   = cp_c * 8;
    auto issue = [&](int ks, uint32_t stg) {
        const int k0 = ks * 32;
        uint32_t d0 = stg + (uint32_t)cp_r * LDA + (uint32_t)cp_c * 16u;
        uint32_t d1 = d0 + 64u * LDA;
        size_t a0 = (size_t)(m0 + cp_r) * 1024 + k0 + ce;
        size_t a1 = a0 + 64 * 1024;
        size_t b0 = (size_t)cp_r * 1024 + k0 + ce;
        cp_async16(d0 + GF_A, A + a0);
        cp_async16(d1 + GF_A, A + a1);
        cp_async16(d0 + GF_B, B0 + b0);
        cp_async16(d1 + GF_B, B0 + 65536 + b0);
        cp_commit();
    };

    const uint32_t a_row = (uint32_t)(wm * 64 + (lane & 7) + ((lane >> 3) & 1) * 8);
    const uint32_t a_kb  = (uint32_t)(lane >> 4) * 16u;
    const uint32_t b_row = (uint32_t)(wn * 32 + (lane & 7) + (lane >> 4) * 8);
    const uint32_t b_kb  = (uint32_t)((lane >> 3) & 1) * 16u;

    issue(0, sb);
    issue(1, sb + GF_STG);

    for (int ks = 0; ks < 32; ++ks) {
        if (ks < 31) cp_wait<1>(); else cp_wait<0>();
        __syncthreads();
        if (ks + 2 < 32) issue(ks + 2, sb + (uint32_t)((ks + 2) % 3) * GF_STG);

        const uint32_t stg = sb + (uint32_t)(ks % 3) * GF_STG;
        const uint32_t aB = stg + GF_A + a_row * LDA + a_kb;
        const uint32_t bB = stg + GF_B + b_row * LDA + b_kb;

        #pragma unroll
        for (int kk = 0; kk < 2; ++kk) {
            const uint32_t koff = (uint32_t)kk * 32u;

            uint32_t af[4][4];
            #pragma unroll
            for (int mt = 0; mt < 4; ++mt)
                ldmatrix_x4(af[mt][0], af[mt][1], af[mt][2], af[mt][3],
                            aB + (uint32_t)mt * 16u * LDA + koff);
            uint32_t bf[4][2];
            #pragma unroll
            for (int ntp = 0; ntp < 2; ++ntp) {
                uint32_t r0, r1, r2, r3;
                ldmatrix_x4(r0, r1, r2, r3, bB + (uint32_t)ntp * 16u * LDA + koff);
                bf[ntp * 2][0] = r0; bf[ntp * 2][1] = r1;
                bf[ntp * 2 + 1][0] = r2; bf[ntp * 2 + 1][1] = r3;
            }

            #pragma unroll
            for (int mt = 0; mt < 4; ++mt)
                #pragma unroll
                for (int nt = 0; nt < 4; ++nt)
                    mma_f16(acc[mt][nt], af[mt][0], af[mt][1], af[mt][2], af[mt][3],
                            bf[nt][0], bf[nt][1]);
        }
    }

    const int g  = lane >> 2;
    const int tg = lane & 3;
    #pragma unroll
    for (int mt = 0; mt < 4; ++mt)
        #pragma unroll
        for (int nt = 0; nt < 4; ++nt) {
            int n    = wn * 32 + nt * 8 + tg * 2;
            int gsel = n >> 6;
            int c64  = n & 63;
            int e    = grp0 + gsel;
            const float* bp = bias + (size_t)e * 64;
            float b0 = bp[c64], b1 = bp[c64 + 1];
            int r0 = m0 + wm * 64 + mt * 16 + g;
            size_t base0 = ((size_t)e * 8192 + r0) * 64 + c64;
            size_t base1 = base0 + 8 * 64;
            *(uint32_t*)&g_v16[base0] =
                pack_f16x2(acc[mt][nt][0] + b0, acc[mt][nt][1] + b1);
            *(uint32_t*)&g_v16[base1] =
                pack_f16x2(acc[mt][nt][2] + b0, acc[mt][nt][3] + b1);
        }
}

// ============================================================================
// gemm_proj: 128x64 tile, 2-term split-fp16, 5-stage (1 CTA/SM, 6.9 waves).
//   8 warps 4m x 2n, warp tile 32x32.
// ============================================================================
#define GP_AHI 0u
#define GP_ALO 10240u
#define GP_B   20480u
#define GP_STG 25600u
#define GP_SMEM (5 * 25600)

__global__ __launch_bounds__(256)
void gemm_proj(const float* __restrict__ bias, float* __restrict__ C)
{
    extern __shared__ __align__(128) char smem[];
    const uint32_t sb  = smem_u32(smem);
    const int tid  = threadIdx.x;
    const int lane = tid & 31;
    const int wid  = tid >> 5;
    const int wm   = wid & 3;        // 4 m-blocks of 32 rows
    const int wn   = wid >> 2;       // 2 n-blocks of 32 cols
    const int m0   = blockIdx.x * 128;
    const int n0   = blockIdx.y * 64;

    const __half* Ahi = g_avhi;
    const __half* Alo = g_avlo;
    const __half* B0  = g_wp16 + (size_t)n0 * 1024;

    float acc[2][4][4];
    #pragma unroll
    for (int mt = 0; mt < 2; ++mt)
        #pragma unroll
        for (int nt = 0; nt < 4; ++nt)
            #pragma unroll
            for (int i = 0; i < 4; ++i) acc[mt][nt][i] = 0.f;

    const int cp_r = tid >> 2;      // 0..63
    const int cp_c = tid & 3;
    const int ce   = cp_c * 8;
    auto issue = [&](int ks, uint32_t stg) {
        const int k0 = ks * 32;
        uint32_t d0 = stg + (uint32_t)cp_r * LDA + (uint32_t)cp_c * 16u;
        uint32_t d1 = d0 + 64u * LDA;
        size_t a0 = (size_t)(m0 + cp_r) * 1024 + k0 + ce;
        size_t a1 = a0 + 64 * 1024;
        size_t b0 = (size_t)cp_r * 1024 + k0 + ce;
        cp_async16(d0 + GP_AHI, Ahi + a0);
        cp_async16(d1 + GP_AHI, Ahi + a1);
        cp_async16(d0 + GP_ALO, Alo + a0);
        cp_async16(d1 + GP_ALO, Alo + a1);
        cp_async16(d0 + GP_B, B0 + b0);
        cp_commit();
    };

    const uint32_t a_row = (uint32_t)(wm * 32 + (lane & 7) + ((lane >> 3) & 1) * 8);
    const uint32_t a_kb  = (uint32_t)(lane >> 4) * 16u;
    const uint32_t b_row = (uint32_t)(wn * 32 + (lane & 7) + (lane >> 4) * 8);
    const uint32_t b_kb  = (uint32_t)((lane >> 3) & 1) * 16u;

    issue(0, sb);
    issue(1, sb + GP_STG);
    issue(2, sb + 2 * GP_STG);
    issue(3, sb + 3 * GP_STG);

    for (int ks = 0; ks < 32; ++ks) {
        if (ks <= 28) cp_wait<3>();
        else if (ks == 29) cp_wait<2>();
        else if (ks == 30) cp_wait<1>();
        else cp_wait<0>();
        __syncthreads();
        if (ks + 4 < 32) issue(ks + 4, sb + (uint32_t)((ks + 4) % 5) * GP_STG);

        const uint32_t stg = sb + (uint32_t)(ks % 5) * GP_STG;
        const uint32_t aHi = stg + GP_AHI + a_row * LDA + a_kb;
        const uint32_t aLo = stg + GP_ALO + a_row * LDA + a_kb;
        const uint32_t bB  = stg + GP_B   + b_row * LDA + b_kb;

        #pragma unroll
        for (int kk = 0; kk < 2; ++kk) {
            const uint32_t koff = (uint32_t)kk * 32u;

            uint32_t ahi[2][4], alo[2][4];
            #pragma unroll
            for (int mt = 0; mt < 2; ++mt) {
                ldmatrix_x4(ahi[mt][0], ahi[mt][1], ahi[mt][2], ahi[mt][3],
                            aHi + (uint32_t)mt * 16u * LDA + koff);
                ldmatrix_x4(alo[mt][0], alo[mt][1], alo[mt][2], alo[mt][3],
                            aLo + (uint32_t)mt * 16u * LDA + koff);
            }
            uint32_t bf[4][2];
            #pragma unroll
            for (int ntp = 0; ntp < 2; ++ntp) {
                uint32_t r0, r1, r2, r3;
                ldmatrix_x4(r0, r1, r2, r3, bB + (uint32_t)ntp * 16u * LDA + koff);
                bf[ntp * 2][0] = r0; bf[ntp * 2][1] = r1;
                bf[ntp * 2 + 1][0] = r2; bf[ntp * 2 + 1][1] = r3;
            }

            #pragma unroll
            for (int mt = 0; mt < 2; ++mt)
                #pragma unroll
                for (int nt = 0; nt < 4; ++nt) {
                    mma_f16(acc[mt][nt], ahi[mt][0], ahi[mt][1], ahi[mt][2], ahi[mt][3],
                            bf[nt][0], bf[nt][1]);
                    mma_f16(acc[mt][nt], alo[mt][0], alo[mt][1], alo[mt][2], alo[mt][3],
                            bf[nt][0], bf[nt][1]);
                }
        }
    }

    const int g  = lane >> 2;
    const int tg = lane & 3;
    #pragma unroll
    for (int mt = 0; mt < 2; ++mt)
        #pragma unroll
        for (int nt = 0; nt < 4; ++nt) {
            int n = n0 + wn * 32 + nt * 8 + tg * 2;
            float b0 = bias[n], b1 = bias[n + 1];
            int r0 = m0 + wm * 32 + mt * 16 + g;
            float2 o0 = make_float2(acc[mt][nt][0] + b0, acc[mt][nt][1] + b1);
            float2 o1 = make_float2(acc[mt][nt][2] + b0, acc[mt][nt][3] + b1);
            *(float2*)(C + (size_t)r0 * 1024 + n)       = o0;
            *(float2*)(C + (size_t)(r0 + 8) * 1024 + n) = o1;
        }
}

// ============================================================================
// attn_mma: flash attention. S 3-term bf16, PV 1-term fp16. 5-stage cp.async,
//   1 CTA/SM (smem-forced), grid 1024 -> 6.9 waves. Emits av split fp16.
// ============================================================================
#define LDS_ROW 144u
#define ST_KHI 0u
#define ST_KLO 9216u
#define ST_V16 18432u
#define STAGE_BYTES 27648u
#define ATTN_SMEM (5 * 27648)

__global__ __launch_bounds__(256)
void attn_mma()
{
    extern __shared__ __align__(128) char smem[];
    const uint32_t sb = smem_u32(smem);
    const int tid  = threadIdx.x;
    const int lane = tid & 31;
    const int wid  = tid >> 5;
    const int g    = lane >> 2;
    const int tg   = lane & 3;
    const int hb   = blockIdx.y;
    const int hd   = hb >> 2;
    const int b    = hb & 3;
    const int q0   = blockIdx.x * 128;

    const __nv_bfloat16* Qhi = g_qhi + ((size_t)hd * 8192 + b * 2048 + q0) * 64;
    const __nv_bfloat16* Qlo = g_qlo + ((size_t)hd * 8192 + b * 2048 + q0) * 64;
    const __nv_bfloat16* Khi = g_khi + (size_t)hb * 2048 * 64;
    const __nv_bfloat16* Klo = g_klo + (size_t)hb * 2048 * 64;
    const __half*        V16 = g_vt16 + (size_t)hb * 64 * 2048;

    // ---- stage Q (pre-scaled, pre-split) via cp.async, extract fragments ----
    #pragma unroll
    for (int i = 0; i < 4; ++i) {
        int idx = tid + i * 256;
        int row = idx >> 3;
        int c   = idx & 7;
        cp_async16(sb + (uint32_t)row * LDS_ROW + (uint32_t)c * 16u,
                   Qhi + (size_t)row * 64 + c * 8);
        cp_async16(sb + 18432u + (uint32_t)row * LDS_ROW + (uint32_t)c * 16u,
                   Qlo + (size_t)row * 64 + c * 8);
    }
    cp_commit();
    cp_wait<0>();
    __syncthreads();

    uint32_t qhi[4][4], qlo[4][4];
    {
        const uint32_t qrow = (uint32_t)(wid * 16 + (lane & 7) + ((lane >> 3) & 1) * 8);
        const uint32_t kb   = (uint32_t)(lane >> 4) * 16u;
        const uint32_t aH = sb + qrow * LDS_ROW + kb;
        const uint32_t aL = sb + 18432u + qrow * LDS_ROW + kb;
        #pragma unroll
        for (int t = 0; t < 4; ++t) {
            ldmatrix_x4(qhi[t][0], qhi[t][1], qhi[t][2], qhi[t][3], aH + t * 32u);
            ldmatrix_x4(qlo[t][0], qlo[t][1], qlo[t][2], qlo[t][3], aL + t * 32u);
        }
    }
    __syncthreads();   // Q consumed — smem free for stages

    float mA = -1e30f, mB = -1e30f, lA = 0.f, lB = 0.f;
    float oacc[8][4];
    #pragma unroll
    for (int j = 0; j < 8; ++j)
        #pragma unroll
        for (int i = 0; i < 4; ++i) oacc[j][i] = 0.f;

    const uint32_t brow = (uint32_t)((lane & 7) + (lane >> 4) * 8);
    const uint32_t bkb  = (uint32_t)((lane >> 3) & 1) * 16u;

    const int cp_row = tid >> 3;     // 0..31
    const int cp_c   = tid & 7;
    auto issue = [&](int j0, uint32_t stg) {
        #pragma unroll
        for (int i = 0; i < 2; ++i) {
            int row = cp_row + i * 32;
            uint32_t doff = stg + (uint32_t)row * LDS_ROW + (uint32_t)cp_c * 16u;
            cp_async16(doff + ST_KHI, Khi + ((size_t)(j0 + row)) * 64 + cp_c * 8);
            cp_async16(doff + ST_KLO, Klo + ((size_t)(j0 + row)) * 64 + cp_c * 8);
            cp_async16(doff + ST_V16, V16 + ((size_t)row) * 2048 + j0 + cp_c * 8);
        }
        cp_commit();
    };

    issue(0,   sb);
    issue(64,  sb + STAGE_BYTES);
    issue(128, sb + 2 * STAGE_BYTES);
    issue(192, sb + 3 * STAGE_BYTES);

    for (int j = 0; j < 32; ++j) {
        if (j <= 28) cp_wait<3>();
        else if (j == 29) cp_wait<2>();
        else if (j == 30) cp_wait<1>();
        else cp_wait<0>();
        __syncthreads();
        if (j + 4 < 32) issue((j + 4) * 64, sb + (uint32_t)((j + 4) % 5) * STAGE_BYTES);

        const uint32_t stg = sb + (uint32_t)(j % 5) * STAGE_BYTES;

        // ---- S = Qscaled @ K^T (split 3-term bf16), log2 units ----
        float sacc[8][4];
        #pragma unroll
        for (int jj = 0; jj < 8; ++jj)
            #pragma unroll
            for (int i = 0; i < 4; ++i) sacc[jj][i] = 0.f;

        #pragma unroll
        for (int td = 0; td < 4; ++td) {
            uint32_t bhi[8][2], blo[8][2];
            #pragma unroll
            for (int ntp = 0; ntp < 4; ++ntp) {
                uint32_t base = (uint32_t)(ntp * 16) * LDS_ROW + brow * LDS_ROW + bkb
                                + (uint32_t)td * 32u;
                uint32_t r0, r1, r2, r3;
                ldmatrix_x4(r0, r1, r2, r3, stg + ST_KHI + base);
                bhi[ntp * 2][0] = r0; bhi[ntp * 2][1] = r1;
                bhi[ntp * 2 + 1][0] = r2; bhi[ntp * 2 + 1][1] = r3;
                ldmatrix_x4(r0, r1, r2, r3, stg + ST_KLO + base);
                blo[ntp * 2][0] = r0; blo[ntp * 2][1] = r1;
                blo[ntp * 2 + 1][0] = r2; blo[ntp * 2 + 1][1] = r3;
            }
            #pragma unroll
            for (int nt = 0; nt < 8; ++nt) {
                mma_bf16(sacc[nt], qhi[td][0], qhi[td][1], qhi[td][2], qhi[td][3],
                         bhi[nt][0], bhi[nt][1]);
                mma_bf16(sacc[nt], qhi[td][0], qhi[td][1], qhi[td][2], qhi[td][3],
                         blo[nt][0], blo[nt][1]);
                mma_bf16(sacc[nt], qlo[td][0], qlo[td][1], qlo[td][2], qlo[td][3],
                         bhi[nt][0], bhi[nt][1]);
            }
        }

        // ---- online softmax (log2 domain) ----
        float rmA = -1e30f, rmB = -1e30f;
        #pragma unroll
        for (int jj = 0; jj < 8; ++jj) {
            rmA = fmaxf(rmA, fmaxf(sacc[jj][0], sacc[jj][1]));
            rmB = fmaxf(rmB, fmaxf(sacc[jj][2], sacc[jj][3]));
        }
        rmA = fmaxf(rmA, __shfl_xor_sync(0xffffffffu, rmA, 1));
        rmA = fmaxf(rmA, __shfl_xor_sync(0xffffffffu, rmA, 2));
        rmB = fmaxf(rmB, __shfl_xor_sync(0xffffffffu, rmB, 1));
        rmB = fmaxf(rmB, __shfl_xor_sync(0xffffffffu, rmB, 2));

        float mnA = fmaxf(mA, rmA), mnB = fmaxf(mB, rmB);
        float corrA = exp2_fast(mA - mnA), corrB = exp2_fast(mB - mnB);

        float sumA = 0.f, sumB = 0.f;
        uint32_t pf[4][4];
        #pragma unroll
        for (int jj = 0; jj < 8; ++jj) {
            float p0 = exp2_fast(sacc[jj][0] - mnA);
            float p1 = exp2_fast(sacc[jj][1] - mnA);
            float p2 = exp2_fast(sacc[jj][2] - mnB);
            float p3 = exp2_fast(sacc[jj][3] - mnB);
            sumA += p0 + p1; sumB += p2 + p3;
            int t = jj >> 1;
            int o = (jj & 1) * 2;
            pf[t][o]     = pack_f16x2(p0, p1);
            pf[t][o + 1] = pack_f16x2(p2, p3);
        }
        sumA += __shfl_xor_sync(0xffffffffu, sumA, 1);
        sumA += __shfl_xor_sync(0xffffffffu, sumA, 2);
        sumB += __shfl_xor_sync(0xffffffffu, sumB, 1);
        sumB += __shfl_xor_sync(0xffffffffu, sumB, 2);

        lA = lA * corrA + sumA;
        lB = lB * corrB + sumB;
        mA = mnA; mB = mnB;

        #pragma unroll
        for (int jj = 0; jj < 8; ++jj) {
            oacc[jj][0] *= corrA; oacc[jj][1] *= corrA;
            oacc[jj][2] *= corrB; oacc[jj][3] *= corrB;
        }

        // ---- O += P @ V (1-term fp16) ----
        #pragma unroll
        for (int t = 0; t < 4; ++t) {
            uint32_t vf[8][2];
            #pragma unroll
            for (int ntp = 0; ntp < 4; ++ntp) {
                uint32_t base = (uint32_t)(ntp * 16) * LDS_ROW + brow * LDS_ROW + bkb
                                + (uint32_t)t * 32u;
                uint32_t r0, r1, r2, r3;
                ldmatrix_x4(r0, r1, r2, r3, stg + ST_V16 + base);
                vf[ntp * 2][0] = r0; vf[ntp * 2][1] = r1;
                vf[ntp * 2 + 1][0] = r2; vf[ntp * 2 + 1][1] = r3;
            }
            #pragma unroll
            for (int nd = 0; nd < 8; ++nd)
                mma_f16(oacc[nd], pf[t][0], pf[t][1], pf[t][2], pf[t][3],
                        vf[nd][0], vf[nd][1]);
        }
    }

    // ---- epilogue: normalize, split to fp16 hi/lo, write g_avhi/g_avlo ----
    const float invA = 1.f / lA, invB = 1.f / lB;
    const int rowA = q0 + wid * 16 + g;
    const int rowB = rowA + 8;
    #pragma unroll
    for (int jd = 0; jd < 8; ++jd) {
        int col = hd * 64 + jd * 8 + tg * 2;
        {
            uint32_t h, l;
            split2_f16(oacc[jd][0] * invA, oacc[jd][1] * invA, h, l);
            size_t base = (size_t)(b * 2048 + rowA) * 1024 + col;
            *(uint32_t*)&g_avhi[base] = h;
            *(uint32_t*)&g_avlo[base] = l;
        }
        {
            uint32_t h, l;
            split2_f16(oacc[jd][2] * invB, oacc[jd][3] * invB, h, l);
            size_t base = (size_t)(b * 2048 + rowB) * 1024 + col;
            *(uint32_t*)&g_avhi[base] = h;
            *(uint32_t*)&g_avlo[base] = l;
        }
    }
}

// ============================================================================
extern "C" void kernel_launch(void* const* d_in, const int* in_sizes, int n_in,
                              void* d_out, int out_size)
{
    const float* x    = (const float*)d_in[0];   // (4, 2048, 1024)
    const float* Wqkv = (const float*)d_in[1];   // (48, 1024, 64)
    const float* bqkv = (const float*)d_in[2];   // (48, 64)
    const float* Wp   = (const float*)d_in[3];   // (1024, 1024)
    const float* bp   = (const float*)d_in[4];   // (1024,)
    float* out = (float*)d_out;                  // (4, 2048, 1024)

    cudaFuncSetAttribute(gemm_qk, cudaFuncAttributeMaxDynamicSharedMemorySize,
                         GEMM_SMEM);
    cudaFuncSetAttribute(gemm_v16, cudaFuncAttributeMaxDynamicSharedMemorySize,
                         GF_SMEM);
    cudaFuncSetAttribute(gemm_proj, cudaFuncAttributeMaxDynamicSharedMemorySize,
                         GP_SMEM);
    cudaFuncSetAttribute(attn_mma, cudaFuncAttributeMaxDynamicSharedMemorySize,
                         ATTN_SMEM);

    // 1) preps
    prep_x<<<2048, 256>>>(x);
    prep_wp16<<<256, 256>>>(Wp);
    transpose_w<<<dim3(32, 2, 48), dim3(32, 8)>>>(Wqkv);

    // 2a) Q/K ensembles: 3-term bf16; epilogue emits pre-scaled/pre-split Q,K
    gemm_qk<<<dim3(64, 16), 256, GEMM_SMEM>>>(bqkv);
    // 2b) V ensembles: 1-term fp16 -> g_v16
    gemm_v16<<<dim3(64, 8), 256, GF_SMEM>>>(bqkv + 32 * 64);

    // 2.5) transpose V fp16 -> [hb][d][l]
    prep_vt<<<dim3(32, 64), 256>>>();

    // 3) attention (5-stage, 1 CTA/SM, 6.9 waves)
    attn_mma<<<dim3(16, 64), 256, ATTN_SMEM>>>();

    // 4) proj: 2-term split-fp16, 128x64 tiles, 5-stage, 1 CTA/SM
    gemm_proj<<<dim3(64, 16), 256, GP_SMEM>>>(bp, out);
}

// round 13
// speedup vs baseline: 1.1109x; 1.1109x over previous
#include <cuda_runtime.h>
#include <cuda_bf16.h>
#include <cuda_fp16.h>
#include <stdint.h>
#include <math.h>

// ============================================================================
// Scratch (device globals — no allocations allowed).
// ============================================================================
__device__ __align__(16) __nv_bfloat16 g_xhi [8192ull * 1024];
__device__ __align__(16) __nv_bfloat16 g_xlo [8192ull * 1024];
__device__ __align__(16) __half        g_x16 [8192ull * 1024];
__device__ __align__(16) __nv_bfloat16 g_wthi[32ull * 64 * 1024];   // Q/K W^T [e][h][d]
__device__ __align__(16) __nv_bfloat16 g_wtlo[32ull * 64 * 1024];
__device__ __align__(16) __half        g_wt16[16ull * 64 * 1024];   // V W^T fp16
__device__ __align__(16) __half        g_wp16[1024ull * 1024];      // Wp fp16
__device__ __align__(16) __half        g_avhi[8192ull * 1024];      // av split fp16
__device__ __align__(16) __half        g_avlo[8192ull * 1024];
__device__ __align__(16) __nv_bfloat16 g_qhi [16ull * 8192 * 64];   // [hd][row][d], scaled
__device__ __align__(16) __nv_bfloat16 g_qlo [16ull * 8192 * 64];
__device__ __align__(16) __nv_bfloat16 g_khi [16ull * 8192 * 64];
__device__ __align__(16) __nv_bfloat16 g_klo [16ull * 8192 * 64];
__device__ __align__(16) __half        g_v16 [16ull * 8192 * 64];   // [hd][row][d]
__device__ __align__(16) __half        g_vt16[64ull * 64 * 2048];   // [hb][d][l]

// ============================================================================
// PTX helpers (sm_80-era ISA — compiles for plain compute_103)
// ============================================================================
__device__ __forceinline__ uint32_t smem_u32(const void* p) {
    uint32_t a;
    asm("{ .reg .u64 t; cvta.to.shared.u64 t, %1; cvt.u32.u64 %0, t; }"
        : "=r"(a) : "l"(p));
    return a;
}

__device__ __forceinline__ void ldmatrix_x4(uint32_t& r0, uint32_t& r1,
                                            uint32_t& r2, uint32_t& r3,
                                            uint32_t addr) {
    asm volatile("ldmatrix.sync.aligned.m8n8.x4.shared.b16 {%0,%1,%2,%3}, [%4];"
                 : "=r"(r0), "=r"(r1), "=r"(r2), "=r"(r3) : "r"(addr));
}

__device__ __forceinline__ void mma_bf16(float* c,
                                         uint32_t a0, uint32_t a1, uint32_t a2, uint32_t a3,
                                         uint32_t b0, uint32_t b1) {
    asm volatile("mma.sync.aligned.m16n8k16.row.col.f32.bf16.bf16.f32 "
                 "{%0,%1,%2,%3}, {%4,%5,%6,%7}, {%8,%9}, {%0,%1,%2,%3};"
                 : "+f"(c[0]), "+f"(c[1]), "+f"(c[2]), "+f"(c[3])
                 : "r"(a0), "r"(a1), "r"(a2), "r"(a3), "r"(b0), "r"(b1));
}

__device__ __forceinline__ void mma_f16(float* c,
                                        uint32_t a0, uint32_t a1, uint32_t a2, uint32_t a3,
                                        uint32_t b0, uint32_t b1) {
    asm volatile("mma.sync.aligned.m16n8k16.row.col.f32.f16.f16.f32 "
                 "{%0,%1,%2,%3}, {%4,%5,%6,%7}, {%8,%9}, {%0,%1,%2,%3};"
                 : "+f"(c[0]), "+f"(c[1]), "+f"(c[2]), "+f"(c[3])
                 : "r"(a0), "r"(a1), "r"(a2), "r"(a3), "r"(b0), "r"(b1));
}

__device__ __forceinline__ void cp_async16(uint32_t dst, const void* src) {
    asm volatile("cp.async.cg.shared.global [%0], [%1], 16;"
                 :: "r"(dst), "l"(src) : "memory");
}
__device__ __forceinline__ void cp_commit() {
    asm volatile("cp.async.commit_group;" ::: "memory");
}
template <int N>
__device__ __forceinline__ void cp_wait() {
    asm volatile("cp.async.wait_group %0;" :: "n"(N) : "memory");
}

__device__ __forceinline__ uint32_t pack_bf16x2(float x, float y) {
    uint32_t r;
    asm("cvt.rn.bf16x2.f32 %0, %1, %2;" : "=r"(r) : "f"(y), "f"(x));
    return r;
}
__device__ __forceinline__ uint32_t pack_f16x2(float x, float y) {
    uint32_t r;
    asm("cvt.rn.f16x2.f32 %0, %1, %2;" : "=r"(r) : "f"(y), "f"(x));
    return r;
}

// fast 2^t for t <= 0, FFMA/ALU only (no MUFU). rel err ~2.5e-6.
__device__ __forceinline__ float exp2_fast(float t) {
    float r = fmaxf(t, -30.f);
    float z = r + 12582912.f;
    int   i = __float_as_int(z);
    float f = r - (z - 12582912.f);
    float p = 1.33335581e-3f;
    p = fmaf(p, f, 9.61812911e-3f);
    p = fmaf(p, f, 5.55041087e-2f);
    p = fmaf(p, f, 2.40226507e-1f);
    p = fmaf(p, f, 6.93147181e-1f);
    p = fmaf(p, f, 1.0f);
    return p * __int_as_float((i + 127) << 23);
}

__device__ __forceinline__ void split4(float4 v, uint32_t& h01, uint32_t& h23,
                                       uint32_t& l01, uint32_t& l23) {
    h01 = pack_bf16x2(v.x, v.y);
    h23 = pack_bf16x2(v.z, v.w);
    float r0 = v.x - __int_as_float(h01 << 16);
    float r1 = v.y - __int_as_float(h01 & 0xFFFF0000u);
    float r2 = v.z - __int_as_float(h23 << 16);
    float r3 = v.w - __int_as_float(h23 & 0xFFFF0000u);
    l01 = pack_bf16x2(r0, r1);
    l23 = pack_bf16x2(r2, r3);
}

__device__ __forceinline__ void split2_bf(float a, float b, uint32_t& h, uint32_t& l) {
    h = pack_bf16x2(a, b);
    float ra = a - __int_as_float(h << 16);
    float rb = b - __int_as_float(h & 0xFFFF0000u);
    l = pack_bf16x2(ra, rb);
}

__device__ __forceinline__ void split2_f16(float a, float b, uint32_t& h, uint32_t& l) {
    h = pack_f16x2(a, b);
    float ha = __half2float(__ushort_as_half((unsigned short)(h & 0xFFFFu)));
    float hb = __half2float(__ushort_as_half((unsigned short)(h >> 16)));
    l = pack_f16x2(a - ha, b - hb);
}

// ============================================================================
// Prep kernels: prep_xw fuses x-split and Wp->fp16 (branch by block range).
// ============================================================================
__global__ __launch_bounds__(256)
void prep_xw(const float* __restrict__ x, const float* __restrict__ Wp) {
    if (blockIdx.x < 2048) {
        #pragma unroll
        for (int i = 0; i < 4; ++i) {
            size_t idx = (size_t)blockIdx.x * 256 + threadIdx.x + (size_t)i * 524288;
            float4 v = *(const float4*)(x + idx * 4);
            uint32_t h01, h23, l01, l23;
            split4(v, h01, h23, l01, l23);
            *(uint2*)&g_xhi[idx * 4] = make_uint2(h01, h23);
            *(uint2*)&g_xlo[idx * 4] = make_uint2(l01, l23);
            *(uint2*)&g_x16[idx * 4] = make_uint2(pack_f16x2(v.x, v.y),
                                                  pack_f16x2(v.z, v.w));
        }
    } else {
        size_t base = (size_t)(blockIdx.x - 2048) * 256 + threadIdx.x;
        #pragma unroll
        for (int i = 0; i < 4; ++i) {
            size_t idx = base + (size_t)i * 65536;
            float4 v = *(const float4*)(Wp + idx * 4);
            *(uint2*)&g_wp16[idx * 4] = make_uint2(pack_f16x2(v.x, v.y),
                                                   pack_f16x2(v.z, v.w));
        }
    }
}

// transpose Wqkv [48][1024][64] -> Q/K: split bf16 [e][64][1024]; V: fp16.
__global__ void transpose_w(const float* __restrict__ W) {
    __shared__ float t[32][33];
    const int e  = blockIdx.z;
    const int k0 = blockIdx.x * 32;
    const int h0 = blockIdx.y * 32;
    const int tx = threadIdx.x, ty = threadIdx.y;
    #pragma unroll
    for (int i = 0; i < 32; i += 8)
        t[ty + i][tx] = W[(size_t)e * 65536 + (size_t)(k0 + ty + i) * 64 + h0 + tx];
    __syncthreads();
    #pragma unroll
    for (int i = 0; i < 32; i += 8) {
        float val = t[tx][ty + i];
        if (e < 32) {
            __nv_bfloat16 hi = __float2bfloat16(val);
            __nv_bfloat16 lo = __float2bfloat16(val - __bfloat162float(hi));
            size_t off = (size_t)e * 65536 + (size_t)(h0 + ty + i) * 1024 + k0 + tx;
            g_wthi[off] = hi;
            g_wtlo[off] = lo;
        } else {
            size_t o16 = (size_t)(e - 32) * 65536 + (size_t)(h0 + ty + i) * 1024 + k0 + tx;
            g_wt16[o16] = __float2half(val);
        }
    }
}

// transpose V fp16 [hb][l][d] -> [hb][d][l]
__global__ __launch_bounds__(256)
void prep_vt()
{
    __shared__ __half t[64 * 72];
    const int tid = threadIdx.x;
    const int hb  = blockIdx.y;
    const int l0  = blockIdx.x * 64;

    const __half* src = g_v16 + ((size_t)hb * 2048 + l0) * 64;
    #pragma unroll
    for (int i = 0; i < 4; ++i) {
        int idx = tid + i * 256;
        int l   = idx >> 4;
        int c4  = idx & 15;
        uint2 v = *(const uint2*)(src + (size_t)l * 64 + c4 * 4);
        int d = c4 * 4;
        t[(d + 0) * 72 + l] = __ushort_as_half((unsigned short)(v.x & 0xFFFF));
        t[(d + 1) * 72 + l] = __ushort_as_half((unsigned short)(v.x >> 16));
        t[(d + 2) * 72 + l] = __ushort_as_half((unsigned short)(v.y & 0xFFFF));
        t[(d + 3) * 72 + l] = __ushort_as_half((unsigned short)(v.y >> 16));
    }
    __syncthreads();
    #pragma unroll
    for (int i = 0; i < 2; ++i) {
        int idx = tid + i * 256;
        int d   = idx >> 3;
        int c   = idx & 7;
        uint4 v = *(uint4*)&t[d * 72 + c * 8];
        *(uint4*)&g_vt16[((size_t)hb * 64 + d) * 2048 + l0 + c * 8] = v;
    }
}

// ============================================================================
// gemm_qkv: fused QKV projection. blockIdx.y 0..15 -> Q/K (3-term bf16,
//   128x128 tile); blockIdx.y 16..23 -> V (1-term fp16, 128x128 tile).
//   One launch = V CTAs backfill the Q/K tail wave.
// ============================================================================
#define LDA 80u
#define G2_AHI 0u
#define G2_ALO 10240u
#define G2_BHI 20480u
#define G2_BLO 30720u
#define G2_STG 40960u
#define GEMM_SMEM (3 * 40960)
#define GF_A 0u
#define GF_B 10240u
#define GF_STG 20480u

__global__ __launch_bounds__(256)
void gemm_qkv(const float* __restrict__ bias)
{
    extern __shared__ __align__(128) char smem[];
    const uint32_t sb  = smem_u32(smem);
    const int tid  = threadIdx.x;
    const int lane = tid & 31;
    const int wid  = tid >> 5;
    const int wm   = wid & 1;
    const int wn   = wid >> 1;
    const int m0   = blockIdx.x * 128;

    const int cp_r = tid >> 2;
    const int cp_c = tid & 3;
    const int ce   = cp_c * 8;
    const uint32_t a_row = (uint32_t)(wm * 64 + (lane & 7) + ((lane >> 3) & 1) * 8);
    const uint32_t a_kb  = (uint32_t)(lane >> 4) * 16u;
    const uint32_t b_row = (uint32_t)(wn * 32 + (lane & 7) + (lane >> 4) * 8);
    const uint32_t b_kb  = (uint32_t)((lane >> 3) & 1) * 16u;
    const int g  = lane >> 2;
    const int tg = lane & 3;

    float acc[4][4][4];
    #pragma unroll
    for (int mt = 0; mt < 4; ++mt)
        #pragma unroll
        for (int nt = 0; nt < 4; ++nt)
            #pragma unroll
            for (int i = 0; i < 4; ++i) acc[mt][nt][i] = 0.f;

    if (blockIdx.y < 16) {
        // ==================== Q/K path: 3-term split bf16 ====================
        const int grp0 = blockIdx.y * 2;
        const __nv_bfloat16* Ahi = g_xhi;
        const __nv_bfloat16* Alo = g_xlo;
        const __nv_bfloat16* Bh0 = g_wthi + (size_t)grp0 * 65536;
        const __nv_bfloat16* Bl0 = g_wtlo + (size_t)grp0 * 65536;

        auto issue = [&](int ks, uint32_t stg) {
            const int k0 = ks * 32;
            uint32_t d0 = stg + (uint32_t)cp_r * LDA + (uint32_t)cp_c * 16u;
            uint32_t d1 = d0 + 64u * LDA;
            size_t a0 = (size_t)(m0 + cp_r) * 1024 + k0 + ce;
            size_t a1 = a0 + 64 * 1024;
            size_t b0 = (size_t)cp_r * 1024 + k0 + ce;
            cp_async16(d0 + G2_AHI, Ahi + a0);
            cp_async16(d1 + G2_AHI, Ahi + a1);
            cp_async16(d0 + G2_ALO, Alo + a0);
            cp_async16(d1 + G2_ALO, Alo + a1);
            cp_async16(d0 + G2_BHI, Bh0 + b0);
            cp_async16(d1 + G2_BHI, Bh0 + 65536 + b0);
            cp_async16(d0 + G2_BLO, Bl0 + b0);
            cp_async16(d1 + G2_BLO, Bl0 + 65536 + b0);
            cp_commit();
        };

        issue(0, sb);
        issue(1, sb + G2_STG);

        for (int ks = 0; ks < 32; ++ks) {
            if (ks < 31) cp_wait<1>(); else cp_wait<0>();
            __syncthreads();
            if (ks + 2 < 32) issue(ks + 2, sb + (uint32_t)((ks + 2) % 3) * G2_STG);

            const uint32_t stg = sb + (uint32_t)(ks % 3) * G2_STG;
            const uint32_t aHi = stg + G2_AHI + a_row * LDA + a_kb;
            const uint32_t aLo = stg + G2_ALO + a_row * LDA + a_kb;
            const uint32_t bHi = stg + G2_BHI + b_row * LDA + b_kb;
            const uint32_t bLo = stg + G2_BLO + b_row * LDA + b_kb;

            #pragma unroll
            for (int kk = 0; kk < 2; ++kk) {
                const uint32_t koff = (uint32_t)kk * 32u;

                uint32_t ahi[4][4], alo[4][4];
                #pragma unroll
                for (int mt = 0; mt < 4; ++mt) {
                    ldmatrix_x4(ahi[mt][0], ahi[mt][1], ahi[mt][2], ahi[mt][3],
                                aHi + (uint32_t)mt * 16u * LDA + koff);
                    ldmatrix_x4(alo[mt][0], alo[mt][1], alo[mt][2], alo[mt][3],
                                aLo + (uint32_t)mt * 16u * LDA + koff);
                }
                uint32_t bhi[4][2], blo[4][2];
                #pragma unroll
                for (int ntp = 0; ntp < 2; ++ntp) {
                    uint32_t r0, r1, r2, r3;
                    ldmatrix_x4(r0, r1, r2, r3, bHi + (uint32_t)ntp * 16u * LDA + koff);
                    bhi[ntp * 2][0] = r0; bhi[ntp * 2][1] = r1;
                    bhi[ntp * 2 + 1][0] = r2; bhi[ntp * 2 + 1][1] = r3;
                    ldmatrix_x4(r0, r1, r2, r3, bLo + (uint32_t)ntp * 16u * LDA + koff);
                    blo[ntp * 2][0] = r0; blo[ntp * 2][1] = r1;
                    blo[ntp * 2 + 1][0] = r2; blo[ntp * 2 + 1][1] = r3;
                }

                #pragma unroll
                for (int mt = 0; mt < 4; ++mt)
                    #pragma unroll
                    for (int nt = 0; nt < 4; ++nt) {
                        mma_bf16(acc[mt][nt], ahi[mt][0], ahi[mt][1], ahi[mt][2], ahi[mt][3],
                                 bhi[nt][0], bhi[nt][1]);
                        mma_bf16(acc[mt][nt], ahi[mt][0], ahi[mt][1], ahi[mt][2], ahi[mt][3],
                                 blo[nt][0], blo[nt][1]);
                        mma_bf16(acc[mt][nt], alo[mt][0], alo[mt][1], alo[mt][2], alo[mt][3],
                                 bhi[nt][0], bhi[nt][1]);
                    }
            }
        }

        const float QSCALE = 11.5415603272f;
        #pragma unroll
        for (int mt = 0; mt < 4; ++mt)
            #pragma unroll
            for (int nt = 0; nt < 4; ++nt) {
                int n    = wn * 32 + nt * 8 + tg * 2;
                int gsel = n >> 6;
                int c64  = n & 63;
                int e    = grp0 + gsel;
                const float* bp = bias + (size_t)e * 64;
                float b0 = bp[c64], b1 = bp[c64 + 1];
                int r0 = m0 + wm * 64 + mt * 16 + g;
                float v00 = acc[mt][nt][0] + b0, v01 = acc[mt][nt][1] + b1;
                float v10 = acc[mt][nt][2] + b0, v11 = acc[mt][nt][3] + b1;
                bool isQ = (e < 16);
                float s = isQ ? QSCALE : 1.f;
                v00 *= s; v01 *= s; v10 *= s; v11 *= s;
                __nv_bfloat16* dh = isQ ? g_qhi : g_khi;
                __nv_bfloat16* dl = isQ ? g_qlo : g_klo;
                int eo = isQ ? e : (e - 16);
                size_t base0 = ((size_t)eo * 8192 + r0) * 64 + c64;
                size_t base1 = base0 + 8 * 64;
                uint32_t h, l;
                split2_bf(v00, v01, h, l);
                *(uint32_t*)&dh[base0] = h;
                *(uint32_t*)&dl[base0] = l;
                split2_bf(v10, v11, h, l);
                *(uint32_t*)&dh[base1] = h;
                *(uint32_t*)&dl[base1] = l;
            }
    } else {
        // ==================== V path: 1-term fp16 ====================
        const int grp0 = (blockIdx.y - 16) * 2;
        const float* biasv = bias + 32 * 64;
        const __half* A  = g_x16;
        const __half* B0 = g_wt16 + (size_t)grp0 * 65536;

        auto issue = [&](int ks, uint32_t stg) {
            const int k0 = ks * 32;
            uint32_t d0 = stg + (uint32_t)cp_r * LDA + (uint32_t)cp_c * 16u;
            uint32_t d1 = d0 + 64u * LDA;
            size_t a0 = (size_t)(m0 + cp_r) * 1024 + k0 + ce;
            size_t a1 = a0 + 64 * 1024;
            size_t b0 = (size_t)cp_r * 1024 + k0 + ce;
            cp_async16(d0 + GF_A, A + a0);
            cp_async16(d1 + GF_A, A + a1);
            cp_async16(d0 + GF_B, B0 + b0);
            cp_async16(d1 + GF_B, B0 + 65536 + b0);
            cp_commit();
        };

        issue(0, sb);
        issue(1, sb + GF_STG);

        for (int ks = 0; ks < 32; ++ks) {
            if (ks < 31) cp_wait<1>(); else cp_wait<0>();
            __syncthreads();
            if (ks + 2 < 32) issue(ks + 2, sb + (uint32_t)((ks + 2) % 3) * GF_STG);

            const uint32_t stg = sb + (uint32_t)(ks % 3) * GF_STG;
            const uint32_t aB = stg + GF_A + a_row * LDA + a_kb;
            const uint32_t bB = stg + GF_B + b_row * LDA + b_kb;

            #pragma unroll
            for (int kk = 0; kk < 2; ++kk) {
                const uint32_t koff = (uint32_t)kk * 32u;

                uint32_t af[4][4];
                #pragma unroll
                for (int mt = 0; mt < 4; ++mt)
                    ldmatrix_x4(af[mt][0], af[mt][1], af[mt][2], af[mt][3],
                                aB + (uint32_t)mt * 16u * LDA + koff);
                uint32_t bf[4][2];
                #pragma unroll
                for (int ntp = 0; ntp < 2; ++ntp) {
                    uint32_t r0, r1, r2, r3;
                    ldmatrix_x4(r0, r1, r2, r3, bB + (uint32_t)ntp * 16u * LDA + koff);
                    bf[ntp * 2][0] = r0; bf[ntp * 2][1] = r1;
                    bf[ntp * 2 + 1][0] = r2; bf[ntp * 2 + 1][1] = r3;
                }

                #pragma unroll
                for (int mt = 0; mt < 4; ++mt)
                    #pragma unroll
                    for (int nt = 0; nt < 4; ++nt)
                        mma_f16(acc[mt][nt], af[mt][0], af[mt][1], af[mt][2], af[mt][3],
                                bf[nt][0], bf[nt][1]);
            }
        }

        #pragma unroll
        for (int mt = 0; mt < 4; ++mt)
            #pragma unroll
            for (int nt = 0; nt < 4; ++nt) {
                int n    = wn * 32 + nt * 8 + tg * 2;
                int gsel = n >> 6;
                int c64  = n & 63;
                int e    = grp0 + gsel;
                const float* bp = biasv + (size_t)e * 64;
                float b0 = bp[c64], b1 = bp[c64 + 1];
                int r0 = m0 + wm * 64 + mt * 16 + g;
                size_t base0 = ((size_t)e * 8192 + r0) * 64 + c64;
                size_t base1 = base0 + 8 * 64;
                *(uint32_t*)&g_v16[base0] =
                    pack_f16x2(acc[mt][nt][0] + b0, acc[mt][nt][1] + b1);
                *(uint32_t*)&g_v16[base1] =
                    pack_f16x2(acc[mt][nt][2] + b0, acc[mt][nt][3] + b1);
            }
    }
}

// ============================================================================
// gemm_proj: 128x128 tile, 2-term split-fp16, 3-stage, 2 CTAs/SM (R11 proven).
// ============================================================================
#define GP_AHI 0u
#define GP_ALO 10240u
#define GP_B   20480u
#define GP_STG 30720u
#define GP_SMEM (3 * 30720)

__global__ __launch_bounds__(256)
void gemm_proj(const float* __restrict__ bias, float* __restrict__ C)
{
    extern __shared__ __align__(128) char smem[];
    const uint32_t sb  = smem_u32(smem);
    const int tid  = threadIdx.x;
    const int lane = tid & 31;
    const int wid  = tid >> 5;
    const int wm   = wid & 1;
    const int wn   = wid >> 1;
    const int m0   = blockIdx.x * 128;
    const int n0   = blockIdx.y * 128;

    const __half* Ahi = g_avhi;
    const __half* Alo = g_avlo;
    const __half* B0  = g_wp16 + (size_t)n0 * 1024;

    float acc[4][4][4];
    #pragma unroll
    for (int mt = 0; mt < 4; ++mt)
        #pragma unroll
        for (int nt = 0; nt < 4; ++nt)
            #pragma unroll
            for (int i = 0; i < 4; ++i) acc[mt][nt][i] = 0.f;

    const int cp_r = tid >> 2;
    const int cp_c = tid & 3;
    const int ce   = cp_c * 8;
    auto issue = [&](int ks, uint32_t stg) {
        const int k0 = ks * 32;
        uint32_t d0 = stg + (uint32_t)cp_r * LDA + (uint32_t)cp_c * 16u;
        uint32_t d1 = d0 + 64u * LDA;
        size_t a0 = (size_t)(m0 + cp_r) * 1024 + k0 + ce;
        size_t a1 = a0 + 64 * 1024;
        size_t b0 = (size_t)cp_r * 1024 + k0 + ce;
        cp_async16(d0 + GP_AHI, Ahi + a0);
        cp_async16(d1 + GP_AHI, Ahi + a1);
        cp_async16(d0 + GP_ALO, Alo + a0);
        cp_async16(d1 + GP_ALO, Alo + a1);
        cp_async16(d0 + GP_B, B0 + b0);
        cp_async16(d1 + GP_B, B0 + 65536 + b0);
        cp_commit();
    };

    const uint32_t a_row = (uint32_t)(wm * 64 + (lane & 7) + ((lane >> 3) & 1) * 8);
    const uint32_t a_kb  = (uint32_t)(lane >> 4) * 16u;
    const uint32_t b_row = (uint32_t)(wn * 32 + (lane & 7) + (lane >> 4) * 8);
    const uint32_t b_kb  = (uint32_t)((lane >> 3) & 1) * 16u;

    issue(0, sb);
    issue(1, sb + GP_STG);

    for (int ks = 0; ks < 32; ++ks) {
        if (ks < 31) cp_wait<1>(); else cp_wait<0>();
        __syncthreads();
        if (ks + 2 < 32) issue(ks + 2, sb + (uint32_t)((ks + 2) % 3) * GP_STG);

        const uint32_t stg = sb + (uint32_t)(ks % 3) * GP_STG;
        const uint32_t aHi = stg + GP_AHI + a_row * LDA + a_kb;
        const uint32_t aLo = stg + GP_ALO + a_row * LDA + a_kb;
        const uint32_t bB  = stg + GP_B   + b_row * LDA + b_kb;

        #pragma unroll
        for (int kk = 0; kk < 2; ++kk) {
            const uint32_t koff = (uint32_t)kk * 32u;

            uint32_t ahi[4][4], alo[4][4];
            #pragma unroll
            for (int mt = 0; mt < 4; ++mt) {
                ldmatrix_x4(ahi[mt][0], ahi[mt][1], ahi[mt][2], ahi[mt][3],
                            aHi + (uint32_t)mt * 16u * LDA + koff);
                ldmatrix_x4(alo[mt][0], alo[mt][1], alo[mt][2], alo[mt][3],
                            aLo + (uint32_t)mt * 16u * LDA + koff);
            }
            uint32_t bf[4][2];
            #pragma unroll
            for (int ntp = 0; ntp < 2; ++ntp) {
                uint32_t r0, r1, r2, r3;
                ldmatrix_x4(r0, r1, r2, r3, bB + (uint32_t)ntp * 16u * LDA + koff);
                bf[ntp * 2][0] = r0; bf[ntp * 2][1] = r1;
                bf[ntp * 2 + 1][0] = r2; bf[ntp * 2 + 1][1] = r3;
            }

            #pragma unroll
            for (int mt = 0; mt < 4; ++mt)
                #pragma unroll
                for (int nt = 0; nt < 4; ++nt) {
                    mma_f16(acc[mt][nt], ahi[mt][0], ahi[mt][1], ahi[mt][2], ahi[mt][3],
                            bf[nt][0], bf[nt][1]);
                    mma_f16(acc[mt][nt], alo[mt][0], alo[mt][1], alo[mt][2], alo[mt][3],
                            bf[nt][0], bf[nt][1]);
                }
        }
    }

    const int g  = lane >> 2;
    const int tg = lane & 3;
    #pragma unroll
    for (int mt = 0; mt < 4; ++mt)
        #pragma unroll
        for (int nt = 0; nt < 4; ++nt) {
            int n = n0 + wn * 32 + nt * 8 + tg * 2;
            float b0 = bias[n], b1 = bias[n + 1];
            int r0 = m0 + wm * 64 + mt * 16 + g;
            float2 o0 = make_float2(acc[mt][nt][0] + b0, acc[mt][nt][1] + b1);
            float2 o1 = make_float2(acc[mt][nt][2] + b0, acc[mt][nt][3] + b1);
            *(float2*)(C + (size_t)r0 * 1024 + n)       = o0;
            *(float2*)(C + (size_t)(r0 + 8) * 1024 + n) = o1;
        }
}

// ============================================================================
// attn_mma: flash attention (R11 proven config). S 3-term bf16, PV 1-term fp16.
//   3-stage cp.async, 2 CTAs/SM. Emits av split fp16.
// ============================================================================
#define LDS_ROW 144u
#define ST_KHI 0u
#define ST_KLO 9216u
#define ST_V16 18432u
#define STAGE_BYTES 27648u
#define ATTN_SMEM (3 * 27648)

__global__ __launch_bounds__(256, 2)
void attn_mma()
{
    extern __shared__ __align__(128) char smem[];
    const uint32_t sb = smem_u32(smem);
    const int tid  = threadIdx.x;
    const int lane = tid & 31;
    const int wid  = tid >> 5;
    const int g    = lane >> 2;
    const int tg   = lane & 3;
    const int hb   = blockIdx.y;
    const int hd   = hb >> 2;
    const int b    = hb & 3;
    const int q0   = blockIdx.x * 128;

    const __nv_bfloat16* Qhi = g_qhi + ((size_t)hd * 8192 + b * 2048 + q0) * 64;
    const __nv_bfloat16* Qlo = g_qlo + ((size_t)hd * 8192 + b * 2048 + q0) * 64;
    const __nv_bfloat16* Khi = g_khi + (size_t)hb * 2048 * 64;
    const __nv_bfloat16* Klo = g_klo + (size_t)hb * 2048 * 64;
    const __half*        V16 = g_vt16 + (size_t)hb * 64 * 2048;

    // ---- stage Q (pre-scaled, pre-split) via cp.async, extract fragments ----
    #pragma unroll
    for (int i = 0; i < 4; ++i) {
        int idx = tid + i * 256;
        int row = idx >> 3;
        int c   = idx & 7;
        cp_async16(sb + (uint32_t)row * LDS_ROW + (uint32_t)c * 16u,
                   Qhi + (size_t)row * 64 + c * 8);
        cp_async16(sb + 18432u + (uint32_t)row * LDS_ROW + (uint32_t)c * 16u,
                   Qlo + (size_t)row * 64 + c * 8);
    }
    cp_commit();
    cp_wait<0>();
    __syncthreads();

    uint32_t qhi[4][4], qlo[4][4];
    {
        const uint32_t qrow = (uint32_t)(wid * 16 + (lane & 7) + ((lane >> 3) & 1) * 8);
        const uint32_t kb   = (uint32_t)(lane >> 4) * 16u;
        const uint32_t aH = sb + qrow * LDS_ROW + kb;
        const uint32_t aL = sb + 18432u + qrow * LDS_ROW + kb;
        #pragma unroll
        for (int t = 0; t < 4; ++t) {
            ldmatrix_x4(qhi[t][0], qhi[t][1], qhi[t][2], qhi[t][3], aH + t * 32u);
            ldmatrix_x4(qlo[t][0], qlo[t][1], qlo[t][2], qlo[t][3], aL + t * 32u);
        }
    }
    __syncthreads();   // Q consumed — smem free for stages

    float mA = -1e30f, mB = -1e30f, lA = 0.f, lB = 0.f;
    float oacc[8][4];
    #pragma unroll
    for (int j = 0; j < 8; ++j)
        #pragma unroll
        for (int i = 0; i < 4; ++i) oacc[j][i] = 0.f;

    const uint32_t brow = (uint32_t)((lane & 7) + (lane >> 4) * 8);
    const uint32_t bkb  = (uint32_t)((lane >> 3) & 1) * 16u;

    const int cp_row = tid >> 3;
    const int cp_c   = tid & 7;
    auto issue = [&](int j0, uint32_t stg) {
        #pragma unroll
        for (int i = 0; i < 2; ++i) {
            int row = cp_row + i * 32;
            uint32_t doff = stg + (uint32_t)row * LDS_ROW + (uint32_t)cp_c * 16u;
            cp_async16(doff + ST_KHI, Khi + ((size_t)(j0 + row)) * 64 + cp_c * 8);
            cp_async16(doff + ST_KLO, Klo + ((size_t)(j0 + row)) * 64 + cp_c * 8);
            cp_async16(doff + ST_V16, V16 + ((size_t)row) * 2048 + j0 + cp_c * 8);
        }
        cp_commit();
    };

    issue(0, sb);
    issue(64, sb + STAGE_BYTES);

    for (int j = 0; j < 32; ++j) {
        if (j < 31) cp_wait<1>(); else cp_wait<0>();
        __syncthreads();
        if (j + 2 < 32) issue((j + 2) * 64, sb + (uint32_t)((j + 2) % 3) * STAGE_BYTES);

        const uint32_t stg = sb + (uint32_t)(j % 3) * STAGE_BYTES;

        // ---- S = Qscaled @ K^T (split 3-term bf16), log2 units ----
        float sacc[8][4];
        #pragma unroll
        for (int jj = 0; jj < 8; ++jj)
            #pragma unroll
            for (int i = 0; i < 4; ++i) sacc[jj][i] = 0.f;

        #pragma unroll
        for (int td = 0; td < 4; ++td) {
            uint32_t bhi[8][2], blo[8][2];
            #pragma unroll
            for (int ntp = 0; ntp < 4; ++ntp) {
                uint32_t base = (uint32_t)(ntp * 16) * LDS_ROW + brow * LDS_ROW + bkb
                                + (uint32_t)td * 32u;
                uint32_t r0, r1, r2, r3;
                ldmatrix_x4(r0, r1, r2, r3, stg + ST_KHI + base);
                bhi[ntp * 2][0] = r0; bhi[ntp * 2][1] = r1;
                bhi[ntp * 2 + 1][0] = r2; bhi[ntp * 2 + 1][1] = r3;
                ldmatrix_x4(r0, r1, r2, r3, stg + ST_KLO + base);
                blo[ntp * 2][0] = r0; blo[ntp * 2][1] = r1;
                blo[ntp * 2 + 1][0] = r2; blo[ntp * 2 + 1][1] = r3;
            }
            #pragma unroll
            for (int nt = 0; nt < 8; ++nt) {
                mma_bf16(sacc[nt], qhi[td][0], qhi[td][1], qhi[td][2], qhi[td][3],
                         bhi[nt][0], bhi[nt][1]);
                mma_bf16(sacc[nt], qhi[td][0], qhi[td][1], qhi[td][2], qhi[td][3],
                         blo[nt][0], blo[nt][1]);
                mma_bf16(sacc[nt], qlo[td][0], qlo[td][1], qlo[td][2], qlo[td][3],
                         bhi[nt][0], bhi[nt][1]);
            }
        }

        // ---- online softmax (log2 domain) ----
        float rmA = -1e30f, rmB = -1e30f;
        #pragma unroll
        for (int jj = 0; jj < 8; ++jj) {
            rmA = fmaxf(rmA, fmaxf(sacc[jj][0], sacc[jj][1]));
            rmB = fmaxf(rmB, fmaxf(sacc[jj][2], sacc[jj][3]));
        }
        rmA = fmaxf(rmA, __shfl_xor_sync(0xffffffffu, rmA, 1));
        rmA = fmaxf(rmA, __shfl_xor_sync(0xffffffffu, rmA, 2));
        rmB = fmaxf(rmB, __shfl_xor_sync(0xffffffffu, rmB, 1));
        rmB = fmaxf(rmB, __shfl_xor_sync(0xffffffffu, rmB, 2));

        float mnA = fmaxf(mA, rmA), mnB = fmaxf(mB, rmB);
        float corrA = exp2_fast(mA - mnA), corrB = exp2_fast(mB - mnB);

        float sumA = 0.f, sumB = 0.f;
        uint32_t pf[4][4];
        #pragma unroll
        for (int jj = 0; jj < 8; ++jj) {
            float p0 = exp2_fast(sacc[jj][0] - mnA);
            float p1 = exp2_fast(sacc[jj][1] - mnA);
            float p2 = exp2_fast(sacc[jj][2] - mnB);
            float p3 = exp2_fast(sacc[jj][3] - mnB);
            sumA += p0 + p1; sumB += p2 + p3;
            int t = jj >> 1;
            int o = (jj & 1) * 2;
            pf[t][o]     = pack_f16x2(p0, p1);
            pf[t][o + 1] = pack_f16x2(p2, p3);
        }
        sumA += __shfl_xor_sync(0xffffffffu, sumA, 1);
        sumA += __shfl_xor_sync(0xffffffffu, sumA, 2);
        sumB += __shfl_xor_sync(0xffffffffu, sumB, 1);
        sumB += __shfl_xor_sync(0xffffffffu, sumB, 2);

        lA = lA * corrA + sumA;
        lB = lB * corrB + sumB;
        mA = mnA; mB = mnB;

        #pragma unroll
        for (int jj = 0; jj < 8; ++jj) {
            oacc[jj][0] *= corrA; oacc[jj][1] *= corrA;
            oacc[jj][2] *= corrB; oacc[jj][3] *= corrB;
        }

        // ---- O += P @ V (1-term fp16) ----
        #pragma unroll
        for (int t = 0; t < 4; ++t) {
            uint32_t vf[8][2];
            #pragma unroll
            for (int ntp = 0; ntp < 4; ++ntp) {
                uint32_t base = (uint32_t)(ntp * 16) * LDS_ROW + brow * LDS_ROW + bkb
                                + (uint32_t)t * 32u;
                uint32_t r0, r1, r2, r3;
                ldmatrix_x4(r0, r1, r2, r3, stg + ST_V16 + base);
                vf[ntp * 2][0] = r0; vf[ntp * 2][1] = r1;
                vf[ntp * 2 + 1][0] = r2; vf[ntp * 2 + 1][1] = r3;
            }
            #pragma unroll
            for (int nd = 0; nd < 8; ++nd)
                mma_f16(oacc[nd], pf[t][0], pf[t][1], pf[t][2], pf[t][3],
                        vf[nd][0], vf[nd][1]);
        }
    }

    // ---- epilogue: normalize, split to fp16 hi/lo, write g_avhi/g_avlo ----
    const float invA = 1.f / lA, invB = 1.f / lB;
    const int rowA = q0 + wid * 16 + g;
    const int rowB = rowA + 8;
    #pragma unroll
    for (int jd = 0; jd < 8; ++jd) {
        int col = hd * 64 + jd * 8 + tg * 2;
        {
            uint32_t h, l;
            split2_f16(oacc[jd][0] * invA, oacc[jd][1] * invA, h, l);
            size_t base = (size_t)(b * 2048 + rowA) * 1024 + col;
            *(uint32_t*)&g_avhi[base] = h;
            *(uint32_t*)&g_avlo[base] = l;
        }
        {
            uint32_t h, l;
            split2_f16(oacc[jd][2] * invB, oacc[jd][3] * invB, h, l);
            size_t base = (size_t)(b * 2048 + rowB) * 1024 + col;
            *(uint32_t*)&g_avhi[base] = h;
            *(uint32_t*)&g_avlo[base] = l;
        }
    }
}

// ============================================================================
extern "C" void kernel_launch(void* const* d_in, const int* in_sizes, int n_in,
                              void* d_out, int out_size)
{
    const float* x    = (const float*)d_in[0];   // (4, 2048, 1024)
    const float* Wqkv = (const float*)d_in[1];   // (48, 1024, 64)
    const float* bqkv = (const float*)d_in[2];   // (48, 64)
    const float* Wp   = (const float*)d_in[3];   // (1024, 1024)
    const float* bp   = (const float*)d_in[4];   // (1024,)
    float* out = (float*)d_out;                  // (4, 2048, 1024)

    cudaFuncSetAttribute(gemm_qkv, cudaFuncAttributeMaxDynamicSharedMemorySize,
                         GEMM_SMEM);
    cudaFuncSetAttribute(gemm_proj, cudaFuncAttributeMaxDynamicSharedMemorySize,
                         GP_SMEM);
    cudaFuncSetAttribute(attn_mma, cudaFuncAttributeMaxDynamicSharedMemorySize,
                         ATTN_SMEM);

    // 1) preps: fused x-split + Wp->fp16; transpose/split Wqkv
    prep_xw<<<2304, 256>>>(x, Wp);
    transpose_w<<<dim3(32, 2, 48), dim3(32, 8)>>>(Wqkv);

    // 2) fused QKV: Q/K 3-term bf16 (y 0..15) + V 1-term fp16 (y 16..23)
    gemm_qkv<<<dim3(64, 24), 256, GEMM_SMEM>>>(bqkv);

    // 2.5) transpose V fp16 -> [hb][d][l]
    prep_vt<<<dim3(32, 64), 256>>>();

    // 3) attention (3-stage, 2 CTAs/SM — R11 proven)
    attn_mma<<<dim3(16, 64), 256, ATTN_SMEM>>>();

    // 4) proj: 2-term split-fp16, 128x128 tiles, 3-stage (R11 proven)
    gemm_proj<<<dim3(64, 8), 256, GP_SMEM>>>(bp, out);
}

// round 15
// speedup vs baseline: 1.1264x; 1.0139x over previous
#include <cuda_runtime.h>
#include <cuda_bf16.h>
#include <cuda_fp16.h>
#include <stdint.h>
#include <math.h>

// ============================================================================
// Scratch (device globals — no allocations allowed).
// ============================================================================
__device__ __align__(16) __nv_bfloat16 g_xhi [8192ull * 1024];
__device__ __align__(16) __nv_bfloat16 g_xlo [8192ull * 1024];
__device__ __align__(16) __half        g_x16 [8192ull * 1024];
__device__ __align__(16) __nv_bfloat16 g_wthi[32ull * 64 * 1024];   // Q/K W^T [e][h][d]
__device__ __align__(16) __nv_bfloat16 g_wtlo[32ull * 64 * 1024];
__device__ __align__(16) __half        g_wt16[16ull * 64 * 1024];   // V W^T fp16
__device__ __align__(16) __half        g_wp16[1024ull * 1024];      // Wp fp16
__device__ __align__(16) __half        g_avhi[8192ull * 1024];      // av split fp16
__device__ __align__(16) __half        g_avlo[8192ull * 1024];
__device__ __align__(16) __nv_bfloat16 g_qhi [16ull * 8192 * 64];   // [hd][row][d], scaled
__device__ __align__(16) __nv_bfloat16 g_qlo [16ull * 8192 * 64];
__device__ __align__(16) __nv_bfloat16 g_khi [16ull * 8192 * 64];
__device__ __align__(16) __nv_bfloat16 g_klo [16ull * 8192 * 64];
__device__ __align__(16) __half        g_vt16[64ull * 64 * 2048];   // [hb][d][l]

// ============================================================================
// PTX helpers (sm_80-era ISA — compiles for plain compute_103)
// ============================================================================
__device__ __forceinline__ uint32_t smem_u32(const void* p) {
    uint32_t a;
    asm("{ .reg .u64 t; cvta.to.shared.u64 t, %1; cvt.u32.u64 %0, t; }"
        : "=r"(a) : "l"(p));
    return a;
}

__device__ __forceinline__ void ldmatrix_x4(uint32_t& r0, uint32_t& r1,
                                            uint32_t& r2, uint32_t& r3,
                                            uint32_t addr) {
    asm volatile("ldmatrix.sync.aligned.m8n8.x4.shared.b16 {%0,%1,%2,%3}, [%4];"
                 : "=r"(r0), "=r"(r1), "=r"(r2), "=r"(r3) : "r"(addr));
}

__device__ __forceinline__ void mma_bf16(float* c,
                                         uint32_t a0, uint32_t a1, uint32_t a2, uint32_t a3,
                                         uint32_t b0, uint32_t b1) {
    asm volatile("mma.sync.aligned.m16n8k16.row.col.f32.bf16.bf16.f32 "
                 "{%0,%1,%2,%3}, {%4,%5,%6,%7}, {%8,%9}, {%0,%1,%2,%3};"
                 : "+f"(c[0]), "+f"(c[1]), "+f"(c[2]), "+f"(c[3])
                 : "r"(a0), "r"(a1), "r"(a2), "r"(a3), "r"(b0), "r"(b1));
}

__device__ __forceinline__ void mma_f16(float* c,
                                        uint32_t a0, uint32_t a1, uint32_t a2, uint32_t a3,
                                        uint32_t b0, uint32_t b1) {
    asm volatile("mma.sync.aligned.m16n8k16.row.col.f32.f16.f16.f32 "
                 "{%0,%1,%2,%3}, {%4,%5,%6,%7}, {%8,%9}, {%0,%1,%2,%3};"
                 : "+f"(c[0]), "+f"(c[1]), "+f"(c[2]), "+f"(c[3])
                 : "r"(a0), "r"(a1), "r"(a2), "r"(a3), "r"(b0), "r"(b1));
}

__device__ __forceinline__ void cp_async16(uint32_t dst, const void* src) {
    asm volatile("cp.async.cg.shared.global [%0], [%1], 16;"
                 :: "r"(dst), "l"(src) : "memory");
}
__device__ __forceinline__ void cp_commit() {
    asm volatile("cp.async.commit_group;" ::: "memory");
}
template <int N>
__device__ __forceinline__ void cp_wait() {
    asm volatile("cp.async.wait_group %0;" :: "n"(N) : "memory");
}

__device__ __forceinline__ uint32_t pack_bf16x2(float x, float y) {
    uint32_t r;
    asm("cvt.rn.bf16x2.f32 %0, %1, %2;" : "=r"(r) : "f"(y), "f"(x));
    return r;
}
__device__ __forceinline__ uint32_t pack_f16x2(float x, float y) {
    uint32_t r;
    asm("cvt.rn.f16x2.f32 %0, %1, %2;" : "=r"(r) : "f"(y), "f"(x));
    return r;
}

// fast 2^t for t <= 0, FFMA/ALU only (no MUFU). rel err ~2.5e-6.
__device__ __forceinline__ float exp2_fast(float t) {
    float r = fmaxf(t, -30.f);
    float z = r + 12582912.f;
    int   i = __float_as_int(z);
    float f = r - (z - 12582912.f);
    float p = 1.33335581e-3f;
    p = fmaf(p, f, 9.61812911e-3f);
    p = fmaf(p, f, 5.55041087e-2f);
    p = fmaf(p, f, 2.40226507e-1f);
    p = fmaf(p, f, 6.93147181e-1f);
    p = fmaf(p, f, 1.0f);
    return p * __int_as_float((i + 127) << 23);
}

__device__ __forceinline__ void split4(float4 v, uint32_t& h01, uint32_t& h23,
                                       uint32_t& l01, uint32_t& l23) {
    h01 = pack_bf16x2(v.x, v.y);
    h23 = pack_bf16x2(v.z, v.w);
    float r0 = v.x - __int_as_float(h01 << 16);
    float r1 = v.y - __int_as_float(h01 & 0xFFFF0000u);
    float r2 = v.z - __int_as_float(h23 << 16);
    float r3 = v.w - __int_as_float(h23 & 0xFFFF0000u);
    l01 = pack_bf16x2(r0, r1);
    l23 = pack_bf16x2(r2, r3);
}

__device__ __forceinline__ void split2_bf(float a, float b, uint32_t& h, uint32_t& l) {
    h = pack_bf16x2(a, b);
    float ra = a - __int_as_float(h << 16);
    float rb = b - __int_as_float(h & 0xFFFF0000u);
    l = pack_bf16x2(ra, rb);
}

__device__ __forceinline__ void split2_f16(float a, float b, uint32_t& h, uint32_t& l) {
    h = pack_f16x2(a, b);
    float ha = __half2float(__ushort_as_half((unsigned short)(h & 0xFFFFu)));
    float hb = __half2float(__ushort_as_half((unsigned short)(h >> 16)));
    l = pack_f16x2(a - ha, b - hb);
}

// ============================================================================
// prep_all: fused x-split (blocks 0..2047), Wp->fp16 (2048..2303),
//           Wqkv transpose/split (2304..5375).
// ============================================================================
__global__ __launch_bounds__(256)
void prep_all(const float* __restrict__ x, const float* __restrict__ Wp,
              const float* __restrict__ W)
{
    const int tid = threadIdx.x;
    if (blockIdx.x < 2048) {
        #pragma unroll
        for (int i = 0; i < 4; ++i) {
            size_t idx = (size_t)blockIdx.x * 256 + tid + (size_t)i * 524288;
            float4 v = *(const float4*)(x + idx * 4);
            uint32_t h01, h23, l01, l23;
            split4(v, h01, h23, l01, l23);
            *(uint2*)&g_xhi[idx * 4] = make_uint2(h01, h23);
            *(uint2*)&g_xlo[idx * 4] = make_uint2(l01, l23);
            *(uint2*)&g_x16[idx * 4] = make_uint2(pack_f16x2(v.x, v.y),
                                                  pack_f16x2(v.z, v.w));
        }
    } else if (blockIdx.x < 2304) {
        size_t base = (size_t)(blockIdx.x - 2048) * 256 + tid;
        #pragma unroll
        for (int i = 0; i < 4; ++i) {
            size_t idx = base + (size_t)i * 65536;
            float4 v = *(const float4*)(Wp + idx * 4);
            *(uint2*)&g_wp16[idx * 4] = make_uint2(pack_f16x2(v.x, v.y),
                                                   pack_f16x2(v.z, v.w));
        }
    } else {
        __shared__ float t[32][33];
        const int blk = blockIdx.x - 2304;       // 0..3071
        const int e   = blk >> 6;                // 0..47
        const int k0  = ((blk >> 1) & 31) * 32;
        const int h0  = (blk & 1) * 32;
        const int tx  = tid & 31;
        const int ty  = tid >> 5;                // 0..7
        #pragma unroll
        for (int i = 0; i < 32; i += 8)
            t[ty + i][tx] = W[(size_t)e * 65536 + (size_t)(k0 + ty + i) * 64 + h0 + tx];
        __syncthreads();
        #pragma unroll
        for (int i = 0; i < 32; i += 8) {
            float val = t[tx][ty + i];
            if (e < 32) {
                __nv_bfloat16 hi = __float2bfloat16(val);
                __nv_bfloat16 lo = __float2bfloat16(val - __bfloat162float(hi));
                size_t off = (size_t)e * 65536 + (size_t)(h0 + ty + i) * 1024 + k0 + tx;
                g_wthi[off] = hi;
                g_wtlo[off] = lo;
            } else {
                size_t o16 = (size_t)(e - 32) * 65536 +
                             (size_t)(h0 + ty + i) * 1024 + k0 + tx;
                g_wt16[o16] = __float2half(val);
            }
        }
    }
}

// ============================================================================
// gemm_qkv: fused QKV projection. blockIdx.y 0..15 -> Q/K (3-term bf16);
//   16..23 -> V (1-term fp16) with in-kernel transpose epilogue writing
//   g_vt16 [hb][d][l] directly (prep_vt eliminated).
// ============================================================================
#define LDA 80u
#define G2_AHI 0u
#define G2_ALO 10240u
#define G2_BHI 20480u
#define G2_BLO 30720u
#define G2_STG 40960u
#define GEMM_SMEM (3 * 40960)
#define GF_A 0u
#define GF_B 10240u
#define GF_STG 20480u

__global__ __launch_bounds__(256)
void gemm_qkv(const float* __restrict__ bias)
{
    extern __shared__ __align__(128) char smem[];
    const uint32_t sb  = smem_u32(smem);
    const int tid  = threadIdx.x;
    const int lane = tid & 31;
    const int wid  = tid >> 5;
    const int wm   = wid & 1;
    const int wn   = wid >> 1;
    const int m0   = blockIdx.x * 128;

    const int cp_r = tid >> 2;
    const int cp_c = tid & 3;
    const int ce   = cp_c * 8;
    const uint32_t a_row = (uint32_t)(wm * 64 + (lane & 7) + ((lane >> 3) & 1) * 8);
    const uint32_t a_kb  = (uint32_t)(lane >> 4) * 16u;
    const uint32_t b_row = (uint32_t)(wn * 32 + (lane & 7) + (lane >> 4) * 8);
    const uint32_t b_kb  = (uint32_t)((lane >> 3) & 1) * 16u;
    const int g  = lane >> 2;
    const int tg = lane & 3;

    float acc[4][4][4];
    #pragma unroll
    for (int mt = 0; mt < 4; ++mt)
        #pragma unroll
        for (int nt = 0; nt < 4; ++nt)
            #pragma unroll
            for (int i = 0; i < 4; ++i) acc[mt][nt][i] = 0.f;

    if (blockIdx.y < 16) {
        // ==================== Q/K path: 3-term split bf16 ====================
        const int grp0 = blockIdx.y * 2;
        const __nv_bfloat16* Ahi = g_xhi;
        const __nv_bfloat16* Alo = g_xlo;
        const __nv_bfloat16* Bh0 = g_wthi + (size_t)grp0 * 65536;
        const __nv_bfloat16* Bl0 = g_wtlo + (size_t)grp0 * 65536;

        auto issue = [&](int ks, uint32_t stg) {
            const int k0 = ks * 32;
            uint32_t d0 = stg + (uint32_t)cp_r * LDA + (uint32_t)cp_c * 16u;
            uint32_t d1 = d0 + 64u * LDA;
            size_t a0 = (size_t)(m0 + cp_r) * 1024 + k0 + ce;
            size_t a1 = a0 + 64 * 1024;
            size_t b0 = (size_t)cp_r * 1024 + k0 + ce;
            cp_async16(d0 + G2_AHI, Ahi + a0);
            cp_async16(d1 + G2_AHI, Ahi + a1);
            cp_async16(d0 + G2_ALO, Alo + a0);
            cp_async16(d1 + G2_ALO, Alo + a1);
            cp_async16(d0 + G2_BHI, Bh0 + b0);
            cp_async16(d1 + G2_BHI, Bh0 + 65536 + b0);
            cp_async16(d0 + G2_BLO, Bl0 + b0);
            cp_async16(d1 + G2_BLO, Bl0 + 65536 + b0);
            cp_commit();
        };

        issue(0, sb);
        issue(1, sb + G2_STG);

        for (int ks = 0; ks < 32; ++ks) {
            if (ks < 31) cp_wait<1>(); else cp_wait<0>();
            __syncthreads();
            if (ks + 2 < 32) issue(ks + 2, sb + (uint32_t)((ks + 2) % 3) * G2_STG);

            const uint32_t stg = sb + (uint32_t)(ks % 3) * G2_STG;
            const uint32_t aHi = stg + G2_AHI + a_row * LDA + a_kb;
            const uint32_t aLo = stg + G2_ALO + a_row * LDA + a_kb;
            const uint32_t bHi = stg + G2_BHI + b_row * LDA + b_kb;
            const uint32_t bLo = stg + G2_BLO + b_row * LDA + b_kb;

            #pragma unroll
            for (int kk = 0; kk < 2; ++kk) {
                const uint32_t koff = (uint32_t)kk * 32u;

                uint32_t ahi[4][4], alo[4][4];
                #pragma unroll
                for (int mt = 0; mt < 4; ++mt) {
                    ldmatrix_x4(ahi[mt][0], ahi[mt][1], ahi[mt][2], ahi[mt][3],
                                aHi + (uint32_t)mt * 16u * LDA + koff);
                    ldmatrix_x4(alo[mt][0], alo[mt][1], alo[mt][2], alo[mt][3],
                                aLo + (uint32_t)mt * 16u * LDA + koff);
                }
                uint32_t bhi[4][2], blo[4][2];
                #pragma unroll
                for (int ntp = 0; ntp < 2; ++ntp) {
                    uint32_t r0, r1, r2, r3;
                    ldmatrix_x4(r0, r1, r2, r3, bHi + (uint32_t)ntp * 16u * LDA + koff);
                    bhi[ntp * 2][0] = r0; bhi[ntp * 2][1] = r1;
                    bhi[ntp * 2 + 1][0] = r2; bhi[ntp * 2 + 1][1] = r3;
                    ldmatrix_x4(r0, r1, r2, r3, bLo + (uint32_t)ntp * 16u * LDA + koff);
                    blo[ntp * 2][0] = r0; blo[ntp * 2][1] = r1;
                    blo[ntp * 2 + 1][0] = r2; blo[ntp * 2 + 1][1] = r3;
                }

                #pragma unroll
                for (int mt = 0; mt < 4; ++mt)
                    #pragma unroll
                    for (int nt = 0; nt < 4; ++nt) {
                        mma_bf16(acc[mt][nt], ahi[mt][0], ahi[mt][1], ahi[mt][2], ahi[mt][3],
                                 bhi[nt][0], bhi[nt][1]);
                        mma_bf16(acc[mt][nt], ahi[mt][0], ahi[mt][1], ahi[mt][2], ahi[mt][3],
                                 blo[nt][0], blo[nt][1]);
                        mma_bf16(acc[mt][nt], alo[mt][0], alo[mt][1], alo[mt][2], alo[mt][3],
                                 bhi[nt][0], bhi[nt][1]);
                    }
            }
        }

        const float QSCALE = 11.5415603272f;
        #pragma unroll
        for (int mt = 0; mt < 4; ++mt)
            #pragma unroll
            for (int nt = 0; nt < 4; ++nt) {
                int n    = wn * 32 + nt * 8 + tg * 2;
                int gsel = n >> 6;
                int c64  = n & 63;
                int e    = grp0 + gsel;
                const float* bp = bias + (size_t)e * 64;
                float b0 = bp[c64], b1 = bp[c64 + 1];
                int r0 = m0 + wm * 64 + mt * 16 + g;
                float v00 = acc[mt][nt][0] + b0, v01 = acc[mt][nt][1] + b1;
                float v10 = acc[mt][nt][2] + b0, v11 = acc[mt][nt][3] + b1;
                bool isQ = (e < 16);
                float s = isQ ? QSCALE : 1.f;
                v00 *= s; v01 *= s; v10 *= s; v11 *= s;
                __nv_bfloat16* dh = isQ ? g_qhi : g_khi;
                __nv_bfloat16* dl = isQ ? g_qlo : g_klo;
                int eo = isQ ? e : (e - 16);
                size_t base0 = ((size_t)eo * 8192 + r0) * 64 + c64;
                size_t base1 = base0 + 8 * 64;
                uint32_t h, l;
                split2_bf(v00, v01, h, l);
                *(uint32_t*)&dh[base0] = h;
                *(uint32_t*)&dl[base0] = l;
                split2_bf(v10, v11, h, l);
                *(uint32_t*)&dh[base1] = h;
                *(uint32_t*)&dl[base1] = l;
            }
    } else {
        // ============ V path: 1-term fp16, transposed epilogue ============
        const int grp0 = (blockIdx.y - 16) * 2;
        const float* biasv = bias + 32 * 64;
        const __half* A  = g_x16;
        const __half* B0 = g_wt16 + (size_t)grp0 * 65536;

        auto issue = [&](int ks, uint32_t stg) {
            const int k0 = ks * 32;
            uint32_t d0 = stg + (uint32_t)cp_r * LDA + (uint32_t)cp_c * 16u;
            uint32_t d1 = d0 + 64u * LDA;
            size_t a0 = (size_t)(m0 + cp_r) * 1024 + k0 + ce;
            size_t a1 = a0 + 64 * 1024;
            size_t b0 = (size_t)cp_r * 1024 + k0 + ce;
            cp_async16(d0 + GF_A, A + a0);
            cp_async16(d1 + GF_A, A + a1);
            cp_async16(d0 + GF_B, B0 + b0);
            cp_async16(d1 + GF_B, B0 + 65536 + b0);
            cp_commit();
        };

        issue(0, sb);
        issue(1, sb + GF_STG);

        for (int ks = 0; ks < 32; ++ks) {
            if (ks < 31) cp_wait<1>(); else cp_wait<0>();
            __syncthreads();
            if (ks + 2 < 32) issue(ks + 2, sb + (uint32_t)((ks + 2) % 3) * GF_STG);

            const uint32_t stg = sb + (uint32_t)(ks % 3) * GF_STG;
            const uint32_t aB = stg + GF_A + a_row * LDA + a_kb;
            const uint32_t bB = stg + GF_B + b_row * LDA + b_kb;

            #pragma unroll
            for (int kk = 0; kk < 2; ++kk) {
                const uint32_t koff = (uint32_t)kk * 32u;

                uint32_t af[4][4];
                #pragma unroll
                for (int mt = 0; mt < 4; ++mt)
                    ldmatrix_x4(af[mt][0], af[mt][1], af[mt][2], af[mt][3],
                                aB + (uint32_t)mt * 16u * LDA + koff);
                uint32_t bf[4][2];
                #pragma unroll
                for (int ntp = 0; ntp < 2; ++ntp) {
                    uint32_t r0, r1, r2, r3;
                    ldmatrix_x4(r0, r1, r2, r3, bB + (uint32_t)ntp * 16u * LDA + koff);
                    bf[ntp * 2][0] = r0; bf[ntp * 2][1] = r1;
                    bf[ntp * 2 + 1][0] = r2; bf[ntp * 2 + 1][1] = r3;
                }

                #pragma unroll
                for (int mt = 0; mt < 4; ++mt)
                    #pragma unroll
                    for (int nt = 0; nt < 4; ++nt)
                        mma_f16(acc[mt][nt], af[mt][0], af[mt][1], af[mt][2], af[mt][3],
                                bf[nt][0], bf[nt][1]);
            }
        }

        // ---- transpose epilogue: stage fp16 [n][row] in smem, write [d][l] ----
        __syncthreads();   // all stage reads done before smem reuse
        __half* tile = (__half*)smem;   // [128 n][136 row-stride]
        #pragma unroll
        for (int mt = 0; mt < 4; ++mt)
            #pragma unroll
            for (int nt = 0; nt < 4; ++nt) {
                int n    = wn * 32 + nt * 8 + tg * 2;
                int c64  = n & 63;
                const float* bp = biasv + (size_t)(grp0 + (n >> 6)) * 64;
                float b0 = bp[c64], b1 = bp[c64 + 1];
                int r0 = wm * 64 + mt * 16 + g;          // local row
                tile[(n    ) * 136 + r0]     = __float2half(acc[mt][nt][0] + b0);
                tile[(n + 1) * 136 + r0]     = __float2half(acc[mt][nt][1] + b1);
                tile[(n    ) * 136 + r0 + 8] = __float2half(acc[mt][nt][2] + b0);
                tile[(n + 1) * 136 + r0 + 8] = __float2half(acc[mt][nt][3] + b1);
            }
        __syncthreads();

        const int b  = m0 >> 11;        // batch of this row block
        const int l0 = m0 & 2047;       // seq offset within batch
        #pragma unroll
        for (int i = 0; i < 8; ++i) {
            int idx = tid + i * 256;     // < 2048: 128 d x 16 granules of 8 halfs
            int d   = idx >> 4;
            int c   = idx & 15;
            uint4 v = *(uint4*)&tile[d * 136 + c * 8];
            int e   = grp0 + (d >> 6);
            int dl  = d & 63;
            int hb  = e * 4 + b;
            *(uint4*)&g_vt16[((size_t)hb * 64 + dl) * 2048 + l0 + c * 8] = v;
        }
    }
}

// ============================================================================
// gemm_proj: 128x128 tile, 2-term split-fp16, 3-stage, 2 CTAs/SM (proven).
// ============================================================================
#define GP_AHI 0u
#define GP_ALO 10240u
#define GP_B   20480u
#define GP_STG 30720u
#define GP_SMEM (3 * 30720)

__global__ __launch_bounds__(256)
void gemm_proj(const float* __restrict__ bias, float* __restrict__ C)
{
    extern __shared__ __align__(128) char smem[];
    const uint32_t sb  = smem_u32(smem);
    const int tid  = threadIdx.x;
    const int lane = tid & 31;
    const int wid  = tid >> 5;
    const int wm   = wid & 1;
    const int wn   = wid >> 1;
    const int m0   = blockIdx.x * 128;
    const int n0   = blockIdx.y * 128;

    const __half* Ahi = g_avhi;
    const __half* Alo = g_avlo;
    const __half* B0  = g_wp16 + (size_t)n0 * 1024;

    float acc[4][4][4];
    #pragma unroll
    for (int mt = 0; mt < 4; ++mt)
        #pragma unroll
        for (int nt = 0; nt < 4; ++nt)
            #pragma unroll
            for (int i = 0; i < 4; ++i) acc[mt][nt][i] = 0.f;

    const int cp_r = tid >> 2;
    const int cp_c = tid & 3;
    const int ce   = cp_c * 8;
    auto issue = [&](int ks, uint32_t stg) {
        const int k0 = ks * 32;
        uint32_t d0 = stg + (uint32_t)cp_r * LDA + (uint32_t)cp_c * 16u;
        uint32_t d1 = d0 + 64u * LDA;
        size_t a0 = (size_t)(m0 + cp_r) * 1024 + k0 + ce;
        size_t a1 = a0 + 64 * 1024;
        size_t b0 = (size_t)cp_r * 1024 + k0 + ce;
        cp_async16(d0 + GP_AHI, Ahi + a0);
        cp_async16(d1 + GP_AHI, Ahi + a1);
        cp_async16(d0 + GP_ALO, Alo + a0);
        cp_async16(d1 + GP_ALO, Alo + a1);
        cp_async16(d0 + GP_B, B0 + b0);
        cp_async16(d1 + GP_B, B0 + 65536 + b0);
        cp_commit();
    };

    const uint32_t a_row = (uint32_t)(wm * 64 + (lane & 7) + ((lane >> 3) & 1) * 8);
    const uint32_t a_kb  = (uint32_t)(lane >> 4) * 16u;
    const uint32_t b_row = (uint32_t)(wn * 32 + (lane & 7) + (lane >> 4) * 8);
    const uint32_t b_kb  = (uint32_t)((lane >> 3) & 1) * 16u;

    issue(0, sb);
    issue(1, sb + GP_STG);

    for (int ks = 0; ks < 32; ++ks) {
        if (ks < 31) cp_wait<1>(); else cp_wait<0>();
        __syncthreads();
        if (ks + 2 < 32) issue(ks + 2, sb + (uint32_t)((ks + 2) % 3) * GP_STG);

        const uint32_t stg = sb + (uint32_t)(ks % 3) * GP_STG;
        const uint32_t aHi = stg + GP_AHI + a_row * LDA + a_kb;
        const uint32_t aLo = stg + GP_ALO + a_row * LDA + a_kb;
        const uint32_t bB  = stg + GP_B   + b_row * LDA + b_kb;

        #pragma unroll
        for (int kk = 0; kk < 2; ++kk) {
            const uint32_t koff = (uint32_t)kk * 32u;

            uint32_t ahi[4][4], alo[4][4];
            #pragma unroll
            for (int mt = 0; mt < 4; ++mt) {
                ldmatrix_x4(ahi[mt][0], ahi[mt][1], ahi[mt][2], ahi[mt][3],
                            aHi + (uint32_t)mt * 16u * LDA + koff);
                ldmatrix_x4(alo[mt][0], alo[mt][1], alo[mt][2], alo[mt][3],
                            aLo + (uint32_t)mt * 16u * LDA + koff);
            }
            uint32_t bf[4][2];
            #pragma unroll
            for (int ntp = 0; ntp < 2; ++ntp) {
                uint32_t r0, r1, r2, r3;
                ldmatrix_x4(r0, r1, r2, r3, bB + (uint32_t)ntp * 16u * LDA + koff);
                bf[ntp * 2][0] = r0; bf[ntp * 2][1] = r1;
                bf[ntp * 2 + 1][0] = r2; bf[ntp * 2 + 1][1] = r3;
            }

            #pragma unroll
            for (int mt = 0; mt < 4; ++mt)
                #pragma unroll
                for (int nt = 0; nt < 4; ++nt) {
                    mma_f16(acc[mt][nt], ahi[mt][0], ahi[mt][1], ahi[mt][2], ahi[mt][3],
                            bf[nt][0], bf[nt][1]);
                    mma_f16(acc[mt][nt], alo[mt][0], alo[mt][1], alo[mt][2], alo[mt][3],
                            bf[nt][0], bf[nt][1]);
                }
        }
    }

    const int g  = lane >> 2;
    const int tg = lane & 3;
    #pragma unroll
    for (int mt = 0; mt < 4; ++mt)
        #pragma unroll
        for (int nt = 0; nt < 4; ++nt) {
            int n = n0 + wn * 32 + nt * 8 + tg * 2;
            float b0 = bias[n], b1 = bias[n + 1];
            int r0 = m0 + wm * 64 + mt * 16 + g;
            float2 o0 = make_float2(acc[mt][nt][0] + b0, acc[mt][nt][1] + b1);
            float2 o1 = make_float2(acc[mt][nt][2] + b0, acc[mt][nt][3] + b1);
            *(float2*)(C + (size_t)r0 * 1024 + n)       = o0;
            *(float2*)(C + (size_t)(r0 + 8) * 1024 + n) = o1;
        }
}

// ============================================================================
// attn_mma: flash attention (proven config). S 3-term bf16, PV 1-term fp16.
//   3-stage cp.async, 2 CTAs/SM. Emits av split fp16.
// ============================================================================
#define LDS_ROW 144u
#define ST_KHI 0u
#define ST_KLO 9216u
#define ST_V16 18432u
#define STAGE_BYTES 27648u
#define ATTN_SMEM (3 * 27648)

__global__ __launch_bounds__(256, 2)
void attn_mma()
{
    extern __shared__ __align__(128) char smem[];
    const uint32_t sb = smem_u32(smem);
    const int tid  = threadIdx.x;
    const int lane = tid & 31;
    const int wid  = tid >> 5;
    const int g    = lane >> 2;
    const int tg   = lane & 3;
    const int hb   = blockIdx.y;
    const int hd   = hb >> 2;
    const int b    = hb & 3;
    const int q0   = blockIdx.x * 128;

    const __nv_bfloat16* Qhi = g_qhi + ((size_t)hd * 8192 + b * 2048 + q0) * 64;
    const __nv_bfloat16* Qlo = g_qlo + ((size_t)hd * 8192 + b * 2048 + q0) * 64;
    const __nv_bfloat16* Khi = g_khi + (size_t)hb * 2048 * 64;
    const __nv_bfloat16* Klo = g_klo + (size_t)hb * 2048 * 64;
    const __half*        V16 = g_vt16 + (size_t)hb * 64 * 2048;

    // ---- stage Q (pre-scaled, pre-split) via cp.async, extract fragments ----
    #pragma unroll
    for (int i = 0; i < 4; ++i) {
        int idx = tid + i * 256;
        int row = idx >> 3;
        int c   = idx & 7;
        cp_async16(sb + (uint32_t)row * LDS_ROW + (uint32_t)c * 16u,
                   Qhi + (size_t)row * 64 + c * 8);
        cp_async16(sb + 18432u + (uint32_t)row * LDS_ROW + (uint32_t)c * 16u,
                   Qlo + (size_t)row * 64 + c * 8);
    }
    cp_commit();
    cp_wait<0>();
    __syncthreads();

    uint32_t qhi[4][4], qlo[4][4];
    {
        const uint32_t qrow = (uint32_t)(wid * 16 + (lane & 7) + ((lane >> 3) & 1) * 8);
        const uint32_t kb   = (uint32_t)(lane >> 4) * 16u;
        const uint32_t aH = sb + qrow * LDS_ROW + kb;
        const uint32_t aL = sb + 18432u + qrow * LDS_ROW + kb;
        #pragma unroll
        for (int t = 0; t < 4; ++t) {
            ldmatrix_x4(qhi[t][0], qhi[t][1], qhi[t][2], qhi[t][3], aH + t * 32u);
            ldmatrix_x4(qlo[t][0], qlo[t][1], qlo[t][2], qlo[t][3], aL + t * 32u);
        }
    }
    __syncthreads();   // Q consumed — smem free for stages

    float mA = -1e30f, mB = -1e30f, lA = 0.f, lB = 0.f;
    float oacc[8][4];
    #pragma unroll
    for (int j = 0; j < 8; ++j)
        #pragma unroll
        for (int i = 0; i < 4; ++i) oacc[j][i] = 0.f;

    const uint32_t brow = (uint32_t)((lane & 7) + (lane >> 4) * 8);
    const uint32_t bkb  = (uint32_t)((lane >> 3) & 1) * 16u;

    const int cp_row = tid >> 3;
    const int cp_c   = tid & 7;
    auto issue = [&](int j0, uint32_t stg) {
        #pragma unroll
        for (int i = 0; i < 2; ++i) {
            int row = cp_row + i * 32;
            uint32_t doff = stg + (uint32_t)row * LDS_ROW + (uint32_t)cp_c * 16u;
            cp_async16(doff + ST_KHI, Khi + ((size_t)(j0 + row)) * 64 + cp_c * 8);
            cp_async16(doff + ST_KLO, Klo + ((size_t)(j0 + row)) * 64 + cp_c * 8);
            cp_async16(doff + ST_V16, V16 + ((size_t)row) * 2048 + j0 + cp_c * 8);
        }
        cp_commit();
    };

    issue(0, sb);
    issue(64, sb + STAGE_BYTES);

    for (int j = 0; j < 32; ++j) {
        if (j < 31) cp_wait<1>(); else cp_wait<0>();
        __syncthreads();
        if (j + 2 < 32) issue((j + 2) * 64, sb + (uint32_t)((j + 2) % 3) * STAGE_BYTES);

        const uint32_t stg = sb + (uint32_t)(j % 3) * STAGE_BYTES;

        // ---- S = Qscaled @ K^T (split 3-term bf16), log2 units ----
        float sacc[8][4];
        #pragma unroll
        for (int jj = 0; jj < 8; ++jj)
            #pragma unroll
            for (int i = 0; i < 4; ++i) sacc[jj][i] = 0.f;

        #pragma unroll
        for (int td = 0; td < 4; ++td) {
            uint32_t bhi[8][2], blo[8][2];
            #pragma unroll
            for (int ntp = 0; ntp < 4; ++ntp) {
                uint32_t base = (uint32_t)(ntp * 16) * LDS_ROW + brow * LDS_ROW + bkb
                                + (uint32_t)td * 32u;
                uint32_t r0, r1, r2, r3;
                ldmatrix_x4(r0, r1, r2, r3, stg + ST_KHI + base);
                bhi[ntp * 2][0] = r0; bhi[ntp * 2][1] = r1;
                bhi[ntp * 2 + 1][0] = r2; bhi[ntp * 2 + 1][1] = r3;
                ldmatrix_x4(r0, r1, r2, r3, stg + ST_KLO + base);
                blo[ntp * 2][0] = r0; blo[ntp * 2][1] = r1;
                blo[ntp * 2 + 1][0] = r2; blo[ntp * 2 + 1][1] = r3;
            }
            #pragma unroll
            for (int nt = 0; nt < 8; ++nt) {
                mma_bf16(sacc[nt], qhi[td][0], qhi[td][1], qhi[td][2], qhi[td][3],
                         bhi[nt][0], bhi[nt][1]);
                mma_bf16(sacc[nt], qhi[td][0], qhi[td][1], qhi[td][2], qhi[td][3],
                         blo[nt][0], blo[nt][1]);
                mma_bf16(sacc[nt], qlo[td][0], qlo[td][1], qlo[td][2], qlo[td][3],
                         bhi[nt][0], bhi[nt][1]);
            }
        }

        // ---- online softmax (log2 domain) ----
        float rmA = -1e30f, rmB = -1e30f;
        #pragma unroll
        for (int jj = 0; jj < 8; ++jj) {
            rmA = fmaxf(rmA, fmaxf(sacc[jj][0], sacc[jj][1]));
            rmB = fmaxf(rmB, fmaxf(sacc[jj][2], sacc[jj][3]));
        }
        rmA = fmaxf(rmA, __shfl_xor_sync(0xffffffffu, rmA, 1));
        rmA = fmaxf(rmA, __shfl_xor_sync(0xffffffffu, rmA, 2));
        rmB = fmaxf(rmB, __shfl_xor_sync(0xffffffffu, rmB, 1));
        rmB = fmaxf(rmB, __shfl_xor_sync(0xffffffffu, rmB, 2));

        float mnA = fmaxf(mA, rmA), mnB = fmaxf(mB, rmB);
        float corrA = exp2_fast(mA - mnA), corrB = exp2_fast(mB - mnB);

        float sumA = 0.f, sumB = 0.f;
        uint32_t pf[4][4];
        #pragma unroll
        for (int jj = 0; jj < 8; ++jj) {
            float p0 = exp2_fast(sacc[jj][0] - mnA);
            float p1 = exp2_fast(sacc[jj][1] - mnA);
            float p2 = exp2_fast(sacc[jj][2] - mnB);
            float p3 = exp2_fast(sacc[jj][3] - mnB);
            sumA += p0 + p1; sumB += p2 + p3;
            int t = jj >> 1;
            int o = (jj & 1) * 2;
            pf[t][o]     = pack_f16x2(p0, p1);
            pf[t][o + 1] = pack_f16x2(p2, p3);
        }
        sumA += __shfl_xor_sync(0xffffffffu, sumA, 1);
        sumA += __shfl_xor_sync(0xffffffffu, sumA, 2);
        sumB += __shfl_xor_sync(0xffffffffu, sumB, 1);
        sumB += __shfl_xor_sync(0xffffffffu, sumB, 2);

        lA = lA * corrA + sumA;
        lB = lB * corrB + sumB;
        mA = mnA; mB = mnB;

        #pragma unroll
        for (int jj = 0; jj < 8; ++jj) {
            oacc[jj][0] *= corrA; oacc[jj][1] *= corrA;
            oacc[jj][2] *= corrB; oacc[jj][3] *= corrB;
        }

        // ---- O += P @ V (1-term fp16) ----
        #pragma unroll
        for (int t = 0; t < 4; ++t) {
            uint32_t vf[8][2];
            #pragma unroll
            for (int ntp = 0; ntp < 4; ++ntp) {
                uint32_t base = (uint32_t)(ntp * 16) * LDS_ROW + brow * LDS_ROW + bkb
                                + (uint32_t)t * 32u;
                uint32_t r0, r1, r2, r3;
                ldmatrix_x4(r0, r1, r2, r3, stg + ST_V16 + base);
                vf[ntp * 2][0] = r0; vf[ntp * 2][1] = r1;
                vf[ntp * 2 + 1][0] = r2; vf[ntp * 2 + 1][1] = r3;
            }
            #pragma unroll
            for (int nd = 0; nd < 8; ++nd)
                mma_f16(oacc[nd], pf[t][0], pf[t][1], pf[t][2], pf[t][3],
                        vf[nd][0], vf[nd][1]);
        }
    }

    // ---- epilogue: normalize, split to fp16 hi/lo, write g_avhi/g_avlo ----
    const float invA = 1.f / lA, invB = 1.f / lB;
    const int rowA = q0 + wid * 16 + g;
    const int rowB = rowA + 8;
    #pragma unroll
    for (int jd = 0; jd < 8; ++jd) {
        int col = hd * 64 + jd * 8 + tg * 2;
        {
            uint32_t h, l;
            split2_f16(oacc[jd][0] * invA, oacc[jd][1] * invA, h, l);
            size_t base = (size_t)(b * 2048 + rowA) * 1024 + col;
            *(uint32_t*)&g_avhi[base] = h;
            *(uint32_t*)&g_avlo[base] = l;
        }
        {
            uint32_t h, l;
            split2_f16(oacc[jd][2] * invB, oacc[jd][3] * invB, h, l);
            size_t base = (size_t)(b * 2048 + rowB) * 1024 + col;
            *(uint32_t*)&g_avhi[base] = h;
            *(uint32_t*)&g_avlo[base] = l;
        }
    }
}

// ============================================================================
extern "C" void kernel_launch(void* const* d_in, const int* in_sizes, int n_in,
                              void* d_out, int out_size)
{
    const float* x    = (const float*)d_in[0];   // (4, 2048, 1024)
    const float* Wqkv = (const float*)d_in[1];   // (48, 1024, 64)
    const float* bqkv = (const float*)d_in[2];   // (48, 64)
    const float* Wp   = (const float*)d_in[3];   // (1024, 1024)
    const float* bp   = (const float*)d_in[4];   // (1024,)
    float* out = (float*)d_out;                  // (4, 2048, 1024)

    cudaFuncSetAttribute(gemm_qkv, cudaFuncAttributeMaxDynamicSharedMemorySize,
                         GEMM_SMEM);
    cudaFuncSetAttribute(gemm_proj, cudaFuncAttributeMaxDynamicSharedMemorySize,
                         GP_SMEM);
    cudaFuncSetAttribute(attn_mma, cudaFuncAttributeMaxDynamicSharedMemorySize,
                         ATTN_SMEM);

    // 1) fused preps: x split + Wp fp16 + Wqkv transpose/split
    prep_all<<<5376, 256>>>(x, Wp, Wqkv);

    // 2) fused QKV: Q/K 3-term bf16 (y 0..15) + V 1-term fp16 (y 16..23);
    //    V epilogue writes transposed g_vt16 directly (no prep_vt).
    gemm_qkv<<<dim3(64, 24), 256, GEMM_SMEM>>>(bqkv);

    // 3) attention (3-stage, 2 CTAs/SM)
    attn_mma<<<dim3(16, 64), 256, ATTN_SMEM>>>();

    // 4) proj: 2-term split-fp16, 128x128 tiles, 3-stage
    gemm_proj<<<dim3(64, 8), 256, GP_SMEM>>>(bp, out);
}

// round 16
// speedup vs baseline: 1.1295x; 1.0028x over previous
#include <cuda_runtime.h>
#include <cuda_bf16.h>
#include <cuda_fp16.h>
#include <stdint.h>
#include <math.h>

// ============================================================================
// Scratch (device globals — no allocations allowed).
// ============================================================================
__device__ __align__(16) __nv_bfloat16 g_xhi [8192ull * 1024];
__device__ __align__(16) __nv_bfloat16 g_xlo [8192ull * 1024];
__device__ __align__(16) __half        g_x16 [8192ull * 1024];
__device__ __align__(16) __nv_bfloat16 g_wthi[32ull * 64 * 1024];   // Q/K W^T [e][h][d]
__device__ __align__(16) __nv_bfloat16 g_wtlo[32ull * 64 * 1024];
__device__ __align__(16) __half        g_wt16[16ull * 64 * 1024];   // V W^T fp16
__device__ __align__(16) __half        g_wp16[1024ull * 1024];      // Wp fp16
__device__ __align__(16) __half        g_avhi[8192ull * 1024];      // av split fp16
__device__ __align__(16) __half        g_avlo[8192ull * 1024];
__device__ __align__(16) __nv_bfloat16 g_qhi [16ull * 8192 * 64];   // [hd][row][d], scaled
__device__ __align__(16) __nv_bfloat16 g_qlo [16ull * 8192 * 64];
__device__ __align__(16) __nv_bfloat16 g_khi [16ull * 8192 * 64];
__device__ __align__(16) __nv_bfloat16 g_klo [16ull * 8192 * 64];
__device__ __align__(16) __half        g_vt16[64ull * 64 * 2048];   // [hb][d][l]

// ============================================================================
// PTX helpers (sm_80-era ISA — compiles for plain compute_103)
// ============================================================================
__device__ __forceinline__ uint32_t smem_u32(const void* p) {
    uint32_t a;
    asm("{ .reg .u64 t; cvta.to.shared.u64 t, %1; cvt.u32.u64 %0, t; }"
        : "=r"(a) : "l"(p));
    return a;
}

__device__ __forceinline__ void ldmatrix_x4(uint32_t& r0, uint32_t& r1,
                                            uint32_t& r2, uint32_t& r3,
                                            uint32_t addr) {
    asm volatile("ldmatrix.sync.aligned.m8n8.x4.shared.b16 {%0,%1,%2,%3}, [%4];"
                 : "=r"(r0), "=r"(r1), "=r"(r2), "=r"(r3) : "r"(addr));
}

__device__ __forceinline__ void mma_bf16(float* c,
                                         uint32_t a0, uint32_t a1, uint32_t a2, uint32_t a3,
                                         uint32_t b0, uint32_t b1) {
    asm volatile("mma.sync.aligned.m16n8k16.row.col.f32.bf16.bf16.f32 "
                 "{%0,%1,%2,%3}, {%4,%5,%6,%7}, {%8,%9}, {%0,%1,%2,%3};"
                 : "+f"(c[0]), "+f"(c[1]), "+f"(c[2]), "+f"(c[3])
                 : "r"(a0), "r"(a1), "r"(a2), "r"(a3), "r"(b0), "r"(b1));
}

__device__ __forceinline__ void mma_f16(float* c,
                                        uint32_t a0, uint32_t a1, uint32_t a2, uint32_t a3,
                                        uint32_t b0, uint32_t b1) {
    asm volatile("mma.sync.aligned.m16n8k16.row.col.f32.f16.f16.f32 "
                 "{%0,%1,%2,%3}, {%4,%5,%6,%7}, {%8,%9}, {%0,%1,%2,%3};"
                 : "+f"(c[0]), "+f"(c[1]), "+f"(c[2]), "+f"(c[3])
                 : "r"(a0), "r"(a1), "r"(a2), "r"(a3), "r"(b0), "r"(b1));
}

__device__ __forceinline__ void cp_async16(uint32_t dst, const void* src) {
    asm volatile("cp.async.cg.shared.global [%0], [%1], 16;"
                 :: "r"(dst), "l"(src) : "memory");
}
__device__ __forceinline__ void cp_commit() {
    asm volatile("cp.async.commit_group;" ::: "memory");
}
template <int N>
__device__ __forceinline__ void cp_wait() {
    asm volatile("cp.async.wait_group %0;" :: "n"(N) : "memory");
}

__device__ __forceinline__ uint32_t pack_bf16x2(float x, float y) {
    uint32_t r;
    asm("cvt.rn.bf16x2.f32 %0, %1, %2;" : "=r"(r) : "f"(y), "f"(x));
    return r;
}
__device__ __forceinline__ uint32_t pack_f16x2(float x, float y) {
    uint32_t r;
    asm("cvt.rn.f16x2.f32 %0, %1, %2;" : "=r"(r) : "f"(y), "f"(x));
    return r;
}

// fast 2^t for t <= 0, FFMA/ALU only (no MUFU). rel err ~2.5e-6.
__device__ __forceinline__ float exp2_fast(float t) {
    float r = fmaxf(t, -30.f);
    float z = r + 12582912.f;
    int   i = __float_as_int(z);
    float f = r - (z - 12582912.f);
    float p = 1.33335581e-3f;
    p = fmaf(p, f, 9.61812911e-3f);
    p = fmaf(p, f, 5.55041087e-2f);
    p = fmaf(p, f, 2.40226507e-1f);
    p = fmaf(p, f, 6.93147181e-1f);
    p = fmaf(p, f, 1.0f);
    return p * __int_as_float((i + 127) << 23);
}

__device__ __forceinline__ void split4(float4 v, uint32_t& h01, uint32_t& h23,
                                       uint32_t& l01, uint32_t& l23) {
    h01 = pack_bf16x2(v.x, v.y);
    h23 = pack_bf16x2(v.z, v.w);
    float r0 = v.x - __int_as_float(h01 << 16);
    float r1 = v.y - __int_as_float(h01 & 0xFFFF0000u);
    float r2 = v.z - __int_as_float(h23 << 16);
    float r3 = v.w - __int_as_float(h23 & 0xFFFF0000u);
    l01 = pack_bf16x2(r0, r1);
    l23 = pack_bf16x2(r2, r3);
}

__device__ __forceinline__ void split2_bf(float a, float b, uint32_t& h, uint32_t& l) {
    h = pack_bf16x2(a, b);
    float ra = a - __int_as_float(h << 16);
    float rb = b - __int_as_float(h & 0xFFFF0000u);
    l = pack_bf16x2(ra, rb);
}

__device__ __forceinline__ void split2_f16(float a, float b, uint32_t& h, uint32_t& l) {
    h = pack_f16x2(a, b);
    float ha = __half2float(__ushort_as_half((unsigned short)(h & 0xFFFFu)));
    float hb = __half2float(__ushort_as_half((unsigned short)(h >> 16)));
    l = pack_f16x2(a - ha, b - hb);
}

// ============================================================================
// prep_all: fused x-split (blocks 0..2047), Wp->fp16 (2048..2303),
//           Wqkv transpose/split (2304..5375).
// ============================================================================
__global__ __launch_bounds__(256)
void prep_all(const float* __restrict__ x, const float* __restrict__ Wp,
              const float* __restrict__ W)
{
    const int tid = threadIdx.x;
    if (blockIdx.x < 2048) {
        #pragma unroll
        for (int i = 0; i < 4; ++i) {
            size_t idx = (size_t)blockIdx.x * 256 + tid + (size_t)i * 524288;
            float4 v = *(const float4*)(x + idx * 4);
            uint32_t h01, h23, l01, l23;
            split4(v, h01, h23, l01, l23);
            *(uint2*)&g_xhi[idx * 4] = make_uint2(h01, h23);
            *(uint2*)&g_xlo[idx * 4] = make_uint2(l01, l23);
            *(uint2*)&g_x16[idx * 4] = make_uint2(pack_f16x2(v.x, v.y),
                                                  pack_f16x2(v.z, v.w));
        }
    } else if (blockIdx.x < 2304) {
        size_t base = (size_t)(blockIdx.x - 2048) * 256 + tid;
        #pragma unroll
        for (int i = 0; i < 4; ++i) {
            size_t idx = base + (size_t)i * 65536;
            float4 v = *(const float4*)(Wp + idx * 4);
            *(uint2*)&g_wp16[idx * 4] = make_uint2(pack_f16x2(v.x, v.y),
                                                   pack_f16x2(v.z, v.w));
        }
    } else {
        __shared__ float t[32][33];
        const int blk = blockIdx.x - 2304;       // 0..3071
        const int e   = blk >> 6;                // 0..47
        const int k0  = ((blk >> 1) & 31) * 32;
        const int h0  = (blk & 1) * 32;
        const int tx  = tid & 31;
        const int ty  = tid >> 5;                // 0..7
        #pragma unroll
        for (int i = 0; i < 32; i += 8)
            t[ty + i][tx] = W[(size_t)e * 65536 + (size_t)(k0 + ty + i) * 64 + h0 + tx];
        __syncthreads();
        #pragma unroll
        for (int i = 0; i < 32; i += 8) {
            float val = t[tx][ty + i];
            if (e < 32) {
                __nv_bfloat16 hi = __float2bfloat16(val);
                __nv_bfloat16 lo = __float2bfloat16(val - __bfloat162float(hi));
                size_t off = (size_t)e * 65536 + (size_t)(h0 + ty + i) * 1024 + k0 + tx;
                g_wthi[off] = hi;
                g_wtlo[off] = lo;
            } else {
                size_t o16 = (size_t)(e - 32) * 65536 +
                             (size_t)(h0 + ty + i) * 1024 + k0 + tx;
                g_wt16[o16] = __float2half(val);
            }
        }
    }
}

// ============================================================================
// gemm_qkv: fused QKV projection. blockIdx.y 0..15 -> Q/K (3-term bf16);
//   16..23 -> V (1-term fp16) with in-kernel transpose epilogue writing
//   g_vt16 [hb][d][l] directly.
// ============================================================================
#define LDA 80u
#define G2_AHI 0u
#define G2_ALO 10240u
#define G2_BHI 20480u
#define G2_BLO 30720u
#define G2_STG 40960u
#define GEMM_SMEM (3 * 40960)
#define GF_A 0u
#define GF_B 10240u
#define GF_STG 20480u

__global__ __launch_bounds__(256)
void gemm_qkv(const float* __restrict__ bias)
{
    extern __shared__ __align__(128) char smem[];
    const uint32_t sb  = smem_u32(smem);
    const int tid  = threadIdx.x;
    const int lane = tid & 31;
    const int wid  = tid >> 5;
    const int wm   = wid & 1;
    const int wn   = wid >> 1;
    const int m0   = blockIdx.x * 128;

    const int cp_r = tid >> 2;
    const int cp_c = tid & 3;
    const int ce   = cp_c * 8;
    const uint32_t a_row = (uint32_t)(wm * 64 + (lane & 7) + ((lane >> 3) & 1) * 8);
    const uint32_t a_kb  = (uint32_t)(lane >> 4) * 16u;
    const uint32_t b_row = (uint32_t)(wn * 32 + (lane & 7) + (lane >> 4) * 8);
    const uint32_t b_kb  = (uint32_t)((lane >> 3) & 1) * 16u;
    const int g  = lane >> 2;
    const int tg = lane & 3;

    float acc[4][4][4];
    #pragma unroll
    for (int mt = 0; mt < 4; ++mt)
        #pragma unroll
        for (int nt = 0; nt < 4; ++nt)
            #pragma unroll
            for (int i = 0; i < 4; ++i) acc[mt][nt][i] = 0.f;

    if (blockIdx.y < 16) {
        // ==================== Q/K path: 3-term split bf16 ====================
        const int grp0 = blockIdx.y * 2;
        const __nv_bfloat16* Ahi = g_xhi;
        const __nv_bfloat16* Alo = g_xlo;
        const __nv_bfloat16* Bh0 = g_wthi + (size_t)grp0 * 65536;
        const __nv_bfloat16* Bl0 = g_wtlo + (size_t)grp0 * 65536;

        auto issue = [&](int ks, uint32_t stg) {
            const int k0 = ks * 32;
            uint32_t d0 = stg + (uint32_t)cp_r * LDA + (uint32_t)cp_c * 16u;
            uint32_t d1 = d0 + 64u * LDA;
            size_t a0 = (size_t)(m0 + cp_r) * 1024 + k0 + ce;
            size_t a1 = a0 + 64 * 1024;
            size_t b0 = (size_t)cp_r * 1024 + k0 + ce;
            cp_async16(d0 + G2_AHI, Ahi + a0);
            cp_async16(d1 + G2_AHI, Ahi + a1);
            cp_async16(d0 + G2_ALO, Alo + a0);
            cp_async16(d1 + G2_ALO, Alo + a1);
            cp_async16(d0 + G2_BHI, Bh0 + b0);
            cp_async16(d1 + G2_BHI, Bh0 + 65536 + b0);
            cp_async16(d0 + G2_BLO, Bl0 + b0);
            cp_async16(d1 + G2_BLO, Bl0 + 65536 + b0);
            cp_commit();
        };

        issue(0, sb);
        issue(1, sb + G2_STG);

        for (int ks = 0; ks < 32; ++ks) {
            if (ks < 31) cp_wait<1>(); else cp_wait<0>();
            __syncthreads();
            if (ks + 2 < 32) issue(ks + 2, sb + (uint32_t)((ks + 2) % 3) * G2_STG);

            const uint32_t stg = sb + (uint32_t)(ks % 3) * G2_STG;
            const uint32_t aHi = stg + G2_AHI + a_row * LDA + a_kb;
            const uint32_t aLo = stg + G2_ALO + a_row * LDA + a_kb;
            const uint32_t bHi = stg + G2_BHI + b_row * LDA + b_kb;
            const uint32_t bLo = stg + G2_BLO + b_row * LDA + b_kb;

            #pragma unroll
            for (int kk = 0; kk < 2; ++kk) {
                const uint32_t koff = (uint32_t)kk * 32u;

                uint32_t ahi[4][4], alo[4][4];
                #pragma unroll
                for (int mt = 0; mt < 4; ++mt) {
                    ldmatrix_x4(ahi[mt][0], ahi[mt][1], ahi[mt][2], ahi[mt][3],
                                aHi + (uint32_t)mt * 16u * LDA + koff);
                    ldmatrix_x4(alo[mt][0], alo[mt][1], alo[mt][2], alo[mt][3],
                                aLo + (uint32_t)mt * 16u * LDA + koff);
                }
                uint32_t bhi[4][2], blo[4][2];
                #pragma unroll
                for (int ntp = 0; ntp < 2; ++ntp) {
                    uint32_t r0, r1, r2, r3;
                    ldmatrix_x4(r0, r1, r2, r3, bHi + (uint32_t)ntp * 16u * LDA + koff);
                    bhi[ntp * 2][0] = r0; bhi[ntp * 2][1] = r1;
                    bhi[ntp * 2 + 1][0] = r2; bhi[ntp * 2 + 1][1] = r3;
                    ldmatrix_x4(r0, r1, r2, r3, bLo + (uint32_t)ntp * 16u * LDA + koff);
                    blo[ntp * 2][0] = r0; blo[ntp * 2][1] = r1;
                    blo[ntp * 2 + 1][0] = r2; blo[ntp * 2 + 1][1] = r3;
                }

                #pragma unroll
                for (int mt = 0; mt < 4; ++mt)
                    #pragma unroll
                    for (int nt = 0; nt < 4; ++nt) {
                        mma_bf16(acc[mt][nt], ahi[mt][0], ahi[mt][1], ahi[mt][2], ahi[mt][3],
                                 bhi[nt][0], bhi[nt][1]);
                        mma_bf16(acc[mt][nt], ahi[mt][0], ahi[mt][1], ahi[mt][2], ahi[mt][3],
                                 blo[nt][0], blo[nt][1]);
                        mma_bf16(acc[mt][nt], alo[mt][0], alo[mt][1], alo[mt][2], alo[mt][3],
                                 bhi[nt][0], bhi[nt][1]);
                    }
            }
        }

        const float QSCALE = 11.5415603272f;
        #pragma unroll
        for (int mt = 0; mt < 4; ++mt)
            #pragma unroll
            for (int nt = 0; nt < 4; ++nt) {
                int n    = wn * 32 + nt * 8 + tg * 2;
                int gsel = n >> 6;
                int c64  = n & 63;
                int e    = grp0 + gsel;
                const float* bp = bias + (size_t)e * 64;
                float b0 = bp[c64], b1 = bp[c64 + 1];
                int r0 = m0 + wm * 64 + mt * 16 + g;
                float v00 = acc[mt][nt][0] + b0, v01 = acc[mt][nt][1] + b1;
                float v10 = acc[mt][nt][2] + b0, v11 = acc[mt][nt][3] + b1;
                bool isQ = (e < 16);
                float s = isQ ? QSCALE : 1.f;
                v00 *= s; v01 *= s; v10 *= s; v11 *= s;
                __nv_bfloat16* dh = isQ ? g_qhi : g_khi;
                __nv_bfloat16* dl = isQ ? g_qlo : g_klo;
                int eo = isQ ? e : (e - 16);
                size_t base0 = ((size_t)eo * 8192 + r0) * 64 + c64;
                size_t base1 = base0 + 8 * 64;
                uint32_t h, l;
                split2_bf(v00, v01, h, l);
                *(uint32_t*)&dh[base0] = h;
                *(uint32_t*)&dl[base0] = l;
                split2_bf(v10, v11, h, l);
                *(uint32_t*)&dh[base1] = h;
                *(uint32_t*)&dl[base1] = l;
            }
    } else {
        // ============ V path: 1-term fp16, transposed epilogue ============
        const int grp0 = (blockIdx.y - 16) * 2;
        const float* biasv = bias + 32 * 64;
        const __half* A  = g_x16;
        const __half* B0 = g_wt16 + (size_t)grp0 * 65536;

        auto issue = [&](int ks, uint32_t stg) {
            const int k0 = ks * 32;
            uint32_t d0 = stg + (uint32_t)cp_r * LDA + (uint32_t)cp_c * 16u;
            uint32_t d1 = d0 + 64u * LDA;
            size_t a0 = (size_t)(m0 + cp_r) * 1024 + k0 + ce;
            size_t a1 = a0 + 64 * 1024;
            size_t b0 = (size_t)cp_r * 1024 + k0 + ce;
            cp_async16(d0 + GF_A, A + a0);
            cp_async16(d1 + GF_A, A + a1);
            cp_async16(d0 + GF_B, B0 + b0);
            cp_async16(d1 + GF_B, B0 + 65536 + b0);
            cp_commit();
        };

        issue(0, sb);
        issue(1, sb + GF_STG);

        for (int ks = 0; ks < 32; ++ks) {
            if (ks < 31) cp_wait<1>(); else cp_wait<0>();
            __syncthreads();
            if (ks + 2 < 32) issue(ks + 2, sb + (uint32_t)((ks + 2) % 3) * GF_STG);

            const uint32_t stg = sb + (uint32_t)(ks % 3) * GF_STG;
            const uint32_t aB = stg + GF_A + a_row * LDA + a_kb;
            const uint32_t bB = stg + GF_B + b_row * LDA + b_kb;

            #pragma unroll
            for (int kk = 0; kk < 2; ++kk) {
                const uint32_t koff = (uint32_t)kk * 32u;

                uint32_t af[4][4];
                #pragma unroll
                for (int mt = 0; mt < 4; ++mt)
                    ldmatrix_x4(af[mt][0], af[mt][1], af[mt][2], af[mt][3],
                                aB + (uint32_t)mt * 16u * LDA + koff);
                uint32_t bf[4][2];
                #pragma unroll
                for (int ntp = 0; ntp < 2; ++ntp) {
                    uint32_t r0, r1, r2, r3;
                    ldmatrix_x4(r0, r1, r2, r3, bB + (uint32_t)ntp * 16u * LDA + koff);
                    bf[ntp * 2][0] = r0; bf[ntp * 2][1] = r1;
                    bf[ntp * 2 + 1][0] = r2; bf[ntp * 2 + 1][1] = r3;
                }

                #pragma unroll
                for (int mt = 0; mt < 4; ++mt)
                    #pragma unroll
                    for (int nt = 0; nt < 4; ++nt)
                        mma_f16(acc[mt][nt], af[mt][0], af[mt][1], af[mt][2], af[mt][3],
                                bf[nt][0], bf[nt][1]);
            }
        }

        // ---- transpose epilogue: stage fp16 [n][row] in smem, write [d][l] ----
        __syncthreads();
        __half* tile = (__half*)smem;   // [128 n][136 row-stride]
        #pragma unroll
        for (int mt = 0; mt < 4; ++mt)
            #pragma unroll
            for (int nt = 0; nt < 4; ++nt) {
                int n    = wn * 32 + nt * 8 + tg * 2;
                int c64  = n & 63;
                const float* bp = biasv + (size_t)(grp0 + (n >> 6)) * 64;
                float b0 = bp[c64], b1 = bp[c64 + 1];
                int r0 = wm * 64 + mt * 16 + g;
                tile[(n    ) * 136 + r0]     = __float2half(acc[mt][nt][0] + b0);
                tile[(n + 1) * 136 + r0]     = __float2half(acc[mt][nt][1] + b1);
                tile[(n    ) * 136 + r0 + 8] = __float2half(acc[mt][nt][2] + b0);
                tile[(n + 1) * 136 + r0 + 8] = __float2half(acc[mt][nt][3] + b1);
            }
        __syncthreads();

        const int b  = m0 >> 11;
        const int l0 = m0 & 2047;
        #pragma unroll
        for (int i = 0; i < 8; ++i) {
            int idx = tid + i * 256;
            int d   = idx >> 4;
            int c   = idx & 15;
            uint4 v = *(uint4*)&tile[d * 136 + c * 8];
            int e   = grp0 + (d >> 6);
            int dl  = d & 63;
            int hb  = e * 4 + b;
            *(uint4*)&g_vt16[((size_t)hb * 64 + dl) * 2048 + l0 + c * 8] = v;
        }
    }
}

// ============================================================================
// gemm_proj: 128x128 tile, 2-term split-fp16, 3-stage, 2 CTAs/SM (proven).
// ============================================================================
#define GP_AHI 0u
#define GP_ALO 10240u
#define GP_B   20480u
#define GP_STG 30720u
#define GP_SMEM (3 * 30720)

__global__ __launch_bounds__(256)
void gemm_proj(const float* __restrict__ bias, float* __restrict__ C)
{
    extern __shared__ __align__(128) char smem[];
    const uint32_t sb  = smem_u32(smem);
    const int tid  = threadIdx.x;
    const int lane = tid & 31;
    const int wid  = tid >> 5;
    const int wm   = wid & 1;
    const int wn   = wid >> 1;
    const int m0   = blockIdx.x * 128;
    const int n0   = blockIdx.y * 128;

    const __half* Ahi = g_avhi;
    const __half* Alo = g_avlo;
    const __half* B0  = g_wp16 + (size_t)n0 * 1024;

    float acc[4][4][4];
    #pragma unroll
    for (int mt = 0; mt < 4; ++mt)
        #pragma unroll
        for (int nt = 0; nt < 4; ++nt)
            #pragma unroll
            for (int i = 0; i < 4; ++i) acc[mt][nt][i] = 0.f;

    const int cp_r = tid >> 2;
    const int cp_c = tid & 3;
    const int ce   = cp_c * 8;
    auto issue = [&](int ks, uint32_t stg) {
        const int k0 = ks * 32;
        uint32_t d0 = stg + (uint32_t)cp_r * LDA + (uint32_t)cp_c * 16u;
        uint32_t d1 = d0 + 64u * LDA;
        size_t a0 = (size_t)(m0 + cp_r) * 1024 + k0 + ce;
        size_t a1 = a0 + 64 * 1024;
        size_t b0 = (size_t)cp_r * 1024 + k0 + ce;
        cp_async16(d0 + GP_AHI, Ahi + a0);
        cp_async16(d1 + GP_AHI, Ahi + a1);
        cp_async16(d0 + GP_ALO, Alo + a0);
        cp_async16(d1 + GP_ALO, Alo + a1);
        cp_async16(d0 + GP_B, B0 + b0);
        cp_async16(d1 + GP_B, B0 + 65536 + b0);
        cp_commit();
    };

    const uint32_t a_row = (uint32_t)(wm * 64 + (lane & 7) + ((lane >> 3) & 1) * 8);
    const uint32_t a_kb  = (uint32_t)(lane >> 4) * 16u;
    const uint32_t b_row = (uint32_t)(wn * 32 + (lane & 7) + (lane >> 4) * 8);
    const uint32_t b_kb  = (uint32_t)((lane >> 3) & 1) * 16u;

    issue(0, sb);
    issue(1, sb + GP_STG);

    for (int ks = 0; ks < 32; ++ks) {
        if (ks < 31) cp_wait<1>(); else cp_wait<0>();
        __syncthreads();
        if (ks + 2 < 32) issue(ks + 2, sb + (uint32_t)((ks + 2) % 3) * GP_STG);

        const uint32_t stg = sb + (uint32_t)(ks % 3) * GP_STG;
        const uint32_t aHi = stg + GP_AHI + a_row * LDA + a_kb;
        const uint32_t aLo = stg + GP_ALO + a_row * LDA + a_kb;
        const uint32_t bB  = stg + GP_B   + b_row * LDA + b_kb;

        #pragma unroll
        for (int kk = 0; kk < 2; ++kk) {
            const uint32_t koff = (uint32_t)kk * 32u;

            uint32_t ahi[4][4], alo[4][4];
            #pragma unroll
            for (int mt = 0; mt < 4; ++mt) {
                ldmatrix_x4(ahi[mt][0], ahi[mt][1], ahi[mt][2], ahi[mt][3],
                            aHi + (uint32_t)mt * 16u * LDA + koff);
                ldmatrix_x4(alo[mt][0], alo[mt][1], alo[mt][2], alo[mt][3],
                            aLo + (uint32_t)mt * 16u * LDA + koff);
            }
            uint32_t bf[4][2];
            #pragma unroll
            for (int ntp = 0; ntp < 2; ++ntp) {
                uint32_t r0, r1, r2, r3;
                ldmatrix_x4(r0, r1, r2, r3, bB + (uint32_t)ntp * 16u * LDA + koff);
                bf[ntp * 2][0] = r0; bf[ntp * 2][1] = r1;
                bf[ntp * 2 + 1][0] = r2; bf[ntp * 2 + 1][1] = r3;
            }

            #pragma unroll
            for (int mt = 0; mt < 4; ++mt)
                #pragma unroll
                for (int nt = 0; nt < 4; ++nt) {
                    mma_f16(acc[mt][nt], ahi[mt][0], ahi[mt][1], ahi[mt][2], ahi[mt][3],
                            bf[nt][0], bf[nt][1]);
                    mma_f16(acc[mt][nt], alo[mt][0], alo[mt][1], alo[mt][2], alo[mt][3],
                            bf[nt][0], bf[nt][1]);
                }
        }
    }

    const int g  = lane >> 2;
    const int tg = lane & 3;
    #pragma unroll
    for (int mt = 0; mt < 4; ++mt)
        #pragma unroll
        for (int nt = 0; nt < 4; ++nt) {
            int n = n0 + wn * 32 + nt * 8 + tg * 2;
            float b0 = bias[n], b1 = bias[n + 1];
            int r0 = m0 + wm * 64 + mt * 16 + g;
            float2 o0 = make_float2(acc[mt][nt][0] + b0, acc[mt][nt][1] + b1);
            float2 o1 = make_float2(acc[mt][nt][2] + b0, acc[mt][nt][3] + b1);
            *(float2*)(C + (size_t)r0 * 1024 + n)       = o0;
            *(float2*)(C + (size_t)(r0 + 8) * 1024 + n) = o1;
        }
}

// ============================================================================
// attn_mma: flash attention. S 3-term bf16, PV 1-term fp16.
//   4-stage cp.async (new), 2 CTAs/SM (2 x 110.6 KB = 221 KB <= 228 KB).
// ============================================================================
#define LDS_ROW 144u
#define ST_KHI 0u
#define ST_KLO 9216u
#define ST_V16 18432u
#define STAGE_BYTES 27648u
#define ATTN_SMEM (4 * 27648)

__global__ __launch_bounds__(256, 2)
void attn_mma()
{
    extern __shared__ __align__(128) char smem[];
    const uint32_t sb = smem_u32(smem);
    const int tid  = threadIdx.x;
    const int lane = tid & 31;
    const int wid  = tid >> 5;
    const int g    = lane >> 2;
    const int tg   = lane & 3;
    const int hb   = blockIdx.y;
    const int hd   = hb >> 2;
    const int b    = hb & 3;
    const int q0   = blockIdx.x * 128;

    const __nv_bfloat16* Qhi = g_qhi + ((size_t)hd * 8192 + b * 2048 + q0) * 64;
    const __nv_bfloat16* Qlo = g_qlo + ((size_t)hd * 8192 + b * 2048 + q0) * 64;
    const __nv_bfloat16* Khi = g_khi + (size_t)hb * 2048 * 64;
    const __nv_bfloat16* Klo = g_klo + (size_t)hb * 2048 * 64;
    const __half*        V16 = g_vt16 + (size_t)hb * 64 * 2048;

    // ---- stage Q (pre-scaled, pre-split) via cp.async, extract fragments ----
    #pragma unroll
    for (int i = 0; i < 4; ++i) {
        int idx = tid + i * 256;
        int row = idx >> 3;
        int c   = idx & 7;
        cp_async16(sb + (uint32_t)row * LDS_ROW + (uint32_t)c * 16u,
                   Qhi + (size_t)row * 64 + c * 8);
        cp_async16(sb + 18432u + (uint32_t)row * LDS_ROW + (uint32_t)c * 16u,
                   Qlo + (size_t)row * 64 + c * 8);
    }
    cp_commit();
    cp_wait<0>();
    __syncthreads();

    uint32_t qhi[4][4], qlo[4][4];
    {
        const uint32_t qrow = (uint32_t)(wid * 16 + (lane & 7) + ((lane >> 3) & 1) * 8);
        const uint32_t kb   = (uint32_t)(lane >> 4) * 16u;
        const uint32_t aH = sb + qrow * LDS_ROW + kb;
        const uint32_t aL = sb + 18432u + qrow * LDS_ROW + kb;
        #pragma unroll
        for (int t = 0; t < 4; ++t) {
            ldmatrix_x4(qhi[t][0], qhi[t][1], qhi[t][2], qhi[t][3], aH + t * 32u);
            ldmatrix_x4(qlo[t][0], qlo[t][1], qlo[t][2], qlo[t][3], aL + t * 32u);
        }
    }
    __syncthreads();   // Q consumed — smem free for stages

    float mA = -1e30f, mB = -1e30f, lA = 0.f, lB = 0.f;
    float oacc[8][4];
    #pragma unroll
    for (int j = 0; j < 8; ++j)
        #pragma unroll
        for (int i = 0; i < 4; ++i) oacc[j][i] = 0.f;

    const uint32_t brow = (uint32_t)((lane & 7) + (lane >> 4) * 8);
    const uint32_t bkb  = (uint32_t)((lane >> 3) & 1) * 16u;

    const int cp_row = tid >> 3;
    const int cp_c   = tid & 7;
    auto issue = [&](int j0, uint32_t stg) {
        #pragma unroll
        for (int i = 0; i < 2; ++i) {
            int row = cp_row + i * 32;
            uint32_t doff = stg + (uint32_t)row * LDS_ROW + (uint32_t)cp_c * 16u;
            cp_async16(doff + ST_KHI, Khi + ((size_t)(j0 + row)) * 64 + cp_c * 8);
            cp_async16(doff + ST_KLO, Klo + ((size_t)(j0 + row)) * 64 + cp_c * 8);
            cp_async16(doff + ST_V16, V16 + ((size_t)row) * 2048 + j0 + cp_c * 8);
        }
        cp_commit();
    };

    issue(0,   sb);
    issue(64,  sb + STAGE_BYTES);
    issue(128, sb + 2 * STAGE_BYTES);

    for (int j = 0; j < 32; ++j) {
        if (j <= 29) cp_wait<2>();
        else if (j == 30) cp_wait<1>();
        else cp_wait<0>();
        __syncthreads();
        if (j + 3 < 32) issue((j + 3) * 64, sb + (uint32_t)((j + 3) % 4) * STAGE_BYTES);

        const uint32_t stg = sb + (uint32_t)(j % 4) * STAGE_BYTES;

        // ---- S = Qscaled @ K^T (split 3-term bf16), log2 units ----
        float sacc[8][4];
        #pragma unroll
        for (int jj = 0; jj < 8; ++jj)
            #pragma unroll
            for (int i = 0; i < 4; ++i) sacc[jj][i] = 0.f;

        #pragma unroll
        for (int td = 0; td < 4; ++td) {
            uint32_t bhi[8][2], blo[8][2];
            #pragma unroll
            for (int ntp = 0; ntp < 4; ++ntp) {
                uint32_t base = (uint32_t)(ntp * 16) * LDS_ROW + brow * LDS_ROW + bkb
                                + (uint32_t)td * 32u;
                uint32_t r0, r1, r2, r3;
                ldmatrix_x4(r0, r1, r2, r3, stg + ST_KHI + base);
                bhi[ntp * 2][0] = r0; bhi[ntp * 2][1] = r1;
                bhi[ntp * 2 + 1][0] = r2; bhi[ntp * 2 + 1][1] = r3;
                ldmatrix_x4(r0, r1, r2, r3, stg + ST_KLO + base);
                blo[ntp * 2][0] = r0; blo[ntp * 2][1] = r1;
                blo[ntp * 2 + 1][0] = r2; blo[ntp * 2 + 1][1] = r3;
            }
            #pragma unroll
            for (int nt = 0; nt < 8; ++nt) {
                mma_bf16(sacc[nt], qhi[td][0], qhi[td][1], qhi[td][2], qhi[td][3],
                         bhi[nt][0], bhi[nt][1]);
                mma_bf16(sacc[nt], qhi[td][0], qhi[td][1], qhi[td][2], qhi[td][3],
                         blo[nt][0], blo[nt][1]);
                mma_bf16(sacc[nt], qlo[td][0], qlo[td][1], qlo[td][2], qlo[td][3],
                         bhi[nt][0], bhi[nt][1]);
            }
        }

        // ---- online softmax (log2 domain) ----
        float rmA = -1e30f, rmB = -1e30f;
        #pragma unroll
        for (int jj = 0; jj < 8; ++jj) {
            rmA = fmaxf(rmA, fmaxf(sacc[jj][0], sacc[jj][1]));
            rmB = fmaxf(rmB, fmaxf(sacc[jj][2], sacc[jj][3]));
        }
        rmA = fmaxf(rmA, __shfl_xor_sync(0xffffffffu, rmA, 1));
        rmA = fmaxf(rmA, __shfl_xor_sync(0xffffffffu, rmA, 2));
        rmB = fmaxf(rmB, __shfl_xor_sync(0xffffffffu, rmB, 1));
        rmB = fmaxf(rmB, __shfl_xor_sync(0xffffffffu, rmB, 2));

        float mnA = fmaxf(mA, rmA), mnB = fmaxf(mB, rmB);
        float corrA = exp2_fast(mA - mnA), corrB = exp2_fast(mB - mnB);

        float sumA = 0.f, sumB = 0.f;
        uint32_t pf[4][4];
        #pragma unroll
        for (int jj = 0; jj < 8; ++jj) {
            float p0 = exp2_fast(sacc[jj][0] - mnA);
            float p1 = exp2_fast(sacc[jj][1] - mnA);
            float p2 = exp2_fast(sacc[jj][2] - mnB);
            float p3 = exp2_fast(sacc[jj][3] - mnB);
            sumA += p0 + p1; sumB += p2 + p3;
            int t = jj >> 1;
            int o = (jj & 1) * 2;
            pf[t][o]     = pack_f16x2(p0, p1);
            pf[t][o + 1] = pack_f16x2(p2, p3);
        }
        sumA += __shfl_xor_sync(0xffffffffu, sumA, 1);
        sumA += __shfl_xor_sync(0xffffffffu, sumA, 2);
        sumB += __shfl_xor_sync(0xffffffffu, sumB, 1);
        sumB += __shfl_xor_sync(0xffffffffu, sumB, 2);

        lA = lA * corrA + sumA;
        lB = lB * corrB + sumB;
        mA = mnA; mB = mnB;

        #pragma unroll
        for (int jj = 0; jj < 8; ++jj) {
            oacc[jj][0] *= corrA; oacc[jj][1] *= corrA;
            oacc[jj][2] *= corrB; oacc[jj][3] *= corrB;
        }

        // ---- O += P @ V (1-term fp16) ----
        #pragma unroll
        for (int t = 0; t < 4; ++t) {
            uint32_t vf[8][2];
            #pragma unroll
            for (int ntp = 0; ntp < 4; ++ntp) {
                uint32_t base = (uint32_t)(ntp * 16) * LDS_ROW + brow * LDS_ROW + bkb
                                + (uint32_t)t * 32u;
                uint32_t r0, r1, r2, r3;
                ldmatrix_x4(r0, r1, r2, r3, stg + ST_V16 + base);
                vf[ntp * 2][0] = r0; vf[ntp * 2][1] = r1;
                vf[ntp * 2 + 1][0] = r2; vf[ntp * 2 + 1][1] = r3;
            }
            #pragma unroll
            for (int nd = 0; nd < 8; ++nd)
                mma_f16(oacc[nd], pf[t][0], pf[t][1], pf[t][2], pf[t][3],
                        vf[nd][0], vf[nd][1]);
        }
    }

    // ---- epilogue: normalize, split to fp16 hi/lo, write g_avhi/g_avlo ----
    const float invA = 1.f / lA, invB = 1.f / lB;
    const int rowA = q0 + wid * 16 + g;
    const int rowB = rowA + 8;
    #pragma unroll
    for (int jd = 0; jd < 8; ++jd) {
        int col = hd * 64 + jd * 8 + tg * 2;
        {
            uint32_t h, l;
            split2_f16(oacc[jd][0] * invA, oacc[jd][1] * invA, h, l);
            size_t base = (size_t)(b * 2048 + rowA) * 1024 + col;
            *(uint32_t*)&g_avhi[base] = h;
            *(uint32_t*)&g_avlo[base] = l;
        }
        {
            uint32_t h, l;
            split2_f16(oacc[jd][2] * invB, oacc[jd][3] * invB, h, l);
            size_t base = (size_t)(b * 2048 + rowB) * 1024 + col;
            *(uint32_t*)&g_avhi[base] = h;
            *(uint32_t*)&g_avlo[base] = l;
        }
    }
}

// ============================================================================
extern "C" void kernel_launch(void* const* d_in, const int* in_sizes, int n_in,
                              void* d_out, int out_size)
{
    const float* x    = (const float*)d_in[0];   // (4, 2048, 1024)
    const float* Wqkv = (const float*)d_in[1];   // (48, 1024, 64)
    const float* bqkv = (const float*)d_in[2];   // (48, 64)
    const float* Wp   = (const float*)d_in[3];   // (1024, 1024)
    const float* bp   = (const float*)d_in[4];   // (1024,)
    float* out = (float*)d_out;                  // (4, 2048, 1024)

    cudaFuncSetAttribute(gemm_qkv, cudaFuncAttributeMaxDynamicSharedMemorySize,
                         GEMM_SMEM);
    cudaFuncSetAttribute(gemm_proj, cudaFuncAttributeMaxDynamicSharedMemorySize,
                         GP_SMEM);
    cudaFuncSetAttribute(attn_mma, cudaFuncAttributeMaxDynamicSharedMemorySize,
                         ATTN_SMEM);

    // 1) fused preps: x split + Wp fp16 + Wqkv transpose/split
    prep_all<<<5376, 256>>>(x, Wp, Wqkv);

    // 2) fused QKV: Q/K 3-term bf16 (y 0..15) + V 1-term fp16 (y 16..23);
    //    V epilogue writes transposed g_vt16 directly.
    gemm_qkv<<<dim3(64, 24), 256, GEMM_SMEM>>>(bqkv);

    // 3) attention (4-stage, 2 CTAs/SM)
    attn_mma<<<dim3(16, 64), 256, ATTN_SMEM>>>();

    // 4) proj: 2-term split-fp16, 128x128 tiles, 3-stage
    gemm_proj<<<dim3(64, 8), 256, GP_SMEM>>>(bp, out);
}

// round 17
// speedup vs baseline: 1.1540x; 1.0217x over previous
#include <cuda_runtime.h>
#include <cuda_bf16.h>
#include <cuda_fp16.h>
#include <stdint.h>
#include <math.h>

// ============================================================================
// Scratch (device globals — no allocations allowed).
// ============================================================================
__device__ __align__(16) __nv_bfloat16 g_xhi [8192ull * 1024];
__device__ __align__(16) __nv_bfloat16 g_xlo [8192ull * 1024];
__device__ __align__(16) __half        g_x16 [8192ull * 1024];
__device__ __align__(16) __nv_bfloat16 g_wthi[32ull * 64 * 1024];   // Q/K W^T [e][h][d]
__device__ __align__(16) __nv_bfloat16 g_wtlo[32ull * 64 * 1024];
__device__ __align__(16) __half        g_wt16[16ull * 64 * 1024];   // V W^T fp16
__device__ __align__(16) __half        g_wp16[1024ull * 1024];      // Wp fp16
__device__ __align__(16) __half        g_avhi[8192ull * 1024];      // av split fp16
__device__ __align__(16) __half        g_avlo[8192ull * 1024];
__device__ __align__(16) __nv_bfloat16 g_qhi [16ull * 8192 * 64];   // [hd][row][d], scaled
__device__ __align__(16) __nv_bfloat16 g_qlo [16ull * 8192 * 64];
__device__ __align__(16) __nv_bfloat16 g_khi [16ull * 8192 * 64];
__device__ __align__(16) __nv_bfloat16 g_klo [16ull * 8192 * 64];
__device__ __align__(16) __half        g_vt16[64ull * 64 * 2048];   // [hb][d][l]

// ============================================================================
// PTX helpers (sm_80-era ISA — compiles for plain compute_103)
// ============================================================================
__device__ __forceinline__ uint32_t smem_u32(const void* p) {
    uint32_t a;
    asm("{ .reg .u64 t; cvta.to.shared.u64 t, %1; cvt.u32.u64 %0, t; }"
        : "=r"(a) : "l"(p));
    return a;
}

__device__ __forceinline__ void ldmatrix_x4(uint32_t& r0, uint32_t& r1,
                                            uint32_t& r2, uint32_t& r3,
                                            uint32_t addr) {
    asm volatile("ldmatrix.sync.aligned.m8n8.x4.shared.b16 {%0,%1,%2,%3}, [%4];"
                 : "=r"(r0), "=r"(r1), "=r"(r2), "=r"(r3) : "r"(addr));
}

__device__ __forceinline__ void mma_bf16(float* c,
                                         uint32_t a0, uint32_t a1, uint32_t a2, uint32_t a3,
                                         uint32_t b0, uint32_t b1) {
    asm volatile("mma.sync.aligned.m16n8k16.row.col.f32.bf16.bf16.f32 "
                 "{%0,%1,%2,%3}, {%4,%5,%6,%7}, {%8,%9}, {%0,%1,%2,%3};"
                 : "+f"(c[0]), "+f"(c[1]), "+f"(c[2]), "+f"(c[3])
                 : "r"(a0), "r"(a1), "r"(a2), "r"(a3), "r"(b0), "r"(b1));
}

__device__ __forceinline__ void mma_f16(float* c,
                                        uint32_t a0, uint32_t a1, uint32_t a2, uint32_t a3,
                                        uint32_t b0, uint32_t b1) {
    asm volatile("mma.sync.aligned.m16n8k16.row.col.f32.f16.f16.f32 "
                 "{%0,%1,%2,%3}, {%4,%5,%6,%7}, {%8,%9}, {%0,%1,%2,%3};"
                 : "+f"(c[0]), "+f"(c[1]), "+f"(c[2]), "+f"(c[3])
                 : "r"(a0), "r"(a1), "r"(a2), "r"(a3), "r"(b0), "r"(b1));
}

__device__ __forceinline__ void cp_async16(uint32_t dst, const void* src) {
    asm volatile("cp.async.cg.shared.global [%0], [%1], 16;"
                 :: "r"(dst), "l"(src) : "memory");
}
__device__ __forceinline__ void cp_commit() {
    asm volatile("cp.async.commit_group;" ::: "memory");
}
template <int N>
__device__ __forceinline__ void cp_wait() {
    asm volatile("cp.async.wait_group %0;" :: "n"(N) : "memory");
}

__device__ __forceinline__ uint32_t pack_bf16x2(float x, float y) {
    uint32_t r;
    asm("cvt.rn.bf16x2.f32 %0, %1, %2;" : "=r"(r) : "f"(y), "f"(x));
    return r;
}
__device__ __forceinline__ uint32_t pack_f16x2(float x, float y) {
    uint32_t r;
    asm("cvt.rn.f16x2.f32 %0, %1, %2;" : "=r"(r) : "f"(y), "f"(x));
    return r;
}

// fast 2^t for t <= 0, FFMA/ALU only (no MUFU). rel err ~2.5e-6.
__device__ __forceinline__ float exp2_fast(float t) {
    float r = fmaxf(t, -30.f);
    float z = r + 12582912.f;
    int   i = __float_as_int(z);
    float f = r - (z - 12582912.f);
    float p = 1.33335581e-3f;
    p = fmaf(p, f, 9.61812911e-3f);
    p = fmaf(p, f, 5.55041087e-2f);
    p = fmaf(p, f, 2.40226507e-1f);
    p = fmaf(p, f, 6.93147181e-1f);
    p = fmaf(p, f, 1.0f);
    return p * __int_as_float((i + 127) << 23);
}

__device__ __forceinline__ void split4(float4 v, uint32_t& h01, uint32_t& h23,
                                       uint32_t& l01, uint32_t& l23) {
    h01 = pack_bf16x2(v.x, v.y);
    h23 = pack_bf16x2(v.z, v.w);
    float r0 = v.x - __int_as_float(h01 << 16);
    float r1 = v.y - __int_as_float(h01 & 0xFFFF0000u);
    float r2 = v.z - __int_as_float(h23 << 16);
    float r3 = v.w - __int_as_float(h23 & 0xFFFF0000u);
    l01 = pack_bf16x2(r0, r1);
    l23 = pack_bf16x2(r2, r3);
}

__device__ __forceinline__ void split2_bf(float a, float b, uint32_t& h, uint32_t& l) {
    h = pack_bf16x2(a, b);
    float ra = a - __int_as_float(h << 16);
    float rb = b - __int_as_float(h & 0xFFFF0000u);
    l = pack_bf16x2(ra, rb);
}

__device__ __forceinline__ void split2_f16(float a, float b, uint32_t& h, uint32_t& l) {
    h = pack_f16x2(a, b);
    float ha = __half2float(__ushort_as_half((unsigned short)(h & 0xFFFFu)));
    float hb = __half2float(__ushort_as_half((unsigned short)(h >> 16)));
    l = pack_f16x2(a - ha, b - hb);
}

// ============================================================================
// prep_all: fused x-split (blocks 0..2047), Wp->fp16 (2048..2303),
//           Wqkv transpose/split (2304..5375).
// ============================================================================
__global__ __launch_bounds__(256)
void prep_all(const float* __restrict__ x, const float* __restrict__ Wp,
              const float* __restrict__ W)
{
    const int tid = threadIdx.x;
    if (blockIdx.x < 2048) {
        #pragma unroll
        for (int i = 0; i < 4; ++i) {
            size_t idx = (size_t)blockIdx.x * 256 + tid + (size_t)i * 524288;
            float4 v = *(const float4*)(x + idx * 4);
            uint32_t h01, h23, l01, l23;
            split4(v, h01, h23, l01, l23);
            *(uint2*)&g_xhi[idx * 4] = make_uint2(h01, h23);
            *(uint2*)&g_xlo[idx * 4] = make_uint2(l01, l23);
            *(uint2*)&g_x16[idx * 4] = make_uint2(pack_f16x2(v.x, v.y),
                                                  pack_f16x2(v.z, v.w));
        }
    } else if (blockIdx.x < 2304) {
        size_t base = (size_t)(blockIdx.x - 2048) * 256 + tid;
        #pragma unroll
        for (int i = 0; i < 4; ++i) {
            size_t idx = base + (size_t)i * 65536;
            float4 v = *(const float4*)(Wp + idx * 4);
            *(uint2*)&g_wp16[idx * 4] = make_uint2(pack_f16x2(v.x, v.y),
                                                   pack_f16x2(v.z, v.w));
        }
    } else {
        __shared__ float t[32][33];
        const int blk = blockIdx.x - 2304;       // 0..3071
        const int e   = blk >> 6;                // 0..47
        const int k0  = ((blk >> 1) & 31) * 32;
        const int h0  = (blk & 1) * 32;
        const int tx  = tid & 31;
        const int ty  = tid >> 5;                // 0..7
        #pragma unroll
        for (int i = 0; i < 32; i += 8)
            t[ty + i][tx] = W[(size_t)e * 65536 + (size_t)(k0 + ty + i) * 64 + h0 + tx];
        __syncthreads();
        #pragma unroll
        for (int i = 0; i < 32; i += 8) {
            float val = t[tx][ty + i];
            if (e < 32) {
                __nv_bfloat16 hi = __float2bfloat16(val);
                __nv_bfloat16 lo = __float2bfloat16(val - __bfloat162float(hi));
                size_t off = (size_t)e * 65536 + (size_t)(h0 + ty + i) * 1024 + k0 + tx;
                g_wthi[off] = hi;
                g_wtlo[off] = lo;
            } else {
                size_t o16 = (size_t)(e - 32) * 65536 +
                             (size_t)(h0 + ty + i) * 1024 + k0 + tx;
                g_wt16[o16] = __float2half(val);
            }
        }
    }
}

// ============================================================================
// gemm_qkv: fused QKV. 128x64 tiles, 8 warps 4m x 2n, warp tile 32x32,
//   3-stage, 2 CTAs/SM (92.2 KB smem, regs capped 128).
//   blockIdx.y 0..31 -> Q/K ensemble e=y (3-term bf16, pre-split epilogue);
//   blockIdx.y 32..47 -> V ensemble e=y-32 (1-term fp16, transposed epilogue).
// ============================================================================
#define LDA 80u
#define GQ_AHI 0u
#define GQ_ALO 10240u
#define GQ_BHI 20480u
#define GQ_BLO 25600u
#define GQ_STG 30720u
#define GEMM_SMEM (3 * 30720)
#define GV_A 0u
#define GV_B 10240u
#define GV_STG 15360u

__global__ __launch_bounds__(256, 2)
void gemm_qkv(const float* __restrict__ bias)
{
    extern __shared__ __align__(128) char smem[];
    const uint32_t sb  = smem_u32(smem);
    const int tid  = threadIdx.x;
    const int lane = tid & 31;
    const int wid  = tid >> 5;
    const int wm   = wid & 3;        // 4 m-blocks of 32 rows
    const int wn   = wid >> 2;       // 2 n-blocks of 32 cols
    const int m0   = blockIdx.x * 128;

    const int cp_r = tid >> 2;       // 0..63
    const int cp_c = tid & 3;        // 16B granule within 64B row
    const int ce   = cp_c * 8;
    const uint32_t a_row = (uint32_t)(wm * 32 + (lane & 7) + ((lane >> 3) & 1) * 8);
    const uint32_t a_kb  = (uint32_t)(lane >> 4) * 16u;
    const uint32_t b_row = (uint32_t)(wn * 32 + (lane & 7) + (lane >> 4) * 8);
    const uint32_t b_kb  = (uint32_t)((lane >> 3) & 1) * 16u;
    const int g  = lane >> 2;
    const int tg = lane & 3;

    float acc[2][4][4];
    #pragma unroll
    for (int mt = 0; mt < 2; ++mt)
        #pragma unroll
        for (int nt = 0; nt < 4; ++nt)
            #pragma unroll
            for (int i = 0; i < 4; ++i) acc[mt][nt][i] = 0.f;

    if (blockIdx.y < 32) {
        // ==================== Q/K path: 3-term split bf16 ====================
        const int e = blockIdx.y;
        const __nv_bfloat16* Ahi = g_xhi;
        const __nv_bfloat16* Alo = g_xlo;
        const __nv_bfloat16* Bh  = g_wthi + (size_t)e * 65536;
        const __nv_bfloat16* Bl  = g_wtlo + (size_t)e * 65536;

        auto issue = [&](int ks, uint32_t stg) {
            const int k0 = ks * 32;
            uint32_t d0 = stg + (uint32_t)cp_r * LDA + (uint32_t)cp_c * 16u;
            uint32_t d1 = d0 + 64u * LDA;
            size_t a0 = (size_t)(m0 + cp_r) * 1024 + k0 + ce;
            size_t a1 = a0 + 64 * 1024;
            size_t b0 = (size_t)cp_r * 1024 + k0 + ce;
            cp_async16(d0 + GQ_AHI, Ahi + a0);
            cp_async16(d1 + GQ_AHI, Ahi + a1);
            cp_async16(d0 + GQ_ALO, Alo + a0);
            cp_async16(d1 + GQ_ALO, Alo + a1);
            cp_async16(d0 + GQ_BHI, Bh + b0);
            cp_async16(d0 + GQ_BLO, Bl + b0);
            cp_commit();
        };

        issue(0, sb);
        issue(1, sb + GQ_STG);

        for (int ks = 0; ks < 32; ++ks) {
            if (ks < 31) cp_wait<1>(); else cp_wait<0>();
            __syncthreads();
            if (ks + 2 < 32) issue(ks + 2, sb + (uint32_t)((ks + 2) % 3) * GQ_STG);

            const uint32_t stg = sb + (uint32_t)(ks % 3) * GQ_STG;
            const uint32_t aHi = stg + GQ_AHI + a_row * LDA + a_kb;
            const uint32_t aLo = stg + GQ_ALO + a_row * LDA + a_kb;
            const uint32_t bHi = stg + GQ_BHI + b_row * LDA + b_kb;
            const uint32_t bLo = stg + GQ_BLO + b_row * LDA + b_kb;

            #pragma unroll
            for (int kk = 0; kk < 2; ++kk) {
                const uint32_t koff = (uint32_t)kk * 32u;

                uint32_t ahi[2][4], alo[2][4];
                #pragma unroll
                for (int mt = 0; mt < 2; ++mt) {
                    ldmatrix_x4(ahi[mt][0], ahi[mt][1], ahi[mt][2], ahi[mt][3],
                                aHi + (uint32_t)mt * 16u * LDA + koff);
                    ldmatrix_x4(alo[mt][0], alo[mt][1], alo[mt][2], alo[mt][3],
                                aLo + (uint32_t)mt * 16u * LDA + koff);
                }
                uint32_t bhi[4][2], blo[4][2];
                #pragma unroll
                for (int ntp = 0; ntp < 2; ++ntp) {
                    uint32_t r0, r1, r2, r3;
                    ldmatrix_x4(r0, r1, r2, r3, bHi + (uint32_t)ntp * 16u * LDA + koff);
                    bhi[ntp * 2][0] = r0; bhi[ntp * 2][1] = r1;
                    bhi[ntp * 2 + 1][0] = r2; bhi[ntp * 2 + 1][1] = r3;
                    ldmatrix_x4(r0, r1, r2, r3, bLo + (uint32_t)ntp * 16u * LDA + koff);
                    blo[ntp * 2][0] = r0; blo[ntp * 2][1] = r1;
                    blo[ntp * 2 + 1][0] = r2; blo[ntp * 2 + 1][1] = r3;
                }

                #pragma unroll
                for (int mt = 0; mt < 2; ++mt)
                    #pragma unroll
                    for (int nt = 0; nt < 4; ++nt) {
                        mma_bf16(acc[mt][nt], ahi[mt][0], ahi[mt][1], ahi[mt][2], ahi[mt][3],
                                 bhi[nt][0], bhi[nt][1]);
                        mma_bf16(acc[mt][nt], ahi[mt][0], ahi[mt][1], ahi[mt][2], ahi[mt][3],
                                 blo[nt][0], blo[nt][1]);
                        mma_bf16(acc[mt][nt], alo[mt][0], alo[mt][1], alo[mt][2], alo[mt][3],
                                 bhi[nt][0], bhi[nt][1]);
                    }
            }
        }

        const float QSCALE = 11.5415603272f;
        const bool  isQ = (e < 16);
        const float s   = isQ ? QSCALE : 1.f;
        __nv_bfloat16* dh = isQ ? g_qhi : g_khi;
        __nv_bfloat16* dl = isQ ? g_qlo : g_klo;
        const int eo = isQ ? e : (e - 16);
        const float* bp = bias + (size_t)e * 64;
        #pragma unroll
        for (int mt = 0; mt < 2; ++mt)
            #pragma unroll
            for (int nt = 0; nt < 4; ++nt) {
                int n = wn * 32 + nt * 8 + tg * 2;   // 0..63
                float b0 = bp[n], b1 = bp[n + 1];
                int r0 = m0 + wm * 32 + mt * 16 + g;
                float v00 = (acc[mt][nt][0] + b0) * s, v01 = (acc[mt][nt][1] + b1) * s;
                float v10 = (acc[mt][nt][2] + b0) * s, v11 = (acc[mt][nt][3] + b1) * s;
                size_t base0 = ((size_t)eo * 8192 + r0) * 64 + n;
                size_t base1 = base0 + 8 * 64;
                uint32_t h, l;
                split2_bf(v00, v01, h, l);
                *(uint32_t*)&dh[base0] = h;
                *(uint32_t*)&dl[base0] = l;
                split2_bf(v10, v11, h, l);
                *(uint32_t*)&dh[base1] = h;
                *(uint32_t*)&dl[base1] = l;
            }
    } else {
        // ============ V path: 1-term fp16, transposed epilogue ============
        const int e = blockIdx.y - 32;           // 0..15
        const float* bp = bias + (size_t)(32 + e) * 64;
        const __half* A  = g_x16;
        const __half* B0 = g_wt16 + (size_t)e * 65536;

        auto issue = [&](int ks, uint32_t stg) {
            const int k0 = ks * 32;
            uint32_t d0 = stg + (uint32_t)cp_r * LDA + (uint32_t)cp_c * 16u;
            uint32_t d1 = d0 + 64u * LDA;
            size_t a0 = (size_t)(m0 + cp_r) * 1024 + k0 + ce;
            size_t a1 = a0 + 64 * 1024;
            size_t b0 = (size_t)cp_r * 1024 + k0 + ce;
            cp_async16(d0 + GV_A, A + a0);
            cp_async16(d1 + GV_A, A + a1);
            cp_async16(d0 + GV_B, B0 + b0);
            cp_commit();
        };

        issue(0, sb);
        issue(1, sb + GV_STG);

        for (int ks = 0; ks < 32; ++ks) {
            if (ks < 31) cp_wait<1>(); else cp_wait<0>();
            __syncthreads();
            if (ks + 2 < 32) issue(ks + 2, sb + (uint32_t)((ks + 2) % 3) * GV_STG);

            const uint32_t stg = sb + (uint32_t)(ks % 3) * GV_STG;
            const uint32_t aB = stg + GV_A + a_row * LDA + a_kb;
            const uint32_t bB = stg + GV_B + b_row * LDA + b_kb;

            #pragma unroll
            for (int kk = 0; kk < 2; ++kk) {
                const uint32_t koff = (uint32_t)kk * 32u;

                uint32_t af[2][4];
                #pragma unroll
                for (int mt = 0; mt < 2; ++mt)
                    ldmatrix_x4(af[mt][0], af[mt][1], af[mt][2], af[mt][3],
                                aB + (uint32_t)mt * 16u * LDA + koff);
                uint32_t bf[4][2];
                #pragma unroll
                for (int ntp = 0; ntp < 2; ++ntp) {
                    uint32_t r0, r1, r2, r3;
                    ldmatrix_x4(r0, r1, r2, r3, bB + (uint32_t)ntp * 16u * LDA + koff);
                    bf[ntp * 2][0] = r0; bf[ntp * 2][1] = r1;
                    bf[ntp * 2 + 1][0] = r2; bf[ntp * 2 + 1][1] = r3;
                }

                #pragma unroll
                for (int mt = 0; mt < 2; ++mt)
                    #pragma unroll
                    for (int nt = 0; nt < 4; ++nt)
                        mma_f16(acc[mt][nt], af[mt][0], af[mt][1], af[mt][2], af[mt][3],
                                bf[nt][0], bf[nt][1]);
            }
        }

        // ---- transpose epilogue: stage fp16 [n][row] in smem, write [d][l] ----
        __syncthreads();   // all stage reads done before smem reuse
        __half* tile = (__half*)smem;   // [64 n][136 row-stride]
        #pragma unroll
        for (int mt = 0; mt < 2; ++mt)
            #pragma unroll
            for (int nt = 0; nt < 4; ++nt) {
                int n = wn * 32 + nt * 8 + tg * 2;   // 0..63
                float b0 = bp[n], b1 = bp[n + 1];
                int r0 = wm * 32 + mt * 16 + g;      // local row
                tile[(n    ) * 136 + r0]     = __float2half(acc[mt][nt][0] + b0);
                tile[(n + 1) * 136 + r0]     = __float2half(acc[mt][nt][1] + b1);
                tile[(n    ) * 136 + r0 + 8] = __float2half(acc[mt][nt][2] + b0);
                tile[(n + 1) * 136 + r0 + 8] = __float2half(acc[mt][nt][3] + b1);
            }
        __syncthreads();

        const int b  = m0 >> 11;        // batch of this row block
        const int l0 = m0 & 2047;       // seq offset within batch
        const int hb = e * 4 + b;
        #pragma unroll
        for (int i = 0; i < 4; ++i) {
            int idx = tid + i * 256;     // < 1024: 64 d x 16 granules of 8 halfs
            int d   = idx >> 4;
            int c   = idx & 15;
            uint4 v = *(uint4*)&tile[d * 136 + c * 8];
            *(uint4*)&g_vt16[((size_t)hb * 64 + d) * 2048 + l0 + c * 8] = v;
        }
    }
}

// ============================================================================
// gemm_proj: 128x128 tile, 2-term split-fp16, 3-stage, 2 CTAs/SM (proven).
// ============================================================================
#define GP_AHI 0u
#define GP_ALO 10240u
#define GP_B   20480u
#define GP_STG 30720u
#define GP_SMEM (3 * 30720)

__global__ __launch_bounds__(256)
void gemm_proj(const float* __restrict__ bias, float* __restrict__ C)
{
    extern __shared__ __align__(128) char smem[];
    const uint32_t sb  = smem_u32(smem);
    const int tid  = threadIdx.x;
    const int lane = tid & 31;
    const int wid  = tid >> 5;
    const int wm   = wid & 1;
    const int wn   = wid >> 1;
    const int m0   = blockIdx.x * 128;
    const int n0   = blockIdx.y * 128;

    const __half* Ahi = g_avhi;
    const __half* Alo = g_avlo;
    const __half* B0  = g_wp16 + (size_t)n0 * 1024;

    float acc[4][4][4];
    #pragma unroll
    for (int mt = 0; mt < 4; ++mt)
        #pragma unroll
        for (int nt = 0; nt < 4; ++nt)
            #pragma unroll
            for (int i = 0; i < 4; ++i) acc[mt][nt][i] = 0.f;

    const int cp_r = tid >> 2;
    const int cp_c = tid & 3;
    const int ce   = cp_c * 8;
    auto issue = [&](int ks, uint32_t stg) {
        const int k0 = ks * 32;
        uint32_t d0 = stg + (uint32_t)cp_r * LDA + (uint32_t)cp_c * 16u;
        uint32_t d1 = d0 + 64u * LDA;
        size_t a0 = (size_t)(m0 + cp_r) * 1024 + k0 + ce;
        size_t a1 = a0 + 64 * 1024;
        size_t b0 = (size_t)cp_r * 1024 + k0 + ce;
        cp_async16(d0 + GP_AHI, Ahi + a0);
        cp_async16(d1 + GP_AHI, Ahi + a1);
        cp_async16(d0 + GP_ALO, Alo + a0);
        cp_async16(d1 + GP_ALO, Alo + a1);
        cp_async16(d0 + GP_B, B0 + b0);
        cp_async16(d1 + GP_B, B0 + 65536 + b0);
        cp_commit();
    };

    const uint32_t a_row = (uint32_t)(wm * 64 + (lane & 7) + ((lane >> 3) & 1) * 8);
    const uint32_t a_kb  = (uint32_t)(lane >> 4) * 16u;
    const uint32_t b_row = (uint32_t)(wn * 32 + (lane & 7) + (lane >> 4) * 8);
    const uint32_t b_kb  = (uint32_t)((lane >> 3) & 1) * 16u;

    issue(0, sb);
    issue(1, sb + GP_STG);

    for (int ks = 0; ks < 32; ++ks) {
        if (ks < 31) cp_wait<1>(); else cp_wait<0>();
        __syncthreads();
        if (ks + 2 < 32) issue(ks + 2, sb + (uint32_t)((ks + 2) % 3) * GP_STG);

        const uint32_t stg = sb + (uint32_t)(ks % 3) * GP_STG;
        const uint32_t aHi = stg + GP_AHI + a_row * LDA + a_kb;
        const uint32_t aLo = stg + GP_ALO + a_row * LDA + a_kb;
        const uint32_t bB  = stg + GP_B   + b_row * LDA + b_kb;

        #pragma unroll
        for (int kk = 0; kk < 2; ++kk) {
            const uint32_t koff = (uint32_t)kk * 32u;

            uint32_t ahi[4][4], alo[4][4];
            #pragma unroll
            for (int mt = 0; mt < 4; ++mt) {
                ldmatrix_x4(ahi[mt][0], ahi[mt][1], ahi[mt][2], ahi[mt][3],
                            aHi + (uint32_t)mt * 16u * LDA + koff);
                ldmatrix_x4(alo[mt][0], alo[mt][1], alo[mt][2], alo[mt][3],
                            aLo + (uint32_t)mt * 16u * LDA + koff);
            }
            uint32_t bf[4][2];
            #pragma unroll
            for (int ntp = 0; ntp < 2; ++ntp) {
                uint32_t r0, r1, r2, r3;
                ldmatrix_x4(r0, r1, r2, r3, bB + (uint32_t)ntp * 16u * LDA + koff);
                bf[ntp * 2][0] = r0; bf[ntp * 2][1] = r1;
                bf[ntp * 2 + 1][0] = r2; bf[ntp * 2 + 1][1] = r3;
            }

            #pragma unroll
            for (int mt = 0; mt < 4; ++mt)
                #pragma unroll
                for (int nt = 0; nt < 4; ++nt) {
                    mma_f16(acc[mt][nt], ahi[mt][0], ahi[mt][1], ahi[mt][2], ahi[mt][3],
                            bf[nt][0], bf[nt][1]);
                    mma_f16(acc[mt][nt], alo[mt][0], alo[mt][1], alo[mt][2], alo[mt][3],
                            bf[nt][0], bf[nt][1]);
                }
        }
    }

    const int g  = lane >> 2;
    const int tg = lane & 3;
    #pragma unroll
    for (int mt = 0; mt < 4; ++mt)
        #pragma unroll
        for (int nt = 0; nt < 4; ++nt) {
            int n = n0 + wn * 32 + nt * 8 + tg * 2;
            float b0 = bias[n], b1 = bias[n + 1];
            int r0 = m0 + wm * 64 + mt * 16 + g;
            float2 o0 = make_float2(acc[mt][nt][0] + b0, acc[mt][nt][1] + b1);
            float2 o1 = make_float2(acc[mt][nt][2] + b0, acc[mt][nt][3] + b1);
            *(float2*)(C + (size_t)r0 * 1024 + n)       = o0;
            *(float2*)(C + (size_t)(r0 + 8) * 1024 + n) = o1;
        }
}

// ============================================================================
// attn_mma: flash attention. S 3-term bf16, PV 1-term fp16.
//   4-stage cp.async, 2 CTAs/SM (proven R16 config).
// ============================================================================
#define LDS_ROW 144u
#define ST_KHI 0u
#define ST_KLO 9216u
#define ST_V16 18432u
#define STAGE_BYTES 27648u
#define ATTN_SMEM (4 * 27648)

__global__ __launch_bounds__(256, 2)
void attn_mma()
{
    extern __shared__ __align__(128) char smem[];
    const uint32_t sb = smem_u32(smem);
    const int tid  = threadIdx.x;
    const int lane = tid & 31;
    const int wid  = tid >> 5;
    const int g    = lane >> 2;
    const int tg   = lane & 3;
    const int hb   = blockIdx.y;
    const int hd   = hb >> 2;
    const int b    = hb & 3;
    const int q0   = blockIdx.x * 128;

    const __nv_bfloat16* Qhi = g_qhi + ((size_t)hd * 8192 + b * 2048 + q0) * 64;
    const __nv_bfloat16* Qlo = g_qlo + ((size_t)hd * 8192 + b * 2048 + q0) * 64;
    const __nv_bfloat16* Khi = g_khi + (size_t)hb * 2048 * 64;
    const __nv_bfloat16* Klo = g_klo + (size_t)hb * 2048 * 64;
    const __half*        V16 = g_vt16 + (size_t)hb * 64 * 2048;

    // ---- stage Q (pre-scaled, pre-split) via cp.async, extract fragments ----
    #pragma unroll
    for (int i = 0; i < 4; ++i) {
        int idx = tid + i * 256;
        int row = idx >> 3;
        int c   = idx & 7;
        cp_async16(sb + (uint32_t)row * LDS_ROW + (uint32_t)c * 16u,
                   Qhi + (size_t)row * 64 + c * 8);
        cp_async16(sb + 18432u + (uint32_t)row * LDS_ROW + (uint32_t)c * 16u,
                   Qlo + (size_t)row * 64 + c * 8);
    }
    cp_commit();
    cp_wait<0>();
    __syncthreads();

    uint32_t qhi[4][4], qlo[4][4];
    {
        const uint32_t qrow = (uint32_t)(wid * 16 + (lane & 7) + ((lane >> 3) & 1) * 8);
        const uint32_t kb   = (uint32_t)(lane >> 4) * 16u;
        const uint32_t aH = sb + qrow * LDS_ROW + kb;
        const uint32_t aL = sb + 18432u + qrow * LDS_ROW + kb;
        #pragma unroll
        for (int t = 0; t < 4; ++t) {
            ldmatrix_x4(qhi[t][0], qhi[t][1], qhi[t][2], qhi[t][3], aH + t * 32u);
            ldmatrix_x4(qlo[t][0], qlo[t][1], qlo[t][2], qlo[t][3], aL + t * 32u);
        }
    }
    __syncthreads();   // Q consumed — smem free for stages

    float mA = -1e30f, mB = -1e30f, lA = 0.f, lB = 0.f;
    float oacc[8][4];
    #pragma unroll
    for (int j = 0; j < 8; ++j)
        #pragma unroll
        for (int i = 0; i < 4; ++i) oacc[j][i] = 0.f;

    const uint32_t brow = (uint32_t)((lane & 7) + (lane >> 4) * 8);
    const uint32_t bkb  = (uint32_t)((lane >> 3) & 1) * 16u;

    const int cp_row = tid >> 3;
    const int cp_c   = tid & 7;
    auto issue = [&](int j0, uint32_t stg) {
        #pragma unroll
        for (int i = 0; i < 2; ++i) {
            int row = cp_row + i * 32;
            uint32_t doff = stg + (uint32_t)row * LDS_ROW + (uint32_t)cp_c * 16u;
            cp_async16(doff + ST_KHI, Khi + ((size_t)(j0 + row)) * 64 + cp_c * 8);
            cp_async16(doff + ST_KLO, Klo + ((size_t)(j0 + row)) * 64 + cp_c * 8);
            cp_async16(doff + ST_V16, V16 + ((size_t)row) * 2048 + j0 + cp_c * 8);
        }
        cp_commit();
    };

    issue(0,   sb);
    issue(64,  sb + STAGE_BYTES);
    issue(128, sb + 2 * STAGE_BYTES);

    for (int j = 0; j < 32; ++j) {
        if (j <= 29) cp_wait<2>();
        else if (j == 30) cp_wait<1>();
        else cp_wait<0>();
        __syncthreads();
        if (j + 3 < 32) issue((j + 3) * 64, sb + (uint32_t)((j + 3) % 4) * STAGE_BYTES);

        const uint32_t stg = sb + (uint32_t)(j % 4) * STAGE_BYTES;

        // ---- S = Qscaled @ K^T (split 3-term bf16), log2 units ----
        float sacc[8][4];
        #pragma unroll
        for (int jj = 0; jj < 8; ++jj)
            #pragma unroll
            for (int i = 0; i < 4; ++i) sacc[jj][i] = 0.f;

        #pragma unroll
        for (int td = 0; td < 4; ++td) {
            uint32_t bhi[8][2], blo[8][2];
            #pragma unroll
            for (int ntp = 0; ntp < 4; ++ntp) {
                uint32_t base = (uint32_t)(ntp * 16) * LDS_ROW + brow * LDS_ROW + bkb
                                + (uint32_t)td * 32u;
                uint32_t r0, r1, r2, r3;
                ldmatrix_x4(r0, r1, r2, r3, stg + ST_KHI + base);
                bhi[ntp * 2][0] = r0; bhi[ntp * 2][1] = r1;
                bhi[ntp * 2 + 1][0] = r2; bhi[ntp * 2 + 1][1] = r3;
                ldmatrix_x4(r0, r1, r2, r3, stg + ST_KLO + base);
                blo[ntp * 2][0] = r0; blo[ntp * 2][1] = r1;
                blo[ntp * 2 + 1][0] = r2; blo[ntp * 2 + 1][1] = r3;
            }
            #pragma unroll
            for (int nt = 0; nt < 8; ++nt) {
                mma_bf16(sacc[nt], qhi[td][0], qhi[td][1], qhi[td][2], qhi[td][3],
                         bhi[nt][0], bhi[nt][1]);
                mma_bf16(sacc[nt], qhi[td][0], qhi[td][1], qhi[td][2], qhi[td][3],
                         blo[nt][0], blo[nt][1]);
                mma_bf16(sacc[nt], qlo[td][0], qlo[td][1], qlo[td][2], qlo[td][3],
                         bhi[nt][0], bhi[nt][1]);
            }
        }

        // ---- online softmax (log2 domain) ----
        float rmA = -1e30f, rmB = -1e30f;
        #pragma unroll
        for (int jj = 0; jj < 8; ++jj) {
            rmA = fmaxf(rmA, fmaxf(sacc[jj][0], sacc[jj][1]));
            rmB = fmaxf(rmB, fmaxf(sacc[jj][2], sacc[jj][3]));
        }
        rmA = fmaxf(rmA, __shfl_xor_sync(0xffffffffu, rmA, 1));
        rmA = fmaxf(rmA, __shfl_xor_sync(0xffffffffu, rmA, 2));
        rmB = fmaxf(rmB, __shfl_xor_sync(0xffffffffu, rmB, 1));
        rmB = fmaxf(rmB, __shfl_xor_sync(0xffffffffu, rmB, 2));

        float mnA = fmaxf(mA, rmA), mnB = fmaxf(mB, rmB);
        float corrA = exp2_fast(mA - mnA), corrB = exp2_fast(mB - mnB);

        float sumA = 0.f, sumB = 0.f;
        uint32_t pf[4][4];
        #pragma unroll
        for (int jj = 0; jj < 8; ++jj) {
            float p0 = exp2_fast(sacc[jj][0] - mnA);
            float p1 = exp2_fast(sacc[jj][1] - mnA);
            float p2 = exp2_fast(sacc[jj][2] - mnB);
            float p3 = exp2_fast(sacc[jj][3] - mnB);
            sumA += p0 + p1; sumB += p2 + p3;
            int t = jj >> 1;
            int o = (jj & 1) * 2;
            pf[t][o]     = pack_f16x2(p0, p1);
            pf[t][o + 1] = pack_f16x2(p2, p3);
        }
        sumA += __shfl_xor_sync(0xffffffffu, sumA, 1);
        sumA += __shfl_xor_sync(0xffffffffu, sumA, 2);
        sumB += __shfl_xor_sync(0xffffffffu, sumB, 1);
        sumB += __shfl_xor_sync(0xffffffffu, sumB, 2);

        lA = lA * corrA + sumA;
        lB = lB * corrB + sumB;
        mA = mnA; mB = mnB;

        #pragma unroll
        for (int jj = 0; jj < 8; ++jj) {
            oacc[jj][0] *= corrA; oacc[jj][1] *= corrA;
            oacc[jj][2] *= corrB; oacc[jj][3] *= corrB;
        }

        // ---- O += P @ V (1-term fp16) ----
        #pragma unroll
        for (int t = 0; t < 4; ++t) {
            uint32_t vf[8][2];
            #pragma unroll
            for (int ntp = 0; ntp < 4; ++ntp) {
                uint32_t base = (uint32_t)(ntp * 16) * LDS_ROW + brow * LDS_ROW + bkb
                                + (uint32_t)t * 32u;
                uint32_t r0, r1, r2, r3;
                ldmatrix_x4(r0, r1, r2, r3, stg + ST_V16 + base);
                vf[ntp * 2][0] = r0; vf[ntp * 2][1] = r1;
                vf[ntp * 2 + 1][0] = r2; vf[ntp * 2 + 1][1] = r3;
            }
            #pragma unroll
            for (int nd = 0; nd < 8; ++nd)
                mma_f16(oacc[nd], pf[t][0], pf[t][1], pf[t][2], pf[t][3],
                        vf[nd][0], vf[nd][1]);
        }
    }

    // ---- epilogue: normalize, split to fp16 hi/lo, write g_avhi/g_avlo ----
    const float invA = 1.f / lA, invB = 1.f / lB;
    const int rowA = q0 + wid * 16 + g;
    const int rowB = rowA + 8;
    #pragma unroll
    for (int jd = 0; jd < 8; ++jd) {
        int col = hd * 64 + jd * 8 + tg * 2;
        {
            uint32_t h, l;
            split2_f16(oacc[jd][0] * invA, oacc[jd][1] * invA, h, l);
            size_t base = (size_t)(b * 2048 + rowA) * 1024 + col;
            *(uint32_t*)&g_avhi[base] = h;
            *(uint32_t*)&g_avlo[base] = l;
        }
        {
            uint32_t h, l;
            split2_f16(oacc[jd][2] * invB, oacc[jd][3] * invB, h, l);
            size_t base = (size_t)(b * 2048 + rowB) * 1024 + col;
            *(uint32_t*)&g_avhi[base] = h;
            *(uint32_t*)&g_avlo[base] = l;
        }
    }
}

// ============================================================================
extern "C" void kernel_launch(void* const* d_in, const int* in_sizes, int n_in,
                              void* d_out, int out_size)
{
    const float* x    = (const float*)d_in[0];   // (4, 2048, 1024)
    const float* Wqkv = (const float*)d_in[1];   // (48, 1024, 64)
    const float* bqkv = (const float*)d_in[2];   // (48, 64)
    const float* Wp   = (const float*)d_in[3];   // (1024, 1024)
    const float* bp   = (const float*)d_in[4];   // (1024,)
    float* out = (float*)d_out;                  // (4, 2048, 1024)

    cudaFuncSetAttribute(gemm_qkv, cudaFuncAttributeMaxDynamicSharedMemorySize,
                         GEMM_SMEM);
    cudaFuncSetAttribute(gemm_proj, cudaFuncAttributeMaxDynamicSharedMemorySize,
                         GP_SMEM);
    cudaFuncSetAttribute(attn_mma, cudaFuncAttributeMaxDynamicSharedMemorySize,
                         ATTN_SMEM);

    // 1) fused preps: x split + Wp fp16 + Wqkv transpose/split
    prep_all<<<5376, 256>>>(x, Wp, Wqkv);

    // 2) fused QKV, 128x64 tiles, 2 CTAs/SM: Q/K 3-term bf16 (y 0..31)
    //    + V 1-term fp16 with transposed epilogue (y 32..47)
    gemm_qkv<<<dim3(64, 48), 256, GEMM_SMEM>>>(bqkv);

    // 3) attention (4-stage, 2 CTAs/SM)
    attn_mma<<<dim3(16, 64), 256, ATTN_SMEM>>>();

    // 4) proj: 2-term split-fp16, 128x128 tiles, 3-stage
    gemm_proj<<<dim3(64, 8), 256, GP_SMEM>>>(bp, out);
}